// round 1
// baseline (speedup 1.0000x reference)
#include <cuda_runtime.h>
#include <math.h>

#define S_TOT 2560
#define TXT 256
#define IMG 2304
#define D 3072
#define NH 24
#define DH 128
#define ND3 9216
#define ATT_SCALE 0.08838834764831845f   // 1/sqrt(128)
#define EPS 1e-5f

// ---------------- scratch (device globals: no allocation allowed) ----------------
__device__ float g_qkv[(size_t)S_TOT * ND3];        // 94.4 MB
__device__ float g_q[(size_t)NH * S_TOT * DH];      // 31.5 MB
__device__ float g_k[(size_t)NH * S_TOT * DH];
__device__ float g_v[(size_t)NH * S_TOT * DH];
__device__ float g_attn[(size_t)S_TOT * D];         // 31.5 MB

// ---------------- dual-segment SGEMM: C = A @ W^T (+bias) ----------------
// Rows [0, M0) use (A0, W0, b0, C0); rows [M0, M) use (A1, W1, b1, C1).
// BM=BN=128, BK=8, 256 threads, 8x8 per thread. All dims divisible.
__global__ __launch_bounds__(256, 2)
void gemm_dual(const float* __restrict__ A0, const float* __restrict__ A1,
               const float* __restrict__ W0, const float* __restrict__ W1,
               const float* __restrict__ b0, const float* __restrict__ b1,
               float* __restrict__ C0, float* __restrict__ C1,
               int M0, int K, int N)
{
    const int bm = blockIdx.y, bn = blockIdx.x;
    const int rowbase = bm * 128;

    const float* A; const float* W; const float* b; float* C;
    if (rowbase < M0) {
        A = A0 + (size_t)rowbase * K; W = W0; b = b0; C = C0 + (size_t)rowbase * N;
    } else {
        A = A1 + (size_t)(rowbase - M0) * K; W = W1; b = b1; C = C1 + (size_t)(rowbase - M0) * N;
    }

    __shared__ float As[8][128];
    __shared__ float Bs[8][128];

    const int tid = threadIdx.x;
    const int tx = tid & 15;      // n
    const int ty = tid >> 4;      // m
    const int lr = tid >> 1;      // load row (0..127)
    const int lc = (tid & 1) * 4; // load col (0 or 4)

    const float* Ap = A + (size_t)lr * K + lc;
    const float* Wp = W + (size_t)(bn * 128 + lr) * K + lc;

    float acc[8][8];
    #pragma unroll
    for (int i = 0; i < 8; i++)
        #pragma unroll
        for (int j = 0; j < 8; j++) acc[i][j] = 0.f;

    for (int kt = 0; kt < K; kt += 8) {
        float4 av = *(const float4*)(Ap + kt);
        float4 wv = *(const float4*)(Wp + kt);
        As[lc + 0][lr] = av.x; As[lc + 1][lr] = av.y;
        As[lc + 2][lr] = av.z; As[lc + 3][lr] = av.w;
        Bs[lc + 0][lr] = wv.x; Bs[lc + 1][lr] = wv.y;
        Bs[lc + 2][lr] = wv.z; Bs[lc + 3][lr] = wv.w;
        __syncthreads();
        #pragma unroll
        for (int k = 0; k < 8; k++) {
            float ra[8], rb[8];
            #pragma unroll
            for (int i = 0; i < 8; i++) ra[i] = As[k][ty * 8 + i];
            #pragma unroll
            for (int j = 0; j < 8; j++) rb[j] = Bs[k][tx * 8 + j];
            #pragma unroll
            for (int i = 0; i < 8; i++)
                #pragma unroll
                for (int j = 0; j < 8; j++)
                    acc[i][j] = fmaf(ra[i], rb[j], acc[i][j]);
        }
        __syncthreads();
    }

    float bias[8];
    #pragma unroll
    for (int j = 0; j < 8; j++) bias[j] = b ? b[bn * 128 + tx * 8 + j] : 0.f;

    #pragma unroll
    for (int i = 0; i < 8; i++) {
        float* Crow = C + (size_t)(ty * 8 + i) * N + bn * 128 + tx * 8;
        #pragma unroll
        for (int j = 0; j < 8; j += 4) {
            float4 v;
            v.x = acc[i][j + 0] + bias[j + 0];
            v.y = acc[i][j + 1] + bias[j + 1];
            v.z = acc[i][j + 2] + bias[j + 2];
            v.w = acc[i][j + 3] + bias[j + 3];
            *(float4*)(Crow + j) = v;
        }
    }
}

// ---------------- RMSNorm + RoPE + head split ----------------
// block = (s*NH + h) on x, which(0=q,1=k,2=v) on y; 128 threads = DH
__global__ void norm_rope(const float* __restrict__ cosb, const float* __restrict__ sinb,
                          const float* __restrict__ nqw,  const float* __restrict__ nkw,
                          const float* __restrict__ naqw, const float* __restrict__ nakw)
{
    const int s = blockIdx.x / NH, h = blockIdx.x % NH;
    const int which = blockIdx.y;
    const int dh = threadIdx.x;

    float x = g_qkv[(size_t)s * ND3 + which * D + h * DH + dh];
    float* dst = (which == 0 ? g_q : which == 1 ? g_k : g_v)
                 + ((size_t)h * S_TOT + s) * DH + dh;

    if (which == 2) { *dst = x; return; }   // uniform per block (blockIdx.y)

    __shared__ float sh[128];
    __shared__ float red[4];

    float sq = x * x;
    #pragma unroll
    for (int o = 16; o; o >>= 1) sq += __shfl_xor_sync(0xffffffff, sq, o);
    if ((dh & 31) == 0) red[dh >> 5] = sq;
    __syncthreads();
    float msum = red[0] + red[1] + red[2] + red[3];
    float r = rsqrtf(msum * (1.0f / 128.0f) + EPS);

    const float* w;
    if (which == 0) w = (s < TXT) ? naqw : nqw;
    else            w = (s < TXT) ? nakw : nkw;

    float xn = x * r * w[dh];
    sh[dh] = xn;
    __syncthreads();

    float c  = cosb[s * 64 + (dh >> 1)];
    float sn = sinb[s * 64 + (dh >> 1)];
    float other = sh[dh ^ 1];
    float o = (dh & 1) ? fmaf(xn, c,  other * sn)
                       : fmaf(xn, c, -other * sn);
    *dst = o;
}

// ---------------- Flash attention, fp32 ----------------
// grid (40 q-tiles, 24 heads), 256 threads, BM=BN=64.
// Dynamic smem: Qst[128][68] | Kst[128][68] | Vs[64][128] | Ss[64][68]
#define FBM 64
#define FBN 64
#define FPAD 68

extern __shared__ float fsm[];

__global__ __launch_bounds__(256, 1)
void flash_attn()
{
    float* Qst = fsm;                     // transposed: [dh][r]
    float* Kst = Qst + 128 * FPAD;
    float* Vs  = Kst + 128 * FPAD;        // [r][dh]
    float* Ss  = Vs + FBN * DH;           // [r][c]
    __shared__ float mrow[FBM], lrow[FBM], arow[FBM];

    const int h  = blockIdx.y;
    const int q0 = blockIdx.x * FBM;
    const int tid = threadIdx.x;
    const int tx = tid & 15, ty = tid >> 4;

    const float* Q = g_q + (size_t)h * S_TOT * DH;
    const float* K = g_k + (size_t)h * S_TOT * DH;
    const float* V = g_v + (size_t)h * S_TOT * DH;

    for (int i = tid; i < FBM * DH; i += 256) {
        int r = i >> 7, dh = i & 127;
        Qst[dh * FPAD + r] = Q[(size_t)(q0 + r) * DH + dh];
    }
    if (tid < FBM) { mrow[tid] = -3.4e38f; lrow[tid] = 0.f; }

    float Oacc[4][8];
    #pragma unroll
    for (int i = 0; i < 4; i++)
        #pragma unroll
        for (int j = 0; j < 8; j++) Oacc[i][j] = 0.f;
    __syncthreads();

    for (int kv0 = 0; kv0 < S_TOT; kv0 += FBN) {
        // load K (transposed) and V
        for (int i = tid; i < FBN * DH; i += 256) {
            int r = i >> 7, dh = i & 127;
            Kst[dh * FPAD + r] = K[(size_t)(kv0 + r) * DH + dh];
        }
        for (int i = tid * 4; i < FBN * DH; i += 256 * 4)
            *(float4*)(Vs + i) = *(const float4*)(V + (size_t)kv0 * DH + i);
        __syncthreads();

        // ---- scores: S[ty*4+i][tx*4+j] ----
        float sacc[4][4];
        #pragma unroll
        for (int i = 0; i < 4; i++)
            #pragma unroll
            for (int j = 0; j < 4; j++) sacc[i][j] = 0.f;

        for (int k = 0; k < DH; k++) {
            float4 rav = *(const float4*)(Qst + k * FPAD + ty * 4);
            float4 rbv = *(const float4*)(Kst + k * FPAD + tx * 4);
            float ra[4] = {rav.x, rav.y, rav.z, rav.w};
            float rb[4] = {rbv.x, rbv.y, rbv.z, rbv.w};
            #pragma unroll
            for (int i = 0; i < 4; i++)
                #pragma unroll
                for (int j = 0; j < 4; j++)
                    sacc[i][j] = fmaf(ra[i], rb[j], sacc[i][j]);
        }
        #pragma unroll
        for (int i = 0; i < 4; i++)
            #pragma unroll
            for (int j = 0; j < 4; j++)
                Ss[(ty * 4 + i) * FPAD + tx * 4 + j] = sacc[i][j] * ATT_SCALE;
        __syncthreads();

        // ---- online softmax: 4 threads per row ----
        {
            const int row = tid >> 2, seg = tid & 3;
            float* Srow = Ss + row * FPAD + seg * 16;
            float mx = -3.4e38f;
            #pragma unroll
            for (int c = 0; c < 16; c++) mx = fmaxf(mx, Srow[c]);
            mx = fmaxf(mx, __shfl_xor_sync(0xffffffff, mx, 1));
            mx = fmaxf(mx, __shfl_xor_sync(0xffffffff, mx, 2));
            float mold = mrow[row];
            float mnew = fmaxf(mold, mx);
            float lsum = 0.f;
            #pragma unroll
            for (int c = 0; c < 16; c++) {
                float p = __expf(Srow[c] - mnew);
                Srow[c] = p;
                lsum += p;
            }
            lsum += __shfl_xor_sync(0xffffffff, lsum, 1);
            lsum += __shfl_xor_sync(0xffffffff, lsum, 2);
            if (seg == 0) {
                float alpha = __expf(mold - mnew);
                arow[row] = alpha;
                lrow[row] = lrow[row] * alpha + lsum;
                mrow[row] = mnew;
            }
        }
        __syncthreads();

        // ---- PV: O[ty*4+i][tx*8+cc] ----
        float al[4];
        #pragma unroll
        for (int i = 0; i < 4; i++) al[i] = arow[ty * 4 + i];
        #pragma unroll
        for (int i = 0; i < 4; i++)
            #pragma unroll
            for (int j = 0; j < 8; j++) Oacc[i][j] *= al[i];

        for (int j = 0; j < FBN; j++) {
            float p[4];
            #pragma unroll
            for (int i = 0; i < 4; i++) p[i] = Ss[(ty * 4 + i) * FPAD + j];
            float4 v0 = *(const float4*)(Vs + j * DH + tx * 8);
            float4 v1 = *(const float4*)(Vs + j * DH + tx * 8 + 4);
            float vv[8] = {v0.x, v0.y, v0.z, v0.w, v1.x, v1.y, v1.z, v1.w};
            #pragma unroll
            for (int i = 0; i < 4; i++)
                #pragma unroll
                for (int cc = 0; cc < 8; cc++)
                    Oacc[i][cc] = fmaf(p[i], vv[cc], Oacc[i][cc]);
        }
        __syncthreads();
    }

    // ---- normalize + write out[s][h*DH + c] ----
    float linv[4];
    #pragma unroll
    for (int i = 0; i < 4; i++) linv[i] = 1.0f / lrow[ty * 4 + i];
    #pragma unroll
    for (int i = 0; i < 4; i++) {
        float* dst = g_attn + (size_t)(q0 + ty * 4 + i) * D + h * DH + tx * 8;
        float4 o0, o1;
        o0.x = Oacc[i][0] * linv[i]; o0.y = Oacc[i][1] * linv[i];
        o0.z = Oacc[i][2] * linv[i]; o0.w = Oacc[i][3] * linv[i];
        o1.x = Oacc[i][4] * linv[i]; o1.y = Oacc[i][5] * linv[i];
        o1.z = Oacc[i][6] * linv[i]; o1.w = Oacc[i][7] * linv[i];
        *(float4*)(dst)     = o0;
        *(float4*)(dst + 4) = o1;
    }
}

// ---------------- launch ----------------
extern "C" void kernel_launch(void* const* d_in, const int* in_sizes, int n_in,
                              void* d_out, int out_size)
{
    const float* hidden     = (const float*)d_in[0];
    const float* encoder    = (const float*)d_in[1];
    const float* cosb       = (const float*)d_in[2];
    const float* sinb       = (const float*)d_in[3];
    const float* w_qkv      = (const float*)d_in[4];
    const float* w_add_qkv  = (const float*)d_in[5];
    const float* b_add_qkv  = (const float*)d_in[6];
    const float* norm_q_w   = (const float*)d_in[7];
    const float* norm_k_w   = (const float*)d_in[8];
    const float* norm_aq_w  = (const float*)d_in[9];
    const float* norm_ak_w  = (const float*)d_in[10];
    const float* w_out      = (const float*)d_in[11];
    const float* b_out      = (const float*)d_in[12];
    const float* w_add_out  = (const float*)d_in[13];
    const float* b_add_out  = (const float*)d_in[14];
    float* out = (float*)d_out;

    float *qkv, *attn;
    cudaGetSymbolAddress((void**)&qkv,  g_qkv);
    cudaGetSymbolAddress((void**)&attn, g_attn);

    const int FLASH_SMEM = (128 * FPAD + 128 * FPAD + FBN * DH + FBM * FPAD) * 4;
    cudaFuncSetAttribute(flash_attn, cudaFuncAttributeMaxDynamicSharedMemorySize, FLASH_SMEM);

    // 1) QKV projection: enc rows [0,256) use w_add_qkv (+bias), img rows use w_qkv
    gemm_dual<<<dim3(ND3 / 128, S_TOT / 128), 256>>>(
        encoder, hidden, w_add_qkv, w_qkv, b_add_qkv, nullptr,
        qkv, qkv + (size_t)TXT * ND3, TXT, D, ND3);

    // 2) RMSNorm + RoPE + split into per-head q/k/v
    norm_rope<<<dim3(S_TOT * NH, 3), 128>>>(cosb, sinb, norm_q_w, norm_k_w,
                                            norm_aq_w, norm_ak_w);

    // 3) Flash attention
    flash_attn<<<dim3(S_TOT / FBM, NH), 256, FLASH_SMEM>>>();

    // 4) Output projections: enc rows -> w_add_out -> out[IMG*D ...], img rows -> w_out -> out[0 ...]
    gemm_dual<<<dim3(D / 128, S_TOT / 128), 256>>>(
        attn, attn + (size_t)TXT * D, w_add_out, w_out, b_add_out, b_out,
        out + (size_t)IMG * D, out, TXT, D, D);
}

// round 3
// speedup vs baseline: 1.6643x; 1.6643x over previous
#include <cuda_runtime.h>
#include <math.h>
#include <stdint.h>

#define S_TOT 2560
#define TXT 256
#define IMG 2304
#define D 3072
#define NH 24
#define DH 128
#define ND3 9216
#define KDIM 3072
#define ATT_SCALE 0.08838834764831845f   // 1/sqrt(128)
#define EPS 1e-5f

// ---------------- scratch (device globals: no allocation allowed) ----------------
__device__ float g_qkv[(size_t)S_TOT * ND3];
__device__ float g_q[(size_t)NH * S_TOT * DH];
__device__ float g_k[(size_t)NH * S_TOT * DH];
__device__ float g_v[(size_t)NH * S_TOT * DH];
__device__ float g_attn[(size_t)S_TOT * D];
// tf32-prerounded copies
__device__ float g_x[(size_t)S_TOT * D];
__device__ float g_wqkv[(size_t)ND3 * D];
__device__ float g_waddqkv[(size_t)ND3 * D];
__device__ float g_wout[(size_t)D * D];
__device__ float g_waddout[(size_t)D * D];

// ================= helpers =================
static __device__ __forceinline__ uint32_t smem_u32(const void* p) {
    uint32_t r;
    asm("{ .reg .u64 t; cvta.to.shared.u64 t, %1; cvt.u32.u64 %0, t; }" : "=r"(r) : "l"(p));
    return r;
}
static __device__ __forceinline__ float rtf32(float x) {
    uint32_t r;
    asm("cvt.rna.tf32.f32 %0, %1;" : "=r"(r) : "f"(x));
    return __uint_as_float(r);
}
static __device__ __forceinline__ void cp16(uint32_t dst, const float* src) {
    asm volatile("cp.async.cg.shared.global [%0], [%1], 16;" :: "r"(dst), "l"(src));
}
#define CP_COMMIT() asm volatile("cp.async.commit_group;" ::: "memory")
#define CP_WAIT(n)  asm volatile("cp.async.wait_group %0;" :: "n"(n) : "memory")

static __device__ __forceinline__ void mma_tf32(
    float& c0, float& c1, float& c2, float& c3,
    uint32_t a0, uint32_t a1, uint32_t a2, uint32_t a3,
    uint32_t b0, uint32_t b1)
{
    asm volatile(
        "mma.sync.aligned.m16n8k8.row.col.f32.tf32.tf32.f32 "
        "{%0,%1,%2,%3}, {%4,%5,%6,%7}, {%8,%9}, {%0,%1,%2,%3};"
        : "+f"(c0), "+f"(c1), "+f"(c2), "+f"(c3)
        : "r"(a0), "r"(a1), "r"(a2), "r"(a3), "r"(b0), "r"(b1));
}

// ---------------- tf32 pre-round ----------------
__global__ void tf32_round(const float4* __restrict__ src, float4* __restrict__ dst, int n4)
{
    int i = blockIdx.x * blockDim.x + threadIdx.x;
    if (i < n4) {
        float4 v = src[i];
        v.x = rtf32(v.x); v.y = rtf32(v.y); v.z = rtf32(v.z); v.w = rtf32(v.w);
        dst[i] = v;
    }
}

// ================= tf32 mma.sync GEMM =================
// C = A @ W^T (+bias). Block tile 128x256, BK=32, 8 warps (2M x 4N) of 64x64.
// A and W must be tf32-prerounded. Dual weight/output segment switched at row M0.
#define BM 128
#define BN 256
#define BK 32
#define STG 3
#define NCHUNK (KDIM / BK)       // 96
#define APITCH 36                // floats per row (padded)
#define A_ST_FLOATS (BM * APITCH)      // 4608
#define B_ST_FLOATS (BN * APITCH)      // 9216
#define GEMM_SMEM_FLOATS (STG * (A_ST_FLOATS + B_ST_FLOATS))
#define GEMM_SMEM_BYTES (GEMM_SMEM_FLOATS * 4)   // 165888

__global__ __launch_bounds__(256, 1)
void gemm_tf32(const float* __restrict__ A,
               const float* __restrict__ W0, const float* __restrict__ W1,
               const float* __restrict__ b0, const float* __restrict__ b1,
               float* __restrict__ C0, float* __restrict__ C1,
               int M0, int N)
{
    extern __shared__ float sm[];
    float* Asm = sm;                              // [STG][BM][36]
    float* Bsm = sm + STG * A_ST_FLOATS;          // [STG][BN][36]

    const int tid  = threadIdx.x;
    const int lane = tid & 31;
    const int wid  = tid >> 5;
    const int wm   = wid >> 2;      // 0..1
    const int wn   = wid & 3;       // 0..3
    const int g    = lane >> 2;     // 0..7
    const int t    = lane & 3;      // 0..3

    const int bm = blockIdx.y, bn = blockIdx.x;
    const int rowbase = bm * BM;
    const int n0 = bn * BN;

    const float* Ab = A + (size_t)rowbase * KDIM;
    const float* W; const float* bias; float* C;
    if (rowbase < M0) { W = W0; bias = b0; C = C0 + (size_t)rowbase * N; }
    else              { W = W1; bias = b1; C = C1 + (size_t)(rowbase - M0) * N; }

    const uint32_t asu_base = smem_u32(Asm);
    const uint32_t bsu_base = smem_u32(Bsm);

    // ---- async chunk loader ----
    auto load_chunk = [&](int ck, int st) {
        const int k0 = ck * BK;
        const uint32_t au = asu_base + st * (A_ST_FLOATS * 4);
        const uint32_t bu = bsu_base + st * (B_ST_FLOATS * 4);
        #pragma unroll
        for (int i = 0; i < 4; i++) {           // A: 1024 16B chunks
            int idx = tid + 256 * i;
            int row = idx >> 3, c4 = idx & 7;
            cp16(au + row * (APITCH * 4) + c4 * 16,
                 Ab + (size_t)row * KDIM + k0 + c4 * 4);
        }
        #pragma unroll
        for (int i = 0; i < 8; i++) {           // B: 2048 16B chunks
            int idx = tid + 256 * i;
            int row = idx >> 3, c4 = idx & 7;
            cp16(bu + row * (APITCH * 4) + c4 * 16,
                 W + (size_t)(n0 + row) * KDIM + k0 + c4 * 4);
        }
        CP_COMMIT();
    };

    float acc[4][8][4];
    #pragma unroll
    for (int i = 0; i < 4; i++)
        #pragma unroll
        for (int j = 0; j < 8; j++)
            #pragma unroll
            for (int q = 0; q < 4; q++) acc[i][j][q] = 0.f;

    load_chunk(0, 0);
    load_chunk(1, 1);

    for (int j = 0; j < NCHUNK; j++) {
        if (j < NCHUNK - 2) CP_WAIT(1); else CP_WAIT(0);
        __syncthreads();

        if (j + 2 < NCHUNK) load_chunk(j + 2, (j + 2) % STG);

        const int st = j % STG;
        const float* as = Asm + st * A_ST_FLOATS + (wm * 64 + g) * APITCH + t;
        const float* bs = Bsm + st * B_ST_FLOATS + (wn * 64 + g) * APITCH + t;

        #pragma unroll
        for (int c = 0; c < 4; c++) {
            const int kc = c * 8;
            uint32_t af[4][4], bf[8][2];
            #pragma unroll
            for (int mt = 0; mt < 4; mt++) {
                af[mt][0] = __float_as_uint(as[(mt * 16 + 0) * APITCH + kc]);
                af[mt][1] = __float_as_uint(as[(mt * 16 + 8) * APITCH + kc]);
                af[mt][2] = __float_as_uint(as[(mt * 16 + 0) * APITCH + kc + 4]);
                af[mt][3] = __float_as_uint(as[(mt * 16 + 8) * APITCH + kc + 4]);
            }
            #pragma unroll
            for (int nt = 0; nt < 8; nt++) {
                bf[nt][0] = __float_as_uint(bs[nt * 8 * APITCH + kc]);
                bf[nt][1] = __float_as_uint(bs[nt * 8 * APITCH + kc + 4]);
            }
            #pragma unroll
            for (int mt = 0; mt < 4; mt++)
                #pragma unroll
                for (int nt = 0; nt < 8; nt++)
                    mma_tf32(acc[mt][nt][0], acc[mt][nt][1], acc[mt][nt][2], acc[mt][nt][3],
                             af[mt][0], af[mt][1], af[mt][2], af[mt][3],
                             bf[nt][0], bf[nt][1]);
        }
        __syncthreads();
    }

    // ---- epilogue ----
    #pragma unroll
    for (int nt = 0; nt < 8; nt++) {
        const int col = n0 + wn * 64 + nt * 8 + 2 * t;
        float bx = 0.f, by = 0.f;
        if (bias) { bx = bias[col]; by = bias[col + 1]; }
        #pragma unroll
        for (int mt = 0; mt < 4; mt++) {
            const int r0 = wm * 64 + mt * 16 + g;
            float2 v0, v1;
            v0.x = acc[mt][nt][0] + bx; v0.y = acc[mt][nt][1] + by;
            v1.x = acc[mt][nt][2] + bx; v1.y = acc[mt][nt][3] + by;
            *(float2*)(C + (size_t)r0 * N + col)       = v0;
            *(float2*)(C + (size_t)(r0 + 8) * N + col) = v1;
        }
    }
}

// ---------------- RMSNorm + RoPE + head split ----------------
__global__ void norm_rope(const float* __restrict__ cosb, const float* __restrict__ sinb,
                          const float* __restrict__ nqw,  const float* __restrict__ nkw,
                          const float* __restrict__ naqw, const float* __restrict__ nakw)
{
    const int s = blockIdx.x / NH, h = blockIdx.x % NH;
    const int which = blockIdx.y;
    const int dh = threadIdx.x;

    float x = g_qkv[(size_t)s * ND3 + which * D + h * DH + dh];
    float* dst = (which == 0 ? g_q : which == 1 ? g_k : g_v)
                 + ((size_t)h * S_TOT + s) * DH + dh;

    if (which == 2) { *dst = x; return; }

    __shared__ float sh[128];
    __shared__ float red[4];

    float sq = x * x;
    #pragma unroll
    for (int o = 16; o; o >>= 1) sq += __shfl_xor_sync(0xffffffff, sq, o);
    if ((dh & 31) == 0) red[dh >> 5] = sq;
    __syncthreads();
    float msum = red[0] + red[1] + red[2] + red[3];
    float r = rsqrtf(msum * (1.0f / 128.0f) + EPS);

    const float* w;
    if (which == 0) w = (s < TXT) ? naqw : nqw;
    else            w = (s < TXT) ? nakw : nkw;

    float xn = x * r * w[dh];
    sh[dh] = xn;
    __syncthreads();

    float c  = cosb[s * 64 + (dh >> 1)];
    float sn = sinb[s * 64 + (dh >> 1)];
    float other = sh[dh ^ 1];
    float o = (dh & 1) ? fmaf(xn, c,  other * sn)
                       : fmaf(xn, c, -other * sn);
    *dst = o;
}

// ---------------- Flash attention, fp32 (output pre-rounded to tf32) ----------------
#define FBM 64
#define FBN 64
#define FPAD 68

extern __shared__ float fsm[];

__global__ __launch_bounds__(256, 1)
void flash_attn()
{
    float* Qst = fsm;
    float* Kst = Qst + 128 * FPAD;
    float* Vs  = Kst + 128 * FPAD;
    float* Ss  = Vs + FBN * DH;
    __shared__ float mrow[FBM], lrow[FBM], arow[FBM];

    const int h  = blockIdx.y;
    const int q0 = blockIdx.x * FBM;
    const int tid = threadIdx.x;
    const int tx = tid & 15, ty = tid >> 4;

    const float* Q = g_q + (size_t)h * S_TOT * DH;
    const float* K = g_k + (size_t)h * S_TOT * DH;
    const float* V = g_v + (size_t)h * S_TOT * DH;

    for (int i = tid; i < FBM * DH; i += 256) {
        int r = i >> 7, dh = i & 127;
        Qst[dh * FPAD + r] = Q[(size_t)(q0 + r) * DH + dh];
    }
    if (tid < FBM) { mrow[tid] = -3.4e38f; lrow[tid] = 0.f; }

    float Oacc[4][8];
    #pragma unroll
    for (int i = 0; i < 4; i++)
        #pragma unroll
        for (int j = 0; j < 8; j++) Oacc[i][j] = 0.f;
    __syncthreads();

    for (int kv0 = 0; kv0 < S_TOT; kv0 += FBN) {
        for (int i = tid; i < FBN * DH; i += 256) {
            int r = i >> 7, dh = i & 127;
            Kst[dh * FPAD + r] = K[(size_t)(kv0 + r) * DH + dh];
        }
        for (int i = tid * 4; i < FBN * DH; i += 256 * 4)
            *(float4*)(Vs + i) = *(const float4*)(V + (size_t)kv0 * DH + i);
        __syncthreads();

        float sacc[4][4];
        #pragma unroll
        for (int i = 0; i < 4; i++)
            #pragma unroll
            for (int j = 0; j < 4; j++) sacc[i][j] = 0.f;

        for (int k = 0; k < DH; k++) {
            float4 rav = *(const float4*)(Qst + k * FPAD + ty * 4);
            float4 rbv = *(const float4*)(Kst + k * FPAD + tx * 4);
            float ra[4] = {rav.x, rav.y, rav.z, rav.w};
            float rb[4] = {rbv.x, rbv.y, rbv.z, rbv.w};
            #pragma unroll
            for (int i = 0; i < 4; i++)
                #pragma unroll
                for (int j = 0; j < 4; j++)
                    sacc[i][j] = fmaf(ra[i], rb[j], sacc[i][j]);
        }
        #pragma unroll
        for (int i = 0; i < 4; i++)
            #pragma unroll
            for (int j = 0; j < 4; j++)
                Ss[(ty * 4 + i) * FPAD + tx * 4 + j] = sacc[i][j] * ATT_SCALE;
        __syncthreads();

        {
            const int row = tid >> 2, segi = tid & 3;
            float* Srow = Ss + row * FPAD + segi * 16;
            float mx = -3.4e38f;
            #pragma unroll
            for (int c = 0; c < 16; c++) mx = fmaxf(mx, Srow[c]);
            mx = fmaxf(mx, __shfl_xor_sync(0xffffffff, mx, 1));
            mx = fmaxf(mx, __shfl_xor_sync(0xffffffff, mx, 2));
            float mold = mrow[row];
            float mnew = fmaxf(mold, mx);
            float lsum = 0.f;
            #pragma unroll
            for (int c = 0; c < 16; c++) {
                float p = __expf(Srow[c] - mnew);
                Srow[c] = p;
                lsum += p;
            }
            lsum += __shfl_xor_sync(0xffffffff, lsum, 1);
            lsum += __shfl_xor_sync(0xffffffff, lsum, 2);
            if (segi == 0) {
                float alpha = __expf(mold - mnew);
                arow[row] = alpha;
                lrow[row] = lrow[row] * alpha + lsum;
                mrow[row] = mnew;
            }
        }
        __syncthreads();

        float al[4];
        #pragma unroll
        for (int i = 0; i < 4; i++) al[i] = arow[ty * 4 + i];
        #pragma unroll
        for (int i = 0; i < 4; i++)
            #pragma unroll
            for (int j = 0; j < 8; j++) Oacc[i][j] *= al[i];

        for (int j = 0; j < FBN; j++) {
            float p[4];
            #pragma unroll
            for (int i = 0; i < 4; i++) p[i] = Ss[(ty * 4 + i) * FPAD + j];
            float4 v0 = *(const float4*)(Vs + j * DH + tx * 8);
            float4 v1 = *(const float4*)(Vs + j * DH + tx * 8 + 4);
            float vv[8] = {v0.x, v0.y, v0.z, v0.w, v1.x, v1.y, v1.z, v1.w};
            #pragma unroll
            for (int i = 0; i < 4; i++)
                #pragma unroll
                for (int cc = 0; cc < 8; cc++)
                    Oacc[i][cc] = fmaf(p[i], vv[cc], Oacc[i][cc]);
        }
        __syncthreads();
    }

    float linv[4];
    #pragma unroll
    for (int i = 0; i < 4; i++) linv[i] = 1.0f / lrow[ty * 4 + i];
    #pragma unroll
    for (int i = 0; i < 4; i++) {
        float* dst = g_attn + (size_t)(q0 + ty * 4 + i) * D + h * DH + tx * 8;
        float4 o0, o1;
        o0.x = rtf32(Oacc[i][0] * linv[i]); o0.y = rtf32(Oacc[i][1] * linv[i]);
        o0.z = rtf32(Oacc[i][2] * linv[i]); o0.w = rtf32(Oacc[i][3] * linv[i]);
        o1.x = rtf32(Oacc[i][4] * linv[i]); o1.y = rtf32(Oacc[i][5] * linv[i]);
        o1.z = rtf32(Oacc[i][6] * linv[i]); o1.w = rtf32(Oacc[i][7] * linv[i]);
        *(float4*)(dst)     = o0;
        *(float4*)(dst + 4) = o1;
    }
}

// ---------------- launch ----------------
extern "C" void kernel_launch(void* const* d_in, const int* in_sizes, int n_in,
                              void* d_out, int out_size)
{
    const float* hidden     = (const float*)d_in[0];
    const float* encoder    = (const float*)d_in[1];
    const float* cosb       = (const float*)d_in[2];
    const float* sinb       = (const float*)d_in[3];
    const float* w_qkv      = (const float*)d_in[4];
    const float* w_add_qkv  = (const float*)d_in[5];
    const float* b_add_qkv  = (const float*)d_in[6];
    const float* norm_q_w   = (const float*)d_in[7];
    const float* norm_k_w   = (const float*)d_in[8];
    const float* norm_aq_w  = (const float*)d_in[9];
    const float* norm_ak_w  = (const float*)d_in[10];
    const float* w_out      = (const float*)d_in[11];
    const float* b_out      = (const float*)d_in[12];
    const float* w_add_out  = (const float*)d_in[13];
    const float* b_add_out  = (const float*)d_in[14];
    float* out = (float*)d_out;

    float *qkv, *attn, *x, *wq, *waq, *wo, *wao;
    cudaGetSymbolAddress((void**)&qkv,  g_qkv);
    cudaGetSymbolAddress((void**)&attn, g_attn);
    cudaGetSymbolAddress((void**)&x,    g_x);
    cudaGetSymbolAddress((void**)&wq,   g_wqkv);
    cudaGetSymbolAddress((void**)&waq,  g_waddqkv);
    cudaGetSymbolAddress((void**)&wo,   g_wout);
    cudaGetSymbolAddress((void**)&wao,  g_waddout);

    const int FLASH_SMEM = (128 * FPAD + 128 * FPAD + FBN * DH + FBM * FPAD) * 4;
    cudaFuncSetAttribute(flash_attn, cudaFuncAttributeMaxDynamicSharedMemorySize, FLASH_SMEM);
    cudaFuncSetAttribute(gemm_tf32, cudaFuncAttributeMaxDynamicSharedMemorySize, GEMM_SMEM_BYTES);

    // 0) tf32 pre-round: activations and weights
    auto launch_round = [](const float* s, float* d, size_t n) {
        int n4 = (int)(n / 4);
        tf32_round<<<(n4 + 255) / 256, 256>>>((const float4*)s, (float4*)d, n4);
    };
    launch_round(encoder, x,               (size_t)TXT * D);
    launch_round(hidden,  x + (size_t)TXT * D, (size_t)IMG * D);
    launch_round(w_qkv,     wq,  (size_t)ND3 * D);
    launch_round(w_add_qkv, waq, (size_t)ND3 * D);
    launch_round(w_out,     wo,  (size_t)D * D);
    launch_round(w_add_out, wao, (size_t)D * D);

    // 1) QKV projection (tf32 mma.sync)
    gemm_tf32<<<dim3(ND3 / BN, S_TOT / BM), 256, GEMM_SMEM_BYTES>>>(
        x, waq, wq, b_add_qkv, nullptr,
        qkv, qkv + (size_t)TXT * ND3, TXT, ND3);

    // 2) RMSNorm + RoPE + head split
    norm_rope<<<dim3(S_TOT * NH, 3), 128>>>(cosb, sinb, norm_q_w, norm_k_w,
                                            norm_aq_w, norm_ak_w);

    // 3) Flash attention (fp32, tf32-rounded output)
    flash_attn<<<dim3(S_TOT / FBM, NH), 256, FLASH_SMEM>>>();

    // 4) Output projections (tf32 mma.sync)
    gemm_tf32<<<dim3(D / BN, S_TOT / BM), 256, GEMM_SMEM_BYTES>>>(
        attn, wao, wo, b_add_out, b_out,
        out + (size_t)IMG * D, out, TXT, D);
}

// round 4
// speedup vs baseline: 4.2625x; 2.5611x over previous
#include <cuda_runtime.h>
#include <math.h>
#include <stdint.h>

#define S_TOT 2560
#define TXT 256
#define IMG 2304
#define D 3072
#define NH 24
#define DH 128
#define ND3 9216
#define KDIM 3072
#define ATT_SCALE 0.08838834764831845f   // 1/sqrt(128)
#define CEXP (1.4426950408889634f * ATT_SCALE)
#define EPS 1e-5f

// ---------------- scratch (device globals: no allocation allowed) ----------------
__device__ float g_qkv[(size_t)S_TOT * ND3];
__device__ float g_qf[(size_t)NH * S_TOT * DH];   // fragment-packed tf32
__device__ float g_kf[(size_t)NH * S_TOT * DH];
__device__ float g_vf[(size_t)NH * S_TOT * DH];
__device__ float g_attn[(size_t)S_TOT * D];
// tf32-prerounded copies
__device__ float g_x[(size_t)S_TOT * D];
__device__ float g_wqkv[(size_t)ND3 * D];
__device__ float g_waddqkv[(size_t)ND3 * D];
__device__ float g_wout[(size_t)D * D];
__device__ float g_waddout[(size_t)D * D];

// ================= helpers =================
static __device__ __forceinline__ uint32_t smem_u32(const void* p) {
    uint32_t r;
    asm("{ .reg .u64 t; cvta.to.shared.u64 t, %1; cvt.u32.u64 %0, t; }" : "=r"(r) : "l"(p));
    return r;
}
static __device__ __forceinline__ float rtf32(float x) {
    uint32_t r;
    asm("cvt.rna.tf32.f32 %0, %1;" : "=r"(r) : "f"(x));
    return __uint_as_float(r);
}
static __device__ __forceinline__ void cp16(uint32_t dst, const float* src) {
    asm volatile("cp.async.cg.shared.global [%0], [%1], 16;" :: "r"(dst), "l"(src));
}
#define CP_COMMIT() asm volatile("cp.async.commit_group;" ::: "memory")
#define CP_WAIT(n)  asm volatile("cp.async.wait_group %0;" :: "n"(n) : "memory")

static __device__ __forceinline__ void mma_tf32(
    float& c0, float& c1, float& c2, float& c3,
    uint32_t a0, uint32_t a1, uint32_t a2, uint32_t a3,
    uint32_t b0, uint32_t b1)
{
    asm volatile(
        "mma.sync.aligned.m16n8k8.row.col.f32.tf32.tf32.f32 "
        "{%0,%1,%2,%3}, {%4,%5,%6,%7}, {%8,%9}, {%0,%1,%2,%3};"
        : "+f"(c0), "+f"(c1), "+f"(c2), "+f"(c3)
        : "r"(a0), "r"(a1), "r"(a2), "r"(a3), "r"(b0), "r"(b1));
}

// ---------------- tf32 pre-round ----------------
__global__ void tf32_round(const float4* __restrict__ src, float4* __restrict__ dst, int n4)
{
    int i = blockIdx.x * blockDim.x + threadIdx.x;
    if (i < n4) {
        float4 v = src[i];
        v.x = rtf32(v.x); v.y = rtf32(v.y); v.z = rtf32(v.z); v.w = rtf32(v.w);
        dst[i] = v;
    }
}

// ================= tf32 mma.sync GEMM (unchanged from R3) =================
#define BM 128
#define BN 256
#define BK 32
#define STG 3
#define NCHUNK (KDIM / BK)       // 96
#define APITCH 36
#define A_ST_FLOATS (BM * APITCH)
#define B_ST_FLOATS (BN * APITCH)
#define GEMM_SMEM_BYTES (STG * (A_ST_FLOATS + B_ST_FLOATS) * 4)

__global__ __launch_bounds__(256, 1)
void gemm_tf32(const float* __restrict__ A,
               const float* __restrict__ W0, const float* __restrict__ W1,
               const float* __restrict__ b0, const float* __restrict__ b1,
               float* __restrict__ C0, float* __restrict__ C1,
               int M0, int N)
{
    extern __shared__ float sm[];
    float* Asm = sm;
    float* Bsm = sm + STG * A_ST_FLOATS;

    const int tid  = threadIdx.x;
    const int lane = tid & 31;
    const int wid  = tid >> 5;
    const int wm   = wid >> 2;
    const int wn   = wid & 3;
    const int g    = lane >> 2;
    const int t    = lane & 3;

    const int bm = blockIdx.y, bn = blockIdx.x;
    const int rowbase = bm * BM;
    const int n0 = bn * BN;

    const float* Ab = A + (size_t)rowbase * KDIM;
    const float* W; const float* bias; float* C;
    if (rowbase < M0) { W = W0; bias = b0; C = C0 + (size_t)rowbase * N; }
    else              { W = W1; bias = b1; C = C1 + (size_t)(rowbase - M0) * N; }

    const uint32_t asu_base = smem_u32(Asm);
    const uint32_t bsu_base = smem_u32(Bsm);

    auto load_chunk = [&](int ck, int st) {
        const int k0 = ck * BK;
        const uint32_t au = asu_base + st * (A_ST_FLOATS * 4);
        const uint32_t bu = bsu_base + st * (B_ST_FLOATS * 4);
        #pragma unroll
        for (int i = 0; i < 4; i++) {
            int idx = tid + 256 * i;
            int row = idx >> 3, c4 = idx & 7;
            cp16(au + row * (APITCH * 4) + c4 * 16,
                 Ab + (size_t)row * KDIM + k0 + c4 * 4);
        }
        #pragma unroll
        for (int i = 0; i < 8; i++) {
            int idx = tid + 256 * i;
            int row = idx >> 3, c4 = idx & 7;
            cp16(bu + row * (APITCH * 4) + c4 * 16,
                 W + (size_t)(n0 + row) * KDIM + k0 + c4 * 4);
        }
        CP_COMMIT();
    };

    float acc[4][8][4];
    #pragma unroll
    for (int i = 0; i < 4; i++)
        #pragma unroll
        for (int j = 0; j < 8; j++)
            #pragma unroll
            for (int q = 0; q < 4; q++) acc[i][j][q] = 0.f;

    load_chunk(0, 0);
    load_chunk(1, 1);

    for (int j = 0; j < NCHUNK; j++) {
        if (j < NCHUNK - 2) CP_WAIT(1); else CP_WAIT(0);
        __syncthreads();

        if (j + 2 < NCHUNK) load_chunk(j + 2, (j + 2) % STG);

        const int st = j % STG;
        const float* as = Asm + st * A_ST_FLOATS + (wm * 64 + g) * APITCH + t;
        const float* bs = Bsm + st * B_ST_FLOATS + (wn * 64 + g) * APITCH + t;

        #pragma unroll
        for (int c = 0; c < 4; c++) {
            const int kc = c * 8;
            uint32_t af[4][4], bf[8][2];
            #pragma unroll
            for (int mt = 0; mt < 4; mt++) {
                af[mt][0] = __float_as_uint(as[(mt * 16 + 0) * APITCH + kc]);
                af[mt][1] = __float_as_uint(as[(mt * 16 + 8) * APITCH + kc]);
                af[mt][2] = __float_as_uint(as[(mt * 16 + 0) * APITCH + kc + 4]);
                af[mt][3] = __float_as_uint(as[(mt * 16 + 8) * APITCH + kc + 4]);
            }
            #pragma unroll
            for (int nt = 0; nt < 8; nt++) {
                bf[nt][0] = __float_as_uint(bs[nt * 8 * APITCH + kc]);
                bf[nt][1] = __float_as_uint(bs[nt * 8 * APITCH + kc + 4]);
            }
            #pragma unroll
            for (int mt = 0; mt < 4; mt++)
                #pragma unroll
                for (int nt = 0; nt < 8; nt++)
                    mma_tf32(acc[mt][nt][0], acc[mt][nt][1], acc[mt][nt][2], acc[mt][nt][3],
                             af[mt][0], af[mt][1], af[mt][2], af[mt][3],
                             bf[nt][0], bf[nt][1]);
        }
        __syncthreads();
    }

    #pragma unroll
    for (int nt = 0; nt < 8; nt++) {
        const int col = n0 + wn * 64 + nt * 8 + 2 * t;
        float bx = 0.f, by = 0.f;
        if (bias) { bx = bias[col]; by = bias[col + 1]; }
        #pragma unroll
        for (int mt = 0; mt < 4; mt++) {
            const int r0 = wm * 64 + mt * 16 + g;
            float2 v0, v1;
            v0.x = acc[mt][nt][0] + bx; v0.y = acc[mt][nt][1] + by;
            v1.x = acc[mt][nt][2] + bx; v1.y = acc[mt][nt][3] + by;
            *(float2*)(C + (size_t)r0 * N + col)       = v0;
            *(float2*)(C + (size_t)(r0 + 8) * N + col) = v1;
        }
    }
}

// ---------------- RMSNorm + RoPE + head split into fragment-packed layouts ----------------
// Q packed:  [h][s/16][dh/8][128]; chunk idx = ((s&7)*4 + (dh&3))*4 + ((s>>3)&1) + 2*((dh>>2)&1)
// K packed:  [h][s/8][dh/8][64];   chunk idx = ((s&7)*4 + (dh&3))*2 + ((dh>>2)&1)
// V packed:  [h][s/8][dh/8][64];   chunk idx = ((dh&7)*4 + (s&3))*2 + ((s>>2)&1)
__global__ void norm_rope(const float* __restrict__ cosb, const float* __restrict__ sinb,
                          const float* __restrict__ nqw,  const float* __restrict__ nkw,
                          const float* __restrict__ naqw, const float* __restrict__ nakw)
{
    const int s = blockIdx.x / NH, h = blockIdx.x % NH;
    const int which = blockIdx.y;
    const int dh = threadIdx.x;

    float x = g_qkv[(size_t)s * ND3 + which * D + h * DH + dh];

    if (which == 2) {
        size_t off = (((size_t)h * (S_TOT / 8) + (s >> 3)) * 16 + (dh >> 3)) * 64
                   + (size_t)(((dh & 7) * 4 + (s & 3)) * 2 + ((s >> 2) & 1));
        g_vf[off] = rtf32(x);
        return;
    }

    __shared__ float sh[128];
    __shared__ float red[4];

    float sq = x * x;
    #pragma unroll
    for (int o = 16; o; o >>= 1) sq += __shfl_xor_sync(0xffffffff, sq, o);
    if ((dh & 31) == 0) red[dh >> 5] = sq;
    __syncthreads();
    float msum = red[0] + red[1] + red[2] + red[3];
    float r = rsqrtf(msum * (1.0f / 128.0f) + EPS);

    const float* w;
    if (which == 0) w = (s < TXT) ? naqw : nqw;
    else            w = (s < TXT) ? nakw : nkw;

    float xn = x * r * w[dh];
    sh[dh] = xn;
    __syncthreads();

    float c  = cosb[s * 64 + (dh >> 1)];
    float sn = sinb[s * 64 + (dh >> 1)];
    float other = sh[dh ^ 1];
    float o = (dh & 1) ? fmaf(xn, c,  other * sn)
                       : fmaf(xn, c, -other * sn);
    o = rtf32(o);

    if (which == 0) {
        size_t off = (((size_t)h * (S_TOT / 16) + (s >> 4)) * 16 + (dh >> 3)) * 128
                   + (size_t)(((s & 7) * 4 + (dh & 3)) * 4 + ((s >> 3) & 1) + 2 * ((dh >> 2) & 1));
        g_qf[off] = o;
    } else {
        size_t off = (((size_t)h * (S_TOT / 8) + (s >> 3)) * 16 + (dh >> 3)) * 64
                   + (size_t)(((s & 7) * 4 + (dh & 3)) * 2 + ((dh >> 2) & 1));
        g_kf[off] = o;
    }
}

// ---------------- Flash attention, tf32 mma.sync ----------------
// q-tile 128 (8 warps x 16 rows), kv-tile 32, double-buffered K/V.
#define QT 128
#define KT 32
#define NKV (S_TOT / KT)     // 80
#define PPITCH 36
#define FQ_FLOATS (16 * 16 * 128)   // 8 mb x 16 kb x 128 = 16384
#define FK_FLOATS 4096              // 4 kvb x 16 kb x 64
#define FLASH_SMEM ((16384 + 2*4096 + 2*4096 + 128*PPITCH) * 4)

extern __shared__ float fsm[];

__global__ __launch_bounds__(256, 1)
void flash_tc()
{
    float* Qs = fsm;                         // 16384
    float* Ks = fsm + 16384;                 // 2 x 4096
    float* Vs = fsm + 16384 + 8192;          // 2 x 4096
    float* Ps = fsm + 16384 + 16384;         // 128 x 36

    const int h   = blockIdx.y;
    const int q0  = blockIdx.x * QT;
    const int tid = threadIdx.x;
    const int lane = tid & 31, wid = tid >> 5;
    const int g = lane >> 2, t = lane & 3;
    const int m0 = wid * 16;

    const float* Qg = g_qf + ((size_t)h * (S_TOT / 16) + (q0 >> 4)) * (16 * 128);
    const float* Kg = g_kf + (size_t)h * (S_TOT / 8) * (16 * 64);
    const float* Vg = g_vf + (size_t)h * (S_TOT / 8) * (16 * 64);

    const uint32_t qs_u = smem_u32(Qs);
    const uint32_t ks_u = smem_u32(Ks);
    const uint32_t vs_u = smem_u32(Vs);

    // load Q tile (16384 floats)
    #pragma unroll
    for (int i = 0; i < 16; i++)
        cp16(qs_u + (uint32_t)(tid + 256 * i) * 16, Qg + (size_t)(tid + 256 * i) * 4);
    CP_COMMIT();

    auto loadKV = [&](int j, int st) {
        const float* kp = Kg + (size_t)j * 4096;
        const float* vp = Vg + (size_t)j * 4096;
        uint32_t ku = ks_u + st * (4096 * 4);
        uint32_t vu = vs_u + st * (4096 * 4);
        #pragma unroll
        for (int i = 0; i < 4; i++) {
            cp16(ku + (uint32_t)(tid + 256 * i) * 16, kp + (size_t)(tid + 256 * i) * 4);
            cp16(vu + (uint32_t)(tid + 256 * i) * 16, vp + (size_t)(tid + 256 * i) * 4);
        }
        CP_COMMIT();
    };
    loadKV(0, 0);

    float oc[16][4];
    #pragma unroll
    for (int nt = 0; nt < 16; nt++)
        #pragma unroll
        for (int q = 0; q < 4; q++) oc[nt][q] = 0.f;
    float mr0 = -3.4e38f, mr1 = -3.4e38f, lr0 = 0.f, lr1 = 0.f;

    for (int j = 0; j < NKV; j++) {
        if (j + 1 < NKV) { loadKV(j + 1, (j + 1) & 1); CP_WAIT(1); }
        else             { CP_WAIT(0); }
        __syncthreads();

        const float* Kst = Ks + (j & 1) * 4096;
        const float* Vst = Vs + (j & 1) * 4096;

        // ---- QK^T: S[16 x 32] per warp ----
        float sc[4][4];
        #pragma unroll
        for (int nt = 0; nt < 4; nt++)
            #pragma unroll
            for (int q = 0; q < 4; q++) sc[nt][q] = 0.f;

        #pragma unroll
        for (int kc = 0; kc < 16; kc++) {
            float4 a = *(const float4*)(Qs + ((wid * 16 + kc) << 7) + lane * 4);
            #pragma unroll
            for (int nt = 0; nt < 4; nt++) {
                float2 b = *(const float2*)(Kst + ((nt * 16 + kc) << 6) + lane * 2);
                mma_tf32(sc[nt][0], sc[nt][1], sc[nt][2], sc[nt][3],
                         __float_as_uint(a.x), __float_as_uint(a.y),
                         __float_as_uint(a.z), __float_as_uint(a.w),
                         __float_as_uint(b.x), __float_as_uint(b.y));
            }
        }

        // ---- online softmax (registers; rows g and g+8) ----
        float mx0 = -3.4e38f, mx1 = -3.4e38f;
        #pragma unroll
        for (int nt = 0; nt < 4; nt++) {
            mx0 = fmaxf(mx0, fmaxf(sc[nt][0], sc[nt][1]));
            mx1 = fmaxf(mx1, fmaxf(sc[nt][2], sc[nt][3]));
        }
        mx0 = fmaxf(mx0, __shfl_xor_sync(0xffffffff, mx0, 1));
        mx0 = fmaxf(mx0, __shfl_xor_sync(0xffffffff, mx0, 2));
        mx1 = fmaxf(mx1, __shfl_xor_sync(0xffffffff, mx1, 1));
        mx1 = fmaxf(mx1, __shfl_xor_sync(0xffffffff, mx1, 2));

        float mn0 = fmaxf(mr0, mx0), mn1 = fmaxf(mr1, mx1);
        float al0 = exp2f((mr0 - mn0) * CEXP);
        float al1 = exp2f((mr1 - mn1) * CEXP);
        mr0 = mn0; mr1 = mn1;

        float s0 = 0.f, s1 = 0.f;
        #pragma unroll
        for (int nt = 0; nt < 4; nt++) {
            sc[nt][0] = exp2f((sc[nt][0] - mn0) * CEXP);
            sc[nt][1] = exp2f((sc[nt][1] - mn0) * CEXP);
            sc[nt][2] = exp2f((sc[nt][2] - mn1) * CEXP);
            sc[nt][3] = exp2f((sc[nt][3] - mn1) * CEXP);
            s0 += sc[nt][0] + sc[nt][1];
            s1 += sc[nt][2] + sc[nt][3];
        }
        s0 += __shfl_xor_sync(0xffffffff, s0, 1);
        s0 += __shfl_xor_sync(0xffffffff, s0, 2);
        s1 += __shfl_xor_sync(0xffffffff, s1, 1);
        s1 += __shfl_xor_sync(0xffffffff, s1, 2);
        lr0 = lr0 * al0 + s0;
        lr1 = lr1 * al1 + s1;

        #pragma unroll
        for (int nt = 0; nt < 16; nt++) {
            oc[nt][0] *= al0; oc[nt][1] *= al0;
            oc[nt][2] *= al1; oc[nt][3] *= al1;
        }

        // ---- store P (tf32) to smem, re-fragment as A ----
        #pragma unroll
        for (int nt = 0; nt < 4; nt++) {
            float2 p0; p0.x = rtf32(sc[nt][0]); p0.y = rtf32(sc[nt][1]);
            float2 p1; p1.x = rtf32(sc[nt][2]); p1.y = rtf32(sc[nt][3]);
            *(float2*)(Ps + (m0 + g) * PPITCH + nt * 8 + 2 * t)     = p0;
            *(float2*)(Ps + (m0 + g + 8) * PPITCH + nt * 8 + 2 * t) = p1;
        }
        __syncwarp();

        // ---- P @ V: O[16 x 128] per warp ----
        #pragma unroll
        for (int kc = 0; kc < 4; kc++) {
            uint32_t a0 = __float_as_uint(Ps[(m0 + g) * PPITCH + kc * 8 + t]);
            uint32_t a1 = __float_as_uint(Ps[(m0 + g + 8) * PPITCH + kc * 8 + t]);
            uint32_t a2 = __float_as_uint(Ps[(m0 + g) * PPITCH + kc * 8 + t + 4]);
            uint32_t a3 = __float_as_uint(Ps[(m0 + g + 8) * PPITCH + kc * 8 + t + 4]);
            #pragma unroll
            for (int nt = 0; nt < 16; nt++) {
                float2 b = *(const float2*)(Vst + ((kc * 16 + nt) << 6) + lane * 2);
                mma_tf32(oc[nt][0], oc[nt][1], oc[nt][2], oc[nt][3],
                         a0, a1, a2, a3,
                         __float_as_uint(b.x), __float_as_uint(b.y));
            }
        }
        __syncthreads();
    }

    // ---- normalize + write (tf32-rounded for the out-proj GEMM) ----
    float li0 = 1.f / lr0, li1 = 1.f / lr1;
    float* orow0 = g_attn + (size_t)(q0 + m0 + g) * D + h * DH;
    float* orow1 = orow0 + (size_t)8 * D;
    #pragma unroll
    for (int nt = 0; nt < 16; nt++) {
        float2 w0, w1;
        w0.x = rtf32(oc[nt][0] * li0); w0.y = rtf32(oc[nt][1] * li0);
        w1.x = rtf32(oc[nt][2] * li1); w1.y = rtf32(oc[nt][3] * li1);
        *(float2*)(orow0 + nt * 8 + 2 * t) = w0;
        *(float2*)(orow1 + nt * 8 + 2 * t) = w1;
    }
}

// ---------------- launch ----------------
extern "C" void kernel_launch(void* const* d_in, const int* in_sizes, int n_in,
                              void* d_out, int out_size)
{
    const float* hidden     = (const float*)d_in[0];
    const float* encoder    = (const float*)d_in[1];
    const float* cosb       = (const float*)d_in[2];
    const float* sinb       = (const float*)d_in[3];
    const float* w_qkv      = (const float*)d_in[4];
    const float* w_add_qkv  = (const float*)d_in[5];
    const float* b_add_qkv  = (const float*)d_in[6];
    const float* norm_q_w   = (const float*)d_in[7];
    const float* norm_k_w   = (const float*)d_in[8];
    const float* norm_aq_w  = (const float*)d_in[9];
    const float* norm_ak_w  = (const float*)d_in[10];
    const float* w_out      = (const float*)d_in[11];
    const float* b_out      = (const float*)d_in[12];
    const float* w_add_out  = (const float*)d_in[13];
    const float* b_add_out  = (const float*)d_in[14];
    float* out = (float*)d_out;

    float *qkv, *attn, *x, *wq, *waq, *wo, *wao;
    cudaGetSymbolAddress((void**)&qkv,  g_qkv);
    cudaGetSymbolAddress((void**)&attn, g_attn);
    cudaGetSymbolAddress((void**)&x,    g_x);
    cudaGetSymbolAddress((void**)&wq,   g_wqkv);
    cudaGetSymbolAddress((void**)&waq,  g_waddqkv);
    cudaGetSymbolAddress((void**)&wo,   g_wout);
    cudaGetSymbolAddress((void**)&wao,  g_waddout);

    cudaFuncSetAttribute(flash_tc, cudaFuncAttributeMaxDynamicSharedMemorySize, FLASH_SMEM);
    cudaFuncSetAttribute(gemm_tf32, cudaFuncAttributeMaxDynamicSharedMemorySize, GEMM_SMEM_BYTES);

    // 0) tf32 pre-round: activations and weights
    auto launch_round = [](const float* s, float* d, size_t n) {
        int n4 = (int)(n / 4);
        tf32_round<<<(n4 + 255) / 256, 256>>>((const float4*)s, (float4*)d, n4);
    };
    launch_round(encoder, x,                   (size_t)TXT * D);
    launch_round(hidden,  x + (size_t)TXT * D, (size_t)IMG * D);
    launch_round(w_qkv,     wq,  (size_t)ND3 * D);
    launch_round(w_add_qkv, waq, (size_t)ND3 * D);
    launch_round(w_out,     wo,  (size_t)D * D);
    launch_round(w_add_out, wao, (size_t)D * D);

    // 1) QKV projection (tf32 mma.sync)
    gemm_tf32<<<dim3(ND3 / BN, S_TOT / BM), 256, GEMM_SMEM_BYTES>>>(
        x, waq, wq, b_add_qkv, nullptr,
        qkv, qkv + (size_t)TXT * ND3, TXT, ND3);

    // 2) RMSNorm + RoPE + split into fragment-packed q/k/v
    norm_rope<<<dim3(S_TOT * NH, 3), 128>>>(cosb, sinb, norm_q_w, norm_k_w,
                                            norm_aq_w, norm_ak_w);

    // 3) Flash attention (tf32 mma.sync)
    flash_tc<<<dim3(S_TOT / QT, NH), 256, FLASH_SMEM>>>();

    // 4) Output projections (tf32 mma.sync)
    gemm_tf32<<<dim3(D / BN, S_TOT / BM), 256, GEMM_SMEM_BYTES>>>(
        attn, wao, wo, b_add_out, b_out,
        out + (size_t)IMG * D, out, TXT, D);
}

// round 5
// speedup vs baseline: 5.6294x; 1.3207x over previous
#include <cuda_runtime.h>
#include <cuda_fp16.h>
#include <math.h>
#include <stdint.h>

#define S_TOT 2560
#define TXT 256
#define IMG 2304
#define D 3072
#define NH 24
#define DH 128
#define ND3 9216
#define KDIM 3072
#define ATT_SCALE 0.08838834764831845f   // 1/sqrt(128)
#define CEXP (1.4426950408889634f * ATT_SCALE)
#define EPS 1e-5f

// ---------------- scratch (device globals: no allocation allowed) ----------------
__device__ float g_qkv[(size_t)S_TOT * ND3];
__device__ float g_qf[(size_t)NH * S_TOT * DH];   // fragment-packed tf32
__device__ float g_kf[(size_t)NH * S_TOT * DH];
__device__ float g_vf[(size_t)NH * S_TOT * DH];
__device__ __half g_attnh[(size_t)S_TOT * D];
// fp16 copies
__device__ __half g_xh[(size_t)S_TOT * D];
__device__ __half g_wqkvh[(size_t)ND3 * D];
__device__ __half g_waddqkvh[(size_t)ND3 * D];
__device__ __half g_wouth[(size_t)D * D];
__device__ __half g_waddouth[(size_t)D * D];

// ================= helpers =================
static __device__ __forceinline__ uint32_t smem_u32(const void* p) {
    uint32_t r;
    asm("{ .reg .u64 t; cvta.to.shared.u64 t, %1; cvt.u32.u64 %0, t; }" : "=r"(r) : "l"(p));
    return r;
}
static __device__ __forceinline__ float rtf32(float x) {
    uint32_t r;
    asm("cvt.rna.tf32.f32 %0, %1;" : "=r"(r) : "f"(x));
    return __uint_as_float(r);
}
static __device__ __forceinline__ void cp16(uint32_t dst, const void* src) {
    asm volatile("cp.async.cg.shared.global [%0], [%1], 16;" :: "r"(dst), "l"(src));
}
#define CP_COMMIT() asm volatile("cp.async.commit_group;" ::: "memory")
#define CP_WAIT(n)  asm volatile("cp.async.wait_group %0;" :: "n"(n) : "memory")

static __device__ __forceinline__ void mma_tf32(
    float& c0, float& c1, float& c2, float& c3,
    uint32_t a0, uint32_t a1, uint32_t a2, uint32_t a3,
    uint32_t b0, uint32_t b1)
{
    asm volatile(
        "mma.sync.aligned.m16n8k8.row.col.f32.tf32.tf32.f32 "
        "{%0,%1,%2,%3}, {%4,%5,%6,%7}, {%8,%9}, {%0,%1,%2,%3};"
        : "+f"(c0), "+f"(c1), "+f"(c2), "+f"(c3)
        : "r"(a0), "r"(a1), "r"(a2), "r"(a3), "r"(b0), "r"(b1));
}
static __device__ __forceinline__ void mma_f16(
    float& c0, float& c1, float& c2, float& c3,
    uint32_t a0, uint32_t a1, uint32_t a2, uint32_t a3,
    uint32_t b0, uint32_t b1)
{
    asm volatile(
        "mma.sync.aligned.m16n8k16.row.col.f32.f16.f16.f32 "
        "{%0,%1,%2,%3}, {%4,%5,%6,%7}, {%8,%9}, {%0,%1,%2,%3};"
        : "+f"(c0), "+f"(c1), "+f"(c2), "+f"(c3)
        : "r"(a0), "r"(a1), "r"(a2), "r"(a3), "r"(b0), "r"(b1));
}

// ---------------- fp32 -> fp16 conversion pass ----------------
__global__ void f2h(const float4* __restrict__ src, __half2* __restrict__ dst, int n4)
{
    int i = blockIdx.x * blockDim.x + threadIdx.x;
    if (i < n4) {
        float4 v = src[i];
        dst[i * 2]     = __float22half2_rn(make_float2(v.x, v.y));
        dst[i * 2 + 1] = __float22half2_rn(make_float2(v.z, v.w));
    }
}

// ================= fp16 mma.sync GEMM =================
// C = A @ W^T (+bias), fp32 out. Block 128x256, BK=32 halves, 4 stages,
// 8 warps (2M x 4N) of 64x64 warp tiles, m16n8k16.
#define BM 128
#define BN 256
#define BK 32
#define GSTG 4
#define NCHUNK (KDIM / BK)       // 96
#define HPITCH 40                          // halves per row (80B)
#define A_SH (BM * HPITCH)                 // 5120 halves
#define B_SH (BN * HPITCH)                 // 10240 halves
#define GEMM_SMEM_BYTES (GSTG * (A_SH + B_SH) * 2)   // 122880

__global__ __launch_bounds__(256, 1)
void gemm_f16(const __half* __restrict__ A,
              const __half* __restrict__ W0, const __half* __restrict__ W1,
              const float* __restrict__ b0, const float* __restrict__ b1,
              float* __restrict__ C0, float* __restrict__ C1,
              int M0, int N)
{
    extern __shared__ __half hsm[];
    __half* Asm = hsm;
    __half* Bsm = hsm + GSTG * A_SH;

    const int tid  = threadIdx.x;
    const int lane = tid & 31;
    const int wid  = tid >> 5;
    const int wm   = wid >> 2;
    const int wn   = wid & 3;
    const int g    = lane >> 2;
    const int t    = lane & 3;

    const int bm = blockIdx.y, bn = blockIdx.x;
    const int rowbase = bm * BM;
    const int n0 = bn * BN;

    const __half* Ab = A + (size_t)rowbase * KDIM;
    const __half* W; const float* bias; float* C;
    if (rowbase < M0) { W = W0; bias = b0; C = C0 + (size_t)rowbase * N; }
    else              { W = W1; bias = b1; C = C1 + (size_t)(rowbase - M0) * N; }

    const uint32_t asu = smem_u32(Asm);
    const uint32_t bsu = smem_u32(Bsm);

    // ---- async chunk loader: A 512 x 16B, B 1024 x 16B ----
    auto load_chunk = [&](int ck, int st) {
        const int k0 = ck * BK;
        const uint32_t au = asu + st * (A_SH * 2);
        const uint32_t bu = bsu + st * (B_SH * 2);
        #pragma unroll
        for (int i = 0; i < 2; i++) {
            int idx = tid + 256 * i;
            int row = idx >> 2, c = idx & 3;
            cp16(au + row * (HPITCH * 2) + c * 16,
                 Ab + (size_t)row * KDIM + k0 + c * 8);
        }
        #pragma unroll
        for (int i = 0; i < 4; i++) {
            int idx = tid + 256 * i;
            int row = idx >> 2, c = idx & 3;
            cp16(bu + row * (HPITCH * 2) + c * 16,
                 W + (size_t)(n0 + row) * KDIM + k0 + c * 8);
        }
        CP_COMMIT();
    };

    float acc[4][8][4];
    #pragma unroll
    for (int i = 0; i < 4; i++)
        #pragma unroll
        for (int j = 0; j < 8; j++)
            #pragma unroll
            for (int q = 0; q < 4; q++) acc[i][j][q] = 0.f;

    load_chunk(0, 0); load_chunk(1, 1); load_chunk(2, 2);

    for (int j = 0; j < NCHUNK; j++) {
        if      (j < NCHUNK - 2) CP_WAIT(2);
        else if (j == NCHUNK - 2) CP_WAIT(1);
        else                      CP_WAIT(0);
        __syncthreads();

        if (j + 3 < NCHUNK) load_chunk(j + 3, (j + 3) & 3);

        const int st = j & 3;
        const __half* as = Asm + st * A_SH + (wm * 64 + g) * HPITCH;
        const __half* bs = Bsm + st * B_SH + (wn * 64 + g) * HPITCH;

        #pragma unroll
        for (int kc = 0; kc < 2; kc++) {
            const int co = kc * 16 + 2 * t;
            uint32_t af[4][4], bf[8][2];
            #pragma unroll
            for (int mt = 0; mt < 4; mt++) {
                af[mt][0] = *(const uint32_t*)(as + (mt * 16 + 0) * HPITCH + co);
                af[mt][1] = *(const uint32_t*)(as + (mt * 16 + 8) * HPITCH + co);
                af[mt][2] = *(const uint32_t*)(as + (mt * 16 + 0) * HPITCH + co + 8);
                af[mt][3] = *(const uint32_t*)(as + (mt * 16 + 8) * HPITCH + co + 8);
            }
            #pragma unroll
            for (int nt = 0; nt < 8; nt++) {
                bf[nt][0] = *(const uint32_t*)(bs + nt * 8 * HPITCH + co);
                bf[nt][1] = *(const uint32_t*)(bs + nt * 8 * HPITCH + co + 8);
            }
            #pragma unroll
            for (int mt = 0; mt < 4; mt++)
                #pragma unroll
                for (int nt = 0; nt < 8; nt++)
                    mma_f16(acc[mt][nt][0], acc[mt][nt][1], acc[mt][nt][2], acc[mt][nt][3],
                            af[mt][0], af[mt][1], af[mt][2], af[mt][3],
                            bf[nt][0], bf[nt][1]);
        }
    }

    // ---- epilogue ----
    #pragma unroll
    for (int nt = 0; nt < 8; nt++) {
        const int col = n0 + wn * 64 + nt * 8 + 2 * t;
        float bx = 0.f, by = 0.f;
        if (bias) { bx = bias[col]; by = bias[col + 1]; }
        #pragma unroll
        for (int mt = 0; mt < 4; mt++) {
            const int r0 = wm * 64 + mt * 16 + g;
            float2 v0, v1;
            v0.x = acc[mt][nt][0] + bx; v0.y = acc[mt][nt][1] + by;
            v1.x = acc[mt][nt][2] + bx; v1.y = acc[mt][nt][3] + by;
            *(float2*)(C + (size_t)r0 * N + col)       = v0;
            *(float2*)(C + (size_t)(r0 + 8) * N + col) = v1;
        }
    }
}

// ---------------- RMSNorm + RoPE + head split into fragment-packed layouts ----------------
__global__ void norm_rope(const float* __restrict__ cosb, const float* __restrict__ sinb,
                          const float* __restrict__ nqw,  const float* __restrict__ nkw,
                          const float* __restrict__ naqw, const float* __restrict__ nakw)
{
    const int s = blockIdx.x / NH, h = blockIdx.x % NH;
    const int which = blockIdx.y;
    const int dh = threadIdx.x;

    float x = g_qkv[(size_t)s * ND3 + which * D + h * DH + dh];

    if (which == 2) {
        size_t off = (((size_t)h * (S_TOT / 8) + (s >> 3)) * 16 + (dh >> 3)) * 64
                   + (size_t)(((dh & 7) * 4 + (s & 3)) * 2 + ((s >> 2) & 1));
        g_vf[off] = rtf32(x);
        return;
    }

    __shared__ float sh[128];
    __shared__ float red[4];

    float sq = x * x;
    #pragma unroll
    for (int o = 16; o; o >>= 1) sq += __shfl_xor_sync(0xffffffff, sq, o);
    if ((dh & 31) == 0) red[dh >> 5] = sq;
    __syncthreads();
    float msum = red[0] + red[1] + red[2] + red[3];
    float r = rsqrtf(msum * (1.0f / 128.0f) + EPS);

    const float* w;
    if (which == 0) w = (s < TXT) ? naqw : nqw;
    else            w = (s < TXT) ? nakw : nkw;

    float xn = x * r * w[dh];
    sh[dh] = xn;
    __syncthreads();

    float c  = cosb[s * 64 + (dh >> 1)];
    float sn = sinb[s * 64 + (dh >> 1)];
    float other = sh[dh ^ 1];
    float o = (dh & 1) ? fmaf(xn, c,  other * sn)
                       : fmaf(xn, c, -other * sn);
    o = rtf32(o);

    if (which == 0) {
        size_t off = (((size_t)h * (S_TOT / 16) + (s >> 4)) * 16 + (dh >> 3)) * 128
                   + (size_t)(((s & 7) * 4 + (dh & 3)) * 4 + ((s >> 3) & 1) + 2 * ((dh >> 2) & 1));
        g_qf[off] = o;
    } else {
        size_t off = (((size_t)h * (S_TOT / 8) + (s >> 3)) * 16 + (dh >> 3)) * 64
                   + (size_t)(((s & 7) * 4 + (dh & 3)) * 2 + ((dh >> 2) & 1));
        g_kf[off] = o;
    }
}

// ---------------- Flash attention, tf32 mma.sync (fp16 output) ----------------
#define QT 128
#define KT 32
#define NKV (S_TOT / KT)     // 80
#define PPITCH 36
#define FLASH_SMEM ((16384 + 2*4096 + 2*4096 + 128*PPITCH) * 4)

extern __shared__ float fsm[];

__global__ __launch_bounds__(256, 1)
void flash_tc()
{
    float* Qs = fsm;
    float* Ks = fsm + 16384;
    float* Vs = fsm + 16384 + 8192;
    float* Ps = fsm + 16384 + 16384;

    const int h   = blockIdx.y;
    const int q0  = blockIdx.x * QT;
    const int tid = threadIdx.x;
    const int lane = tid & 31, wid = tid >> 5;
    const int g = lane >> 2, t = lane & 3;
    const int m0 = wid * 16;

    const float* Qg = g_qf + ((size_t)h * (S_TOT / 16) + (q0 >> 4)) * (16 * 128);
    const float* Kg = g_kf + (size_t)h * (S_TOT / 8) * (16 * 64);
    const float* Vg = g_vf + (size_t)h * (S_TOT / 8) * (16 * 64);

    const uint32_t qs_u = smem_u32(Qs);
    const uint32_t ks_u = smem_u32(Ks);
    const uint32_t vs_u = smem_u32(Vs);

    #pragma unroll
    for (int i = 0; i < 16; i++)
        cp16(qs_u + (uint32_t)(tid + 256 * i) * 16, Qg + (size_t)(tid + 256 * i) * 4);
    CP_COMMIT();

    auto loadKV = [&](int j, int st) {
        const float* kp = Kg + (size_t)j * 4096;
        const float* vp = Vg + (size_t)j * 4096;
        uint32_t ku = ks_u + st * (4096 * 4);
        uint32_t vu = vs_u + st * (4096 * 4);
        #pragma unroll
        for (int i = 0; i < 4; i++) {
            cp16(ku + (uint32_t)(tid + 256 * i) * 16, kp + (size_t)(tid + 256 * i) * 4);
            cp16(vu + (uint32_t)(tid + 256 * i) * 16, vp + (size_t)(tid + 256 * i) * 4);
        }
        CP_COMMIT();
    };
    loadKV(0, 0);

    float oc[16][4];
    #pragma unroll
    for (int nt = 0; nt < 16; nt++)
        #pragma unroll
        for (int q = 0; q < 4; q++) oc[nt][q] = 0.f;
    float mr0 = -3.4e38f, mr1 = -3.4e38f, lr0 = 0.f, lr1 = 0.f;

    for (int j = 0; j < NKV; j++) {
        if (j + 1 < NKV) { loadKV(j + 1, (j + 1) & 1); CP_WAIT(1); }
        else             { CP_WAIT(0); }
        __syncthreads();

        const float* Kst = Ks + (j & 1) * 4096;
        const float* Vst = Vs + (j & 1) * 4096;

        float sc[4][4];
        #pragma unroll
        for (int nt = 0; nt < 4; nt++)
            #pragma unroll
            for (int q = 0; q < 4; q++) sc[nt][q] = 0.f;

        #pragma unroll
        for (int kc = 0; kc < 16; kc++) {
            float4 a = *(const float4*)(Qs + ((wid * 16 + kc) << 7) + lane * 4);
            #pragma unroll
            for (int nt = 0; nt < 4; nt++) {
                float2 b = *(const float2*)(Kst + ((nt * 16 + kc) << 6) + lane * 2);
                mma_tf32(sc[nt][0], sc[nt][1], sc[nt][2], sc[nt][3],
                         __float_as_uint(a.x), __float_as_uint(a.y),
                         __float_as_uint(a.z), __float_as_uint(a.w),
                         __float_as_uint(b.x), __float_as_uint(b.y));
            }
        }

        float mx0 = -3.4e38f, mx1 = -3.4e38f;
        #pragma unroll
        for (int nt = 0; nt < 4; nt++) {
            mx0 = fmaxf(mx0, fmaxf(sc[nt][0], sc[nt][1]));
            mx1 = fmaxf(mx1, fmaxf(sc[nt][2], sc[nt][3]));
        }
        mx0 = fmaxf(mx0, __shfl_xor_sync(0xffffffff, mx0, 1));
        mx0 = fmaxf(mx0, __shfl_xor_sync(0xffffffff, mx0, 2));
        mx1 = fmaxf(mx1, __shfl_xor_sync(0xffffffff, mx1, 1));
        mx1 = fmaxf(mx1, __shfl_xor_sync(0xffffffff, mx1, 2));

        float mn0 = fmaxf(mr0, mx0), mn1 = fmaxf(mr1, mx1);
        float al0 = exp2f((mr0 - mn0) * CEXP);
        float al1 = exp2f((mr1 - mn1) * CEXP);
        mr0 = mn0; mr1 = mn1;

        float s0 = 0.f, s1 = 0.f;
        #pragma unroll
        for (int nt = 0; nt < 4; nt++) {
            sc[nt][0] = exp2f((sc[nt][0] - mn0) * CEXP);
            sc[nt][1] = exp2f((sc[nt][1] - mn0) * CEXP);
            sc[nt][2] = exp2f((sc[nt][2] - mn1) * CEXP);
            sc[nt][3] = exp2f((sc[nt][3] - mn1) * CEXP);
            s0 += sc[nt][0] + sc[nt][1];
            s1 += sc[nt][2] + sc[nt][3];
        }
        s0 += __shfl_xor_sync(0xffffffff, s0, 1);
        s0 += __shfl_xor_sync(0xffffffff, s0, 2);
        s1 += __shfl_xor_sync(0xffffffff, s1, 1);
        s1 += __shfl_xor_sync(0xffffffff, s1, 2);
        lr0 = lr0 * al0 + s0;
        lr1 = lr1 * al1 + s1;

        #pragma unroll
        for (int nt = 0; nt < 16; nt++) {
            oc[nt][0] *= al0; oc[nt][1] *= al0;
            oc[nt][2] *= al1; oc[nt][3] *= al1;
        }

        #pragma unroll
        for (int nt = 0; nt < 4; nt++) {
            float2 p0; p0.x = rtf32(sc[nt][0]); p0.y = rtf32(sc[nt][1]);
            float2 p1; p1.x = rtf32(sc[nt][2]); p1.y = rtf32(sc[nt][3]);
            *(float2*)(Ps + (m0 + g) * PPITCH + nt * 8 + 2 * t)     = p0;
            *(float2*)(Ps + (m0 + g + 8) * PPITCH + nt * 8 + 2 * t) = p1;
        }
        __syncwarp();

        #pragma unroll
        for (int kc = 0; kc < 4; kc++) {
            uint32_t a0 = __float_as_uint(Ps[(m0 + g) * PPITCH + kc * 8 + t]);
            uint32_t a1 = __float_as_uint(Ps[(m0 + g + 8) * PPITCH + kc * 8 + t]);
            uint32_t a2 = __float_as_uint(Ps[(m0 + g) * PPITCH + kc * 8 + t + 4]);
            uint32_t a3 = __float_as_uint(Ps[(m0 + g + 8) * PPITCH + kc * 8 + t + 4]);
            #pragma unroll
            for (int nt = 0; nt < 16; nt++) {
                float2 b = *(const float2*)(Vst + ((kc * 16 + nt) << 6) + lane * 2);
                mma_tf32(oc[nt][0], oc[nt][1], oc[nt][2], oc[nt][3],
                         a0, a1, a2, a3,
                         __float_as_uint(b.x), __float_as_uint(b.y));
            }
        }
        __syncthreads();
    }

    // ---- normalize + write fp16 (feeds fp16 out-proj) ----
    float li0 = 1.f / lr0, li1 = 1.f / lr1;
    __half* orow0 = g_attnh + (size_t)(q0 + m0 + g) * D + h * DH;
    __half* orow1 = orow0 + (size_t)8 * D;
    #pragma unroll
    for (int nt = 0; nt < 16; nt++) {
        *(__half2*)(orow0 + nt * 8 + 2 * t) =
            __float22half2_rn(make_float2(oc[nt][0] * li0, oc[nt][1] * li0));
        *(__half2*)(orow1 + nt * 8 + 2 * t) =
            __float22half2_rn(make_float2(oc[nt][2] * li1, oc[nt][3] * li1));
    }
}

// ---------------- launch ----------------
extern "C" void kernel_launch(void* const* d_in, const int* in_sizes, int n_in,
                              void* d_out, int out_size)
{
    const float* hidden     = (const float*)d_in[0];
    const float* encoder    = (const float*)d_in[1];
    const float* cosb       = (const float*)d_in[2];
    const float* sinb       = (const float*)d_in[3];
    const float* w_qkv      = (const float*)d_in[4];
    const float* w_add_qkv  = (const float*)d_in[5];
    const float* b_add_qkv  = (const float*)d_in[6];
    const float* norm_q_w   = (const float*)d_in[7];
    const float* norm_k_w   = (const float*)d_in[8];
    const float* norm_aq_w  = (const float*)d_in[9];
    const float* norm_ak_w  = (const float*)d_in[10];
    const float* w_out      = (const float*)d_in[11];
    const float* b_out      = (const float*)d_in[12];
    const float* w_add_out  = (const float*)d_in[13];
    const float* b_add_out  = (const float*)d_in[14];
    float* out = (float*)d_out;

    float *qkv;
    __half *xh, *wqh, *waqh, *woh, *waoh, *attnh;
    cudaGetSymbolAddress((void**)&qkv,   g_qkv);
    cudaGetSymbolAddress((void**)&xh,    g_xh);
    cudaGetSymbolAddress((void**)&wqh,   g_wqkvh);
    cudaGetSymbolAddress((void**)&waqh,  g_waddqkvh);
    cudaGetSymbolAddress((void**)&woh,   g_wouth);
    cudaGetSymbolAddress((void**)&waoh,  g_waddouth);
    cudaGetSymbolAddress((void**)&attnh, g_attnh);

    cudaFuncSetAttribute(flash_tc, cudaFuncAttributeMaxDynamicSharedMemorySize, FLASH_SMEM);
    cudaFuncSetAttribute(gemm_f16, cudaFuncAttributeMaxDynamicSharedMemorySize, GEMM_SMEM_BYTES);

    // 0) fp16 conversion: activations and weights
    auto launch_h = [](const float* s, __half* d, size_t n) {
        int n4 = (int)(n / 4);
        f2h<<<(n4 + 255) / 256, 256>>>((const float4*)s, (__half2*)d, n4);
    };
    launch_h(encoder, xh,                   (size_t)TXT * D);
    launch_h(hidden,  xh + (size_t)TXT * D, (size_t)IMG * D);
    launch_h(w_qkv,     wqh,  (size_t)ND3 * D);
    launch_h(w_add_qkv, waqh, (size_t)ND3 * D);
    launch_h(w_out,     woh,  (size_t)D * D);
    launch_h(w_add_out, waoh, (size_t)D * D);

    // 1) QKV projection (fp16 mma.sync)
    gemm_f16<<<dim3(ND3 / BN, S_TOT / BM), 256, GEMM_SMEM_BYTES>>>(
        xh, waqh, wqh, b_add_qkv, nullptr,
        qkv, qkv + (size_t)TXT * ND3, TXT, ND3);

    // 2) RMSNorm + RoPE + split into fragment-packed q/k/v
    norm_rope<<<dim3(S_TOT * NH, 3), 128>>>(cosb, sinb, norm_q_w, norm_k_w,
                                            norm_aq_w, norm_ak_w);

    // 3) Flash attention (tf32 mma.sync, fp16 output)
    flash_tc<<<dim3(S_TOT / QT, NH), 256, FLASH_SMEM>>>();

    // 4) Output projections (fp16 mma.sync)
    gemm_f16<<<dim3(D / BN, S_TOT / BM), 256, GEMM_SMEM_BYTES>>>(
        attnh, waoh, woh, b_add_out, b_out,
        out + (size_t)IMG * D, out, TXT, D);
}

// round 6
// speedup vs baseline: 7.2198x; 1.2825x over previous
#include <cuda_runtime.h>
#include <cuda_fp16.h>
#include <math.h>
#include <stdint.h>

#define S_TOT 2560
#define TXT 256
#define IMG 2304
#define D 3072
#define NH 24
#define DH 128
#define ND3 9216
#define KDIM 3072
#define ATT_SCALE 0.08838834764831845f   // 1/sqrt(128)
#define CEXP (1.4426950408889634f * ATT_SCALE)
#define EPS 1e-5f

// ---------------- scratch (device globals: no allocation allowed) ----------------
__device__ __half g_qkvh[(size_t)S_TOT * ND3];
__device__ __half g_qfh[(size_t)NH * S_TOT * DH];   // fragment-packed fp16
__device__ __half g_kfh[(size_t)NH * S_TOT * DH];
__device__ __half g_vfh[(size_t)NH * S_TOT * DH];
__device__ __half g_attnh[(size_t)S_TOT * D];
// fp16 copies of inputs
__device__ __half g_xh[(size_t)S_TOT * D];
__device__ __half g_wqkvh[(size_t)ND3 * D];
__device__ __half g_waddqkvh[(size_t)ND3 * D];
__device__ __half g_wouth[(size_t)D * D];
__device__ __half g_waddouth[(size_t)D * D];

// ================= helpers =================
static __device__ __forceinline__ uint32_t smem_u32(const void* p) {
    uint32_t r;
    asm("{ .reg .u64 t; cvta.to.shared.u64 t, %1; cvt.u32.u64 %0, t; }" : "=r"(r) : "l"(p));
    return r;
}
static __device__ __forceinline__ void cp16(uint32_t dst, const void* src) {
    asm volatile("cp.async.cg.shared.global [%0], [%1], 16;" :: "r"(dst), "l"(src));
}
#define CP_COMMIT() asm volatile("cp.async.commit_group;" ::: "memory")
#define CP_WAIT(n)  asm volatile("cp.async.wait_group %0;" :: "n"(n) : "memory")

static __device__ __forceinline__ void mma_f16(
    float& c0, float& c1, float& c2, float& c3,
    uint32_t a0, uint32_t a1, uint32_t a2, uint32_t a3,
    uint32_t b0, uint32_t b1)
{
    asm volatile(
        "mma.sync.aligned.m16n8k16.row.col.f32.f16.f16.f32 "
        "{%0,%1,%2,%3}, {%4,%5,%6,%7}, {%8,%9}, {%0,%1,%2,%3};"
        : "+f"(c0), "+f"(c1), "+f"(c2), "+f"(c3)
        : "r"(a0), "r"(a1), "r"(a2), "r"(a3), "r"(b0), "r"(b1));
}
static __device__ __forceinline__ uint32_t pack_h2(float x, float y) {
    __half2 h = __float22half2_rn(make_float2(x, y));
    return *reinterpret_cast<uint32_t*>(&h);
}

// ---------------- fp32 -> fp16 conversion pass ----------------
__global__ void f2h(const float4* __restrict__ src, __half2* __restrict__ dst, int n4)
{
    int i = blockIdx.x * blockDim.x + threadIdx.x;
    if (i < n4) {
        float4 v = src[i];
        dst[i * 2]     = __float22half2_rn(make_float2(v.x, v.y));
        dst[i * 2 + 1] = __float22half2_rn(make_float2(v.z, v.w));
    }
}

// ================= fp16 mma.sync GEMM =================
// C = A @ W^T (+bias). Block 128x256, BK=32 halves, 4 stages,
// 8 warps (2M x 4N) of 64x64 warp tiles, m16n8k16. OT = float or __half.
#define BM 128
#define BN 256
#define BK 32
#define GSTG 4
#define NCHUNK (KDIM / BK)       // 96
#define HPITCH 40
#define A_SH (BM * HPITCH)
#define B_SH (BN * HPITCH)
#define GEMM_SMEM_BYTES (GSTG * (A_SH + B_SH) * 2)   // 122880

template <typename OT>
__global__ __launch_bounds__(256, 1)
void gemm_f16(const __half* __restrict__ A,
              const __half* __restrict__ W0, const __half* __restrict__ W1,
              const float* __restrict__ b0, const float* __restrict__ b1,
              OT* __restrict__ C0, OT* __restrict__ C1,
              int M0, int N)
{
    extern __shared__ __half hsm[];
    __half* Asm = hsm;
    __half* Bsm = hsm + GSTG * A_SH;

    const int tid  = threadIdx.x;
    const int lane = tid & 31;
    const int wid  = tid >> 5;
    const int wm   = wid >> 2;
    const int wn   = wid & 3;
    const int g    = lane >> 2;
    const int t    = lane & 3;

    const int bm = blockIdx.y, bn = blockIdx.x;
    const int rowbase = bm * BM;
    const int n0 = bn * BN;

    const __half* Ab = A + (size_t)rowbase * KDIM;
    const __half* W; const float* bias; OT* C;
    if (rowbase < M0) { W = W0; bias = b0; C = C0 + (size_t)rowbase * N; }
    else              { W = W1; bias = b1; C = C1 + (size_t)(rowbase - M0) * N; }

    const uint32_t asu = smem_u32(Asm);
    const uint32_t bsu = smem_u32(Bsm);

    auto load_chunk = [&](int ck, int st) {
        const int k0 = ck * BK;
        const uint32_t au = asu + st * (A_SH * 2);
        const uint32_t bu = bsu + st * (B_SH * 2);
        #pragma unroll
        for (int i = 0; i < 2; i++) {
            int idx = tid + 256 * i;
            int row = idx >> 2, c = idx & 3;
            cp16(au + row * (HPITCH * 2) + c * 16,
                 Ab + (size_t)row * KDIM + k0 + c * 8);
        }
        #pragma unroll
        for (int i = 0; i < 4; i++) {
            int idx = tid + 256 * i;
            int row = idx >> 2, c = idx & 3;
            cp16(bu + row * (HPITCH * 2) + c * 16,
                 W + (size_t)(n0 + row) * KDIM + k0 + c * 8);
        }
        CP_COMMIT();
    };

    float acc[4][8][4];
    #pragma unroll
    for (int i = 0; i < 4; i++)
        #pragma unroll
        for (int j = 0; j < 8; j++)
            #pragma unroll
            for (int q = 0; q < 4; q++) acc[i][j][q] = 0.f;

    load_chunk(0, 0); load_chunk(1, 1); load_chunk(2, 2);

    for (int j = 0; j < NCHUNK; j++) {
        if      (j < NCHUNK - 2) CP_WAIT(2);
        else if (j == NCHUNK - 2) CP_WAIT(1);
        else                      CP_WAIT(0);
        __syncthreads();

        if (j + 3 < NCHUNK) load_chunk(j + 3, (j + 3) & 3);

        const int st = j & 3;
        const __half* as = Asm + st * A_SH + (wm * 64 + g) * HPITCH;
        const __half* bs = Bsm + st * B_SH + (wn * 64 + g) * HPITCH;

        #pragma unroll
        for (int kc = 0; kc < 2; kc++) {
            const int co = kc * 16 + 2 * t;
            uint32_t af[4][4], bf[8][2];
            #pragma unroll
            for (int mt = 0; mt < 4; mt++) {
                af[mt][0] = *(const uint32_t*)(as + (mt * 16 + 0) * HPITCH + co);
                af[mt][1] = *(const uint32_t*)(as + (mt * 16 + 8) * HPITCH + co);
                af[mt][2] = *(const uint32_t*)(as + (mt * 16 + 0) * HPITCH + co + 8);
                af[mt][3] = *(const uint32_t*)(as + (mt * 16 + 8) * HPITCH + co + 8);
            }
            #pragma unroll
            for (int nt = 0; nt < 8; nt++) {
                bf[nt][0] = *(const uint32_t*)(bs + nt * 8 * HPITCH + co);
                bf[nt][1] = *(const uint32_t*)(bs + nt * 8 * HPITCH + co + 8);
            }
            #pragma unroll
            for (int mt = 0; mt < 4; mt++)
                #pragma unroll
                for (int nt = 0; nt < 8; nt++)
                    mma_f16(acc[mt][nt][0], acc[mt][nt][1], acc[mt][nt][2], acc[mt][nt][3],
                            af[mt][0], af[mt][1], af[mt][2], af[mt][3],
                            bf[nt][0], bf[nt][1]);
        }
    }

    // ---- epilogue ----
    #pragma unroll
    for (int nt = 0; nt < 8; nt++) {
        const int col = n0 + wn * 64 + nt * 8 + 2 * t;
        float bx = 0.f, by = 0.f;
        if (bias) { bx = bias[col]; by = bias[col + 1]; }
        #pragma unroll
        for (int mt = 0; mt < 4; mt++) {
            const int r0 = wm * 64 + mt * 16 + g;
            if constexpr (sizeof(OT) == 2) {
                *(__half2*)((__half*)C + (size_t)r0 * N + col) =
                    __float22half2_rn(make_float2(acc[mt][nt][0] + bx, acc[mt][nt][1] + by));
                *(__half2*)((__half*)C + (size_t)(r0 + 8) * N + col) =
                    __float22half2_rn(make_float2(acc[mt][nt][2] + bx, acc[mt][nt][3] + by));
            } else {
                float2 v0, v1;
                v0.x = acc[mt][nt][0] + bx; v0.y = acc[mt][nt][1] + by;
                v1.x = acc[mt][nt][2] + bx; v1.y = acc[mt][nt][3] + by;
                *(float2*)((float*)C + (size_t)r0 * N + col)       = v0;
                *(float2*)((float*)C + (size_t)(r0 + 8) * N + col) = v1;
            }
        }
    }
}

// ---------------- RMSNorm + RoPE + head split into fp16 fragment-packed layouts ----------------
// Q A-frag block [h][s/16][dh/16][256]: lane=(s&7)*4+((dh&7)>>1); reg=((s>>3)&1)+2*((dh>>3)&1)
//   idx = lane*8 + reg*2 + (dh&1)
// K B-frag block [h][s/8][dh/16][128]:  lane=(s&7)*4+((dh&7)>>1); reg=(dh>>3)&1
//   idx = lane*4 + reg*2 + (dh&1)
// V B-frag block [h][s/16][dh/8][128]:  lane=(dh&7)*4+((s&7)>>1); reg=(s>>3)&1
//   idx = lane*4 + reg*2 + (s&1)
__global__ void norm_rope(const float* __restrict__ cosb, const float* __restrict__ sinb,
                          const float* __restrict__ nqw,  const float* __restrict__ nkw,
                          const float* __restrict__ naqw, const float* __restrict__ nakw)
{
    const int s = blockIdx.x / NH, h = blockIdx.x % NH;
    const int which = blockIdx.y;
    const int dh = threadIdx.x;

    __half xh16 = g_qkvh[(size_t)s * ND3 + which * D + h * DH + dh];
    float x = __half2float(xh16);

    if (which == 2) {
        int lane = (dh & 7) * 4 + ((s & 7) >> 1);
        int reg  = (s >> 3) & 1;
        size_t off = (((size_t)h * (S_TOT / 16) + (s >> 4)) * 16 + (dh >> 3)) * 128
                   + (size_t)(lane * 4 + reg * 2 + (s & 1));
        g_vfh[off] = xh16;
        return;
    }

    __shared__ float sh[128];
    __shared__ float red[4];

    float sq = x * x;
    #pragma unroll
    for (int o = 16; o; o >>= 1) sq += __shfl_xor_sync(0xffffffff, sq, o);
    if ((dh & 31) == 0) red[dh >> 5] = sq;
    __syncthreads();
    float msum = red[0] + red[1] + red[2] + red[3];
    float r = rsqrtf(msum * (1.0f / 128.0f) + EPS);

    const float* w;
    if (which == 0) w = (s < TXT) ? naqw : nqw;
    else            w = (s < TXT) ? nakw : nkw;

    float xn = x * r * w[dh];
    sh[dh] = xn;
    __syncthreads();

    float c  = cosb[s * 64 + (dh >> 1)];
    float sn = sinb[s * 64 + (dh >> 1)];
    float other = sh[dh ^ 1];
    float o = (dh & 1) ? fmaf(xn, c,  other * sn)
                       : fmaf(xn, c, -other * sn);
    __half oh = __float2half_rn(o);

    if (which == 0) {
        int lane = (s & 7) * 4 + ((dh & 7) >> 1);
        int reg  = ((s >> 3) & 1) + 2 * ((dh >> 3) & 1);
        size_t off = (((size_t)h * (S_TOT / 16) + (s >> 4)) * 8 + (dh >> 4)) * 256
                   + (size_t)(lane * 8 + reg * 2 + (dh & 1));
        g_qfh[off] = oh;
    } else {
        int lane = (s & 7) * 4 + ((dh & 7) >> 1);
        int reg  = (dh >> 3) & 1;
        size_t off = (((size_t)h * (S_TOT / 8) + (s >> 3)) * 8 + (dh >> 4)) * 128
                   + (size_t)(lane * 4 + reg * 2 + (dh & 1));
        g_kfh[off] = oh;
    }
}

// ---------------- Flash attention, fp16 mma.sync ----------------
// q-tile 128 (8 warps x 16 rows), kv-tile 32, double-buffered K/V, P in registers.
#define QT 128
#define KT 32
#define NKV (S_TOT / KT)     // 80
#define FLASH_SMEM ((16384 + 2 * 4096 + 2 * 4096) * 2)   // 65536 bytes

extern __shared__ __half hfsm[];

__global__ __launch_bounds__(256, 2)
void flash_f16()
{
    __half* Qs = hfsm;                 // 16384 halves
    __half* Ks = hfsm + 16384;         // 2 x 4096
    __half* Vs = hfsm + 16384 + 8192;  // 2 x 4096

    const int h   = blockIdx.y;
    const int q0  = blockIdx.x * QT;
    const int tid = threadIdx.x;
    const int lane = tid & 31, wid = tid >> 5;
    const int g = lane >> 2, t = lane & 3;

    const __half* Qg = g_qfh + ((size_t)h * (S_TOT / 16) + (q0 >> 4)) * 2048;
    const __half* Kg = g_kfh + (size_t)h * (S_TOT / 8) * 1024;
    const __half* Vg = g_vfh + (size_t)h * (S_TOT / 16) * 2048;

    const uint32_t qs_u = smem_u32(Qs);
    const uint32_t ks_u = smem_u32(Ks);
    const uint32_t vs_u = smem_u32(Vs);

    #pragma unroll
    for (int i = 0; i < 8; i++)
        cp16(qs_u + (uint32_t)(tid + 256 * i) * 16, Qg + (size_t)(tid + 256 * i) * 8);
    CP_COMMIT();

    auto loadKV = [&](int j, int st) {
        const __half* kp = Kg + (size_t)j * 4096;
        const __half* vp = Vg + (size_t)j * 4096;
        uint32_t ku = ks_u + st * 8192;
        uint32_t vu = vs_u + st * 8192;
        #pragma unroll
        for (int i = 0; i < 2; i++) {
            cp16(ku + (uint32_t)(tid + 256 * i) * 16, kp + (size_t)(tid + 256 * i) * 8);
            cp16(vu + (uint32_t)(tid + 256 * i) * 16, vp + (size_t)(tid + 256 * i) * 8);
        }
        CP_COMMIT();
    };
    loadKV(0, 0);

    float oc[16][4];
    #pragma unroll
    for (int nt = 0; nt < 16; nt++)
        #pragma unroll
        for (int q = 0; q < 4; q++) oc[nt][q] = 0.f;
    float mr0 = -3.4e38f, mr1 = -3.4e38f, lr0 = 0.f, lr1 = 0.f;

    for (int j = 0; j < NKV; j++) {
        if (j + 1 < NKV) { loadKV(j + 1, (j + 1) & 1); CP_WAIT(1); }
        else             { CP_WAIT(0); }
        __syncthreads();

        const __half* Kst = Ks + (j & 1) * 4096;
        const __half* Vst = Vs + (j & 1) * 4096;

        // ---- QK^T: S[16 x 32] per warp (8 k16 chunks) ----
        float sc[4][4];
        #pragma unroll
        for (int nt = 0; nt < 4; nt++)
            #pragma unroll
            for (int q = 0; q < 4; q++) sc[nt][q] = 0.f;

        #pragma unroll
        for (int kc = 0; kc < 8; kc++) {
            uint4 a = *(const uint4*)(Qs + (wid * 8 + kc) * 256 + lane * 8);
            #pragma unroll
            for (int nt = 0; nt < 4; nt++) {
                uint2 b = *(const uint2*)(Kst + (nt * 8 + kc) * 128 + lane * 4);
                mma_f16(sc[nt][0], sc[nt][1], sc[nt][2], sc[nt][3],
                        a.x, a.y, a.z, a.w, b.x, b.y);
            }
        }

        // ---- online softmax (registers; rows g and g+8) ----
        float mx0 = -3.4e38f, mx1 = -3.4e38f;
        #pragma unroll
        for (int nt = 0; nt < 4; nt++) {
            mx0 = fmaxf(mx0, fmaxf(sc[nt][0], sc[nt][1]));
            mx1 = fmaxf(mx1, fmaxf(sc[nt][2], sc[nt][3]));
        }
        mx0 = fmaxf(mx0, __shfl_xor_sync(0xffffffff, mx0, 1));
        mx0 = fmaxf(mx0, __shfl_xor_sync(0xffffffff, mx0, 2));
        mx1 = fmaxf(mx1, __shfl_xor_sync(0xffffffff, mx1, 1));
        mx1 = fmaxf(mx1, __shfl_xor_sync(0xffffffff, mx1, 2));

        float mn0 = fmaxf(mr0, mx0), mn1 = fmaxf(mr1, mx1);
        float al0 = exp2f((mr0 - mn0) * CEXP);
        float al1 = exp2f((mr1 - mn1) * CEXP);
        mr0 = mn0; mr1 = mn1;

        float s0 = 0.f, s1 = 0.f;
        #pragma unroll
        for (int nt = 0; nt < 4; nt++) {
            sc[nt][0] = exp2f((sc[nt][0] - mn0) * CEXP);
            sc[nt][1] = exp2f((sc[nt][1] - mn0) * CEXP);
            sc[nt][2] = exp2f((sc[nt][2] - mn1) * CEXP);
            sc[nt][3] = exp2f((sc[nt][3] - mn1) * CEXP);
            s0 += sc[nt][0] + sc[nt][1];
            s1 += sc[nt][2] + sc[nt][3];
        }
        s0 += __shfl_xor_sync(0xffffffff, s0, 1);
        s0 += __shfl_xor_sync(0xffffffff, s0, 2);
        s1 += __shfl_xor_sync(0xffffffff, s1, 1);
        s1 += __shfl_xor_sync(0xffffffff, s1, 2);
        lr0 = lr0 * al0 + s0;
        lr1 = lr1 * al1 + s1;

        #pragma unroll
        for (int nt = 0; nt < 16; nt++) {
            oc[nt][0] *= al0; oc[nt][1] *= al0;
            oc[nt][2] *= al1; oc[nt][3] *= al1;
        }

        // ---- P @ V: P refragmented in registers (C-layout == A-layout pairs) ----
        #pragma unroll
        for (int kc = 0; kc < 2; kc++) {
            uint32_t a0 = pack_h2(sc[2 * kc][0],     sc[2 * kc][1]);
            uint32_t a1 = pack_h2(sc[2 * kc][2],     sc[2 * kc][3]);
            uint32_t a2 = pack_h2(sc[2 * kc + 1][0], sc[2 * kc + 1][1]);
            uint32_t a3 = pack_h2(sc[2 * kc + 1][2], sc[2 * kc + 1][3]);
            #pragma unroll
            for (int nt = 0; nt < 16; nt++) {
                uint2 b = *(const uint2*)(Vst + (kc * 16 + nt) * 128 + lane * 4);
                mma_f16(oc[nt][0], oc[nt][1], oc[nt][2], oc[nt][3],
                        a0, a1, a2, a3, b.x, b.y);
            }
        }
        __syncthreads();
    }

    // ---- normalize + write fp16 (feeds fp16 out-proj) ----
    float li0 = 1.f / lr0, li1 = 1.f / lr1;
    __half* orow0 = g_attnh + (size_t)(q0 + wid * 16 + g) * D + h * DH;
    __half* orow1 = orow0 + (size_t)8 * D;
    #pragma unroll
    for (int nt = 0; nt < 16; nt++) {
        *(__half2*)(orow0 + nt * 8 + 2 * t) =
            __float22half2_rn(make_float2(oc[nt][0] * li0, oc[nt][1] * li0));
        *(__half2*)(orow1 + nt * 8 + 2 * t) =
            __float22half2_rn(make_float2(oc[nt][2] * li1, oc[nt][3] * li1));
    }
}

// ---------------- launch ----------------
extern "C" void kernel_launch(void* const* d_in, const int* in_sizes, int n_in,
                              void* d_out, int out_size)
{
    const float* hidden     = (const float*)d_in[0];
    const float* encoder    = (const float*)d_in[1];
    const float* cosb       = (const float*)d_in[2];
    const float* sinb       = (const float*)d_in[3];
    const float* w_qkv      = (const float*)d_in[4];
    const float* w_add_qkv  = (const float*)d_in[5];
    const float* b_add_qkv  = (const float*)d_in[6];
    const float* norm_q_w   = (const float*)d_in[7];
    const float* norm_k_w   = (const float*)d_in[8];
    const float* norm_aq_w  = (const float*)d_in[9];
    const float* norm_ak_w  = (const float*)d_in[10];
    const float* w_out      = (const float*)d_in[11];
    const float* b_out      = (const float*)d_in[12];
    const float* w_add_out  = (const float*)d_in[13];
    const float* b_add_out  = (const float*)d_in[14];
    float* out = (float*)d_out;

    __half *qkvh, *xh, *wqh, *waqh, *woh, *waoh, *attnh;
    cudaGetSymbolAddress((void**)&qkvh,  g_qkvh);
    cudaGetSymbolAddress((void**)&xh,    g_xh);
    cudaGetSymbolAddress((void**)&wqh,   g_wqkvh);
    cudaGetSymbolAddress((void**)&waqh,  g_waddqkvh);
    cudaGetSymbolAddress((void**)&woh,   g_wouth);
    cudaGetSymbolAddress((void**)&waoh,  g_waddouth);
    cudaGetSymbolAddress((void**)&attnh, g_attnh);

    cudaFuncSetAttribute(flash_f16, cudaFuncAttributeMaxDynamicSharedMemorySize, FLASH_SMEM);
    cudaFuncSetAttribute(gemm_f16<__half>, cudaFuncAttributeMaxDynamicSharedMemorySize, GEMM_SMEM_BYTES);
    cudaFuncSetAttribute(gemm_f16<float>,  cudaFuncAttributeMaxDynamicSharedMemorySize, GEMM_SMEM_BYTES);

    // 0) fp16 conversion: activations and weights
    auto launch_h = [](const float* s, __half* d, size_t n) {
        int n4 = (int)(n / 4);
        f2h<<<(n4 + 255) / 256, 256>>>((const float4*)s, (__half2*)d, n4);
    };
    launch_h(encoder, xh,                   (size_t)TXT * D);
    launch_h(hidden,  xh + (size_t)TXT * D, (size_t)IMG * D);
    launch_h(w_qkv,     wqh,  (size_t)ND3 * D);
    launch_h(w_add_qkv, waqh, (size_t)ND3 * D);
    launch_h(w_out,     woh,  (size_t)D * D);
    launch_h(w_add_out, waoh, (size_t)D * D);

    // 1) QKV projection (fp16 mma.sync, fp16 output)
    gemm_f16<__half><<<dim3(ND3 / BN, S_TOT / BM), 256, GEMM_SMEM_BYTES>>>(
        xh, waqh, wqh, b_add_qkv, nullptr,
        qkvh, qkvh + (size_t)TXT * ND3, TXT, ND3);

    // 2) RMSNorm + RoPE + split into fp16 fragment-packed q/k/v
    norm_rope<<<dim3(S_TOT * NH, 3), 128>>>(cosb, sinb, norm_q_w, norm_k_w,
                                            norm_aq_w, norm_ak_w);

    // 3) Flash attention (fp16 mma.sync)
    flash_f16<<<dim3(S_TOT / QT, NH), 256, FLASH_SMEM>>>();

    // 4) Output projections (fp16 mma.sync, fp32 output)
    gemm_f16<float><<<dim3(D / BN, S_TOT / BM), 256, GEMM_SMEM_BYTES>>>(
        attnh, waoh, woh, b_add_out, b_out,
        out + (size_t)IMG * D, out, TXT, D);
}

// round 7
// speedup vs baseline: 7.2217x; 1.0003x over previous
#include <cuda_runtime.h>
#include <cuda_fp16.h>
#include <math.h>
#include <stdint.h>

#define S_TOT 2560
#define TXT 256
#define IMG 2304
#define D 3072
#define NH 24
#define DH 128
#define ND3 9216
#define KDIM 3072
#define ATT_SCALE 0.08838834764831845f   // 1/sqrt(128)
#define CEXP (1.4426950408889634f * ATT_SCALE)
#define EPS 1e-5f

// ---------------- scratch (device globals: no allocation allowed) ----------------
__device__ __half g_qkvh[(size_t)S_TOT * ND3];
__device__ __half g_qfh[(size_t)NH * S_TOT * DH];   // fragment-packed fp16
__device__ __half g_kfh[(size_t)NH * S_TOT * DH];
__device__ __half g_vfh[(size_t)NH * S_TOT * DH];
__device__ __half g_attnh[(size_t)S_TOT * D];
// fp16 copies of inputs
__device__ __half g_xh[(size_t)S_TOT * D];
__device__ __half g_wqkvh[(size_t)ND3 * D];
__device__ __half g_waddqkvh[(size_t)ND3 * D];
__device__ __half g_wouth[(size_t)D * D];
__device__ __half g_waddouth[(size_t)D * D];

// ================= helpers =================
static __device__ __forceinline__ uint32_t smem_u32(const void* p) {
    uint32_t r;
    asm("{ .reg .u64 t; cvta.to.shared.u64 t, %1; cvt.u32.u64 %0, t; }" : "=r"(r) : "l"(p));
    return r;
}
static __device__ __forceinline__ void cp16(uint32_t dst, const void* src) {
    asm volatile("cp.async.cg.shared.global [%0], [%1], 16;" :: "r"(dst), "l"(src));
}
#define CP_COMMIT() asm volatile("cp.async.commit_group;" ::: "memory")
#define CP_WAIT(n)  asm volatile("cp.async.wait_group %0;" :: "n"(n) : "memory")

static __device__ __forceinline__ void mma_f16(
    float& c0, float& c1, float& c2, float& c3,
    uint32_t a0, uint32_t a1, uint32_t a2, uint32_t a3,
    uint32_t b0, uint32_t b1)
{
    asm volatile(
        "mma.sync.aligned.m16n8k16.row.col.f32.f16.f16.f32 "
        "{%0,%1,%2,%3}, {%4,%5,%6,%7}, {%8,%9}, {%0,%1,%2,%3};"
        : "+f"(c0), "+f"(c1), "+f"(c2), "+f"(c3)
        : "r"(a0), "r"(a1), "r"(a2), "r"(a3), "r"(b0), "r"(b1));
}
static __device__ __forceinline__ uint32_t pack_h2(float x, float y) {
    __half2 h = __float22half2_rn(make_float2(x, y));
    return *reinterpret_cast<uint32_t*>(&h);
}

// ---------------- fp32 -> fp16 conversion passes ----------------
__global__ void f2h(const float4* __restrict__ src, __half2* __restrict__ dst, int n4)
{
    int i = blockIdx.x * blockDim.x + threadIdx.x;
    if (i < n4) {
        float4 v = src[i];
        dst[i * 2]     = __float22half2_rn(make_float2(v.x, v.y));
        dst[i * 2 + 1] = __float22half2_rn(make_float2(v.z, v.w));
    }
}
// dual-source: encoder rows then hidden rows into one fp16 buffer
__global__ void f2h_x2(const float4* __restrict__ s0, int n0_4,
                       const float4* __restrict__ s1, int n1_4,
                       __half2* __restrict__ dst)
{
    int i = blockIdx.x * blockDim.x + threadIdx.x;
    if (i >= n0_4 + n1_4) return;
    float4 v = (i < n0_4) ? s0[i] : s1[i - n0_4];
    dst[i * 2]     = __float22half2_rn(make_float2(v.x, v.y));
    dst[i * 2 + 1] = __float22half2_rn(make_float2(v.z, v.w));
}

// ================= fp16 mma.sync GEMM =================
// C = A @ W^T (+bias). Block 128x256, BK=32 halves, 4 stages,
// 8 warps (2M x 4N) of 64x64 warp tiles, m16n8k16. OT = float or __half.
// Grid: x = m-blocks (fastest -> wave spans few n-blocks: W stays in L2),
//       y = n-blocks.
#define BM 128
#define BN 256
#define BK 32
#define GSTG 4
#define NCHUNK (KDIM / BK)       // 96
#define HPITCH 40
#define A_SH (BM * HPITCH)
#define B_SH (BN * HPITCH)
#define GEMM_SMEM_BYTES (GSTG * (A_SH + B_SH) * 2)   // 122880

template <typename OT>
__global__ __launch_bounds__(256, 1)
void gemm_f16(const __half* __restrict__ A,
              const __half* __restrict__ W0, const __half* __restrict__ W1,
              const float* __restrict__ b0, const float* __restrict__ b1,
              OT* __restrict__ C0, OT* __restrict__ C1,
              int M0, int N)
{
    extern __shared__ __half hsm[];
    __half* Asm = hsm;
    __half* Bsm = hsm + GSTG * A_SH;

    const int tid  = threadIdx.x;
    const int lane = tid & 31;
    const int wid  = tid >> 5;
    const int wm   = wid >> 2;
    const int wn   = wid & 3;
    const int g    = lane >> 2;
    const int t    = lane & 3;

    const int bm = blockIdx.x, bn = blockIdx.y;   // m fastest
    const int rowbase = bm * BM;
    const int n0 = bn * BN;

    const __half* Ab = A + (size_t)rowbase * KDIM;
    const __half* W; const float* bias; OT* C;
    if (rowbase < M0) { W = W0; bias = b0; C = C0 + (size_t)rowbase * N; }
    else              { W = W1; bias = b1; C = C1 + (size_t)(rowbase - M0) * N; }

    const uint32_t asu = smem_u32(Asm);
    const uint32_t bsu = smem_u32(Bsm);

    auto load_chunk = [&](int ck, int st) {
        const int k0 = ck * BK;
        const uint32_t au = asu + st * (A_SH * 2);
        const uint32_t bu = bsu + st * (B_SH * 2);
        #pragma unroll
        for (int i = 0; i < 2; i++) {
            int idx = tid + 256 * i;
            int row = idx >> 2, c = idx & 3;
            cp16(au + row * (HPITCH * 2) + c * 16,
                 Ab + (size_t)row * KDIM + k0 + c * 8);
        }
        #pragma unroll
        for (int i = 0; i < 4; i++) {
            int idx = tid + 256 * i;
            int row = idx >> 2, c = idx & 3;
            cp16(bu + row * (HPITCH * 2) + c * 16,
                 W + (size_t)(n0 + row) * KDIM + k0 + c * 8);
        }
        CP_COMMIT();
    };

    float acc[4][8][4];
    #pragma unroll
    for (int i = 0; i < 4; i++)
        #pragma unroll
        for (int j = 0; j < 8; j++)
            #pragma unroll
            for (int q = 0; q < 4; q++) acc[i][j][q] = 0.f;

    load_chunk(0, 0); load_chunk(1, 1); load_chunk(2, 2);

    for (int j = 0; j < NCHUNK; j++) {
        if      (j < NCHUNK - 2) CP_WAIT(2);
        else if (j == NCHUNK - 2) CP_WAIT(1);
        else                      CP_WAIT(0);
        __syncthreads();

        if (j + 3 < NCHUNK) load_chunk(j + 3, (j + 3) & 3);

        const int st = j & 3;
        const __half* as = Asm + st * A_SH + (wm * 64 + g) * HPITCH;
        const __half* bs = Bsm + st * B_SH + (wn * 64 + g) * HPITCH;

        #pragma unroll
        for (int kc = 0; kc < 2; kc++) {
            const int co = kc * 16 + 2 * t;
            uint32_t af[4][4], bf[8][2];
            #pragma unroll
            for (int mt = 0; mt < 4; mt++) {
                af[mt][0] = *(const uint32_t*)(as + (mt * 16 + 0) * HPITCH + co);
                af[mt][1] = *(const uint32_t*)(as + (mt * 16 + 8) * HPITCH + co);
                af[mt][2] = *(const uint32_t*)(as + (mt * 16 + 0) * HPITCH + co + 8);
                af[mt][3] = *(const uint32_t*)(as + (mt * 16 + 8) * HPITCH + co + 8);
            }
            #pragma unroll
            for (int nt = 0; nt < 8; nt++) {
                bf[nt][0] = *(const uint32_t*)(bs + nt * 8 * HPITCH + co);
                bf[nt][1] = *(const uint32_t*)(bs + nt * 8 * HPITCH + co + 8);
            }
            #pragma unroll
            for (int mt = 0; mt < 4; mt++)
                #pragma unroll
                for (int nt = 0; nt < 8; nt++)
                    mma_f16(acc[mt][nt][0], acc[mt][nt][1], acc[mt][nt][2], acc[mt][nt][3],
                            af[mt][0], af[mt][1], af[mt][2], af[mt][3],
                            bf[nt][0], bf[nt][1]);
        }
    }

    // ---- epilogue ----
    #pragma unroll
    for (int nt = 0; nt < 8; nt++) {
        const int col = n0 + wn * 64 + nt * 8 + 2 * t;
        float bx = 0.f, by = 0.f;
        if (bias) { bx = bias[col]; by = bias[col + 1]; }
        #pragma unroll
        for (int mt = 0; mt < 4; mt++) {
            const int r0 = wm * 64 + mt * 16 + g;
            if constexpr (sizeof(OT) == 2) {
                *(__half2*)((__half*)C + (size_t)r0 * N + col) =
                    __float22half2_rn(make_float2(acc[mt][nt][0] + bx, acc[mt][nt][1] + by));
                *(__half2*)((__half*)C + (size_t)(r0 + 8) * N + col) =
                    __float22half2_rn(make_float2(acc[mt][nt][2] + bx, acc[mt][nt][3] + by));
            } else {
                float2 v0, v1;
                v0.x = acc[mt][nt][0] + bx; v0.y = acc[mt][nt][1] + by;
                v1.x = acc[mt][nt][2] + bx; v1.y = acc[mt][nt][3] + by;
                *(float2*)((float*)C + (size_t)r0 * N + col)       = v0;
                *(float2*)((float*)C + (size_t)(r0 + 8) * N + col) = v1;
            }
        }
    }
}

// ---------------- RMSNorm + RoPE + head split into fp16 fragment-packed layouts ----------------
__global__ void norm_rope(const float* __restrict__ cosb, const float* __restrict__ sinb,
                          const float* __restrict__ nqw,  const float* __restrict__ nkw,
                          const float* __restrict__ naqw, const float* __restrict__ nakw)
{
    const int s = blockIdx.x / NH, h = blockIdx.x % NH;
    const int which = blockIdx.y;
    const int dh = threadIdx.x;

    __half xh16 = g_qkvh[(size_t)s * ND3 + which * D + h * DH + dh];
    float x = __half2float(xh16);

    if (which == 2) {
        int lane = (dh & 7) * 4 + ((s & 7) >> 1);
        int reg  = (s >> 3) & 1;
        size_t off = (((size_t)h * (S_TOT / 16) + (s >> 4)) * 16 + (dh >> 3)) * 128
                   + (size_t)(lane * 4 + reg * 2 + (s & 1));
        g_vfh[off] = xh16;
        return;
    }

    __shared__ float sh[128];
    __shared__ float red[4];

    float sq = x * x;
    #pragma unroll
    for (int o = 16; o; o >>= 1) sq += __shfl_xor_sync(0xffffffff, sq, o);
    if ((dh & 31) == 0) red[dh >> 5] = sq;
    __syncthreads();
    float msum = red[0] + red[1] + red[2] + red[3];
    float r = rsqrtf(msum * (1.0f / 128.0f) + EPS);

    const float* w;
    if (which == 0) w = (s < TXT) ? naqw : nqw;
    else            w = (s < TXT) ? nakw : nkw;

    float xn = x * r * w[dh];
    sh[dh] = xn;
    __syncthreads();

    float c  = cosb[s * 64 + (dh >> 1)];
    float sn = sinb[s * 64 + (dh >> 1)];
    float other = sh[dh ^ 1];
    float o = (dh & 1) ? fmaf(xn, c,  other * sn)
                       : fmaf(xn, c, -other * sn);
    __half oh = __float2half_rn(o);

    if (which == 0) {
        int lane = (s & 7) * 4 + ((dh & 7) >> 1);
        int reg  = ((s >> 3) & 1) + 2 * ((dh >> 3) & 1);
        size_t off = (((size_t)h * (S_TOT / 16) + (s >> 4)) * 8 + (dh >> 4)) * 256
                   + (size_t)(lane * 8 + reg * 2 + (dh & 1));
        g_qfh[off] = oh;
    } else {
        int lane = (s & 7) * 4 + ((dh & 7) >> 1);
        int reg  = (dh >> 3) & 1;
        size_t off = (((size_t)h * (S_TOT / 8) + (s >> 3)) * 8 + (dh >> 4)) * 128
                   + (size_t)(lane * 4 + reg * 2 + (dh & 1));
        g_kfh[off] = oh;
    }
}

// ---------------- Flash attention, fp16 mma.sync ----------------
#define QT 128
#define KT 32
#define NKV (S_TOT / KT)     // 80
#define FLASH_SMEM ((16384 + 2 * 4096 + 2 * 4096) * 2)   // 65536 bytes

extern __shared__ __half hfsm[];

__global__ __launch_bounds__(256, 2)
void flash_f16()
{
    __half* Qs = hfsm;
    __half* Ks = hfsm + 16384;
    __half* Vs = hfsm + 16384 + 8192;

    const int h   = blockIdx.y;
    const int q0  = blockIdx.x * QT;
    const int tid = threadIdx.x;
    const int lane = tid & 31, wid = tid >> 5;
    const int g = lane >> 2, t = lane & 3;

    const __half* Qg = g_qfh + ((size_t)h * (S_TOT / 16) + (q0 >> 4)) * 2048;
    const __half* Kg = g_kfh + (size_t)h * (S_TOT / 8) * 1024;
    const __half* Vg = g_vfh + (size_t)h * (S_TOT / 16) * 2048;

    const uint32_t qs_u = smem_u32(Qs);
    const uint32_t ks_u = smem_u32(Ks);
    const uint32_t vs_u = smem_u32(Vs);

    #pragma unroll
    for (int i = 0; i < 8; i++)
        cp16(qs_u + (uint32_t)(tid + 256 * i) * 16, Qg + (size_t)(tid + 256 * i) * 8);
    CP_COMMIT();

    auto loadKV = [&](int j, int st) {
        const __half* kp = Kg + (size_t)j * 4096;
        const __half* vp = Vg + (size_t)j * 4096;
        uint32_t ku = ks_u + st * 8192;
        uint32_t vu = vs_u + st * 8192;
        #pragma unroll
        for (int i = 0; i < 2; i++) {
            cp16(ku + (uint32_t)(tid + 256 * i) * 16, kp + (size_t)(tid + 256 * i) * 8);
            cp16(vu + (uint32_t)(tid + 256 * i) * 16, vp + (size_t)(tid + 256 * i) * 8);
        }
        CP_COMMIT();
    };
    loadKV(0, 0);

    float oc[16][4];
    #pragma unroll
    for (int nt = 0; nt < 16; nt++)
        #pragma unroll
        for (int q = 0; q < 4; q++) oc[nt][q] = 0.f;
    float mr0 = -3.4e38f, mr1 = -3.4e38f, lr0 = 0.f, lr1 = 0.f;

    for (int j = 0; j < NKV; j++) {
        if (j + 1 < NKV) { loadKV(j + 1, (j + 1) & 1); CP_WAIT(1); }
        else             { CP_WAIT(0); }
        __syncthreads();

        const __half* Kst = Ks + (j & 1) * 4096;
        const __half* Vst = Vs + (j & 1) * 4096;

        float sc[4][4];
        #pragma unroll
        for (int nt = 0; nt < 4; nt++)
            #pragma unroll
            for (int q = 0; q < 4; q++) sc[nt][q] = 0.f;

        #pragma unroll
        for (int kc = 0; kc < 8; kc++) {
            uint4 a = *(const uint4*)(Qs + (wid * 8 + kc) * 256 + lane * 8);
            #pragma unroll
            for (int nt = 0; nt < 4; nt++) {
                uint2 b = *(const uint2*)(Kst + (nt * 8 + kc) * 128 + lane * 4);
                mma_f16(sc[nt][0], sc[nt][1], sc[nt][2], sc[nt][3],
                        a.x, a.y, a.z, a.w, b.x, b.y);
            }
        }

        float mx0 = -3.4e38f, mx1 = -3.4e38f;
        #pragma unroll
        for (int nt = 0; nt < 4; nt++) {
            mx0 = fmaxf(mx0, fmaxf(sc[nt][0], sc[nt][1]));
            mx1 = fmaxf(mx1, fmaxf(sc[nt][2], sc[nt][3]));
        }
        mx0 = fmaxf(mx0, __shfl_xor_sync(0xffffffff, mx0, 1));
        mx0 = fmaxf(mx0, __shfl_xor_sync(0xffffffff, mx0, 2));
        mx1 = fmaxf(mx1, __shfl_xor_sync(0xffffffff, mx1, 1));
        mx1 = fmaxf(mx1, __shfl_xor_sync(0xffffffff, mx1, 2));

        float mn0 = fmaxf(mr0, mx0), mn1 = fmaxf(mr1, mx1);
        float al0 = exp2f((mr0 - mn0) * CEXP);
        float al1 = exp2f((mr1 - mn1) * CEXP);
        mr0 = mn0; mr1 = mn1;

        float s0 = 0.f, s1 = 0.f;
        #pragma unroll
        for (int nt = 0; nt < 4; nt++) {
            sc[nt][0] = exp2f((sc[nt][0] - mn0) * CEXP);
            sc[nt][1] = exp2f((sc[nt][1] - mn0) * CEXP);
            sc[nt][2] = exp2f((sc[nt][2] - mn1) * CEXP);
            sc[nt][3] = exp2f((sc[nt][3] - mn1) * CEXP);
            s0 += sc[nt][0] + sc[nt][1];
            s1 += sc[nt][2] + sc[nt][3];
        }
        s0 += __shfl_xor_sync(0xffffffff, s0, 1);
        s0 += __shfl_xor_sync(0xffffffff, s0, 2);
        s1 += __shfl_xor_sync(0xffffffff, s1, 1);
        s1 += __shfl_xor_sync(0xffffffff, s1, 2);
        lr0 = lr0 * al0 + s0;
        lr1 = lr1 * al1 + s1;

        #pragma unroll
        for (int nt = 0; nt < 16; nt++) {
            oc[nt][0] *= al0; oc[nt][1] *= al0;
            oc[nt][2] *= al1; oc[nt][3] *= al1;
        }

        #pragma unroll
        for (int kc = 0; kc < 2; kc++) {
            uint32_t a0 = pack_h2(sc[2 * kc][0],     sc[2 * kc][1]);
            uint32_t a1 = pack_h2(sc[2 * kc][2],     sc[2 * kc][3]);
            uint32_t a2 = pack_h2(sc[2 * kc + 1][0], sc[2 * kc + 1][1]);
            uint32_t a3 = pack_h2(sc[2 * kc + 1][2], sc[2 * kc + 1][3]);
            #pragma unroll
            for (int nt = 0; nt < 16; nt++) {
                uint2 b = *(const uint2*)(Vst + (kc * 16 + nt) * 128 + lane * 4);
                mma_f16(oc[nt][0], oc[nt][1], oc[nt][2], oc[nt][3],
                        a0, a1, a2, a3, b.x, b.y);
            }
        }
        __syncthreads();
    }

    float li0 = 1.f / lr0, li1 = 1.f / lr1;
    __half* orow0 = g_attnh + (size_t)(q0 + wid * 16 + g) * D + h * DH;
    __half* orow1 = orow0 + (size_t)8 * D;
    #pragma unroll
    for (int nt = 0; nt < 16; nt++) {
        *(__half2*)(orow0 + nt * 8 + 2 * t) =
            __float22half2_rn(make_float2(oc[nt][0] * li0, oc[nt][1] * li0));
        *(__half2*)(orow1 + nt * 8 + 2 * t) =
            __float22half2_rn(make_float2(oc[nt][2] * li1, oc[nt][3] * li1));
    }
}

// ---------------- launch ----------------
extern "C" void kernel_launch(void* const* d_in, const int* in_sizes, int n_in,
                              void* d_out, int out_size)
{
    const float* hidden     = (const float*)d_in[0];
    const float* encoder    = (const float*)d_in[1];
    const float* cosb       = (const float*)d_in[2];
    const float* sinb       = (const float*)d_in[3];
    const float* w_qkv      = (const float*)d_in[4];
    const float* w_add_qkv  = (const float*)d_in[5];
    const float* b_add_qkv  = (const float*)d_in[6];
    const float* norm_q_w   = (const float*)d_in[7];
    const float* norm_k_w   = (const float*)d_in[8];
    const float* norm_aq_w  = (const float*)d_in[9];
    const float* norm_ak_w  = (const float*)d_in[10];
    const float* w_out      = (const float*)d_in[11];
    const float* b_out      = (const float*)d_in[12];
    const float* w_add_out  = (const float*)d_in[13];
    const float* b_add_out  = (const float*)d_in[14];
    float* out = (float*)d_out;

    __half *qkvh, *xh, *wqh, *waqh, *woh, *waoh, *attnh;
    cudaGetSymbolAddress((void**)&qkvh,  g_qkvh);
    cudaGetSymbolAddress((void**)&xh,    g_xh);
    cudaGetSymbolAddress((void**)&wqh,   g_wqkvh);
    cudaGetSymbolAddress((void**)&waqh,  g_waddqkvh);
    cudaGetSymbolAddress((void**)&woh,   g_wouth);
    cudaGetSymbolAddress((void**)&waoh,  g_waddouth);
    cudaGetSymbolAddress((void**)&attnh, g_attnh);

    cudaFuncSetAttribute(flash_f16, cudaFuncAttributeMaxDynamicSharedMemorySize, FLASH_SMEM);
    cudaFuncSetAttribute(gemm_f16<__half>, cudaFuncAttributeMaxDynamicSharedMemorySize, GEMM_SMEM_BYTES);
    cudaFuncSetAttribute(gemm_f16<float>,  cudaFuncAttributeMaxDynamicSharedMemorySize, GEMM_SMEM_BYTES);

    // Launch order matters for ncu (-s 5 -c 1): gemm_f16<half> is launch #5.
    // 0) activations (one dual-source kernel)
    {
        int n0_4 = (TXT * D) / 4, n1_4 = (IMG * D) / 4;
        int tot = n0_4 + n1_4;
        f2h_x2<<<(tot + 255) / 256, 256>>>((const float4*)encoder, n0_4,
                                           (const float4*)hidden,  n1_4,
                                           (__half2*)xh);
    }
    auto launch_h = [](const float* s, __half* d, size_t n) {
        int n4 = (int)(n / 4);
        f2h<<<(n4 + 255) / 256, 256>>>((const float4*)s, (__half2*)d, n4);
    };
    launch_h(w_qkv,     wqh,  (size_t)ND3 * D);   // launch 1
    launch_h(w_add_qkv, waqh, (size_t)ND3 * D);   // launch 2
    launch_h(w_out,     woh,  (size_t)D * D);     // launch 3
    launch_h(w_add_out, waoh, (size_t)D * D);     // launch 4

    // 1) QKV projection — launch 5 (profiled)
    gemm_f16<__half><<<dim3(S_TOT / BM, ND3 / BN), 256, GEMM_SMEM_BYTES>>>(
        xh, waqh, wqh, b_add_qkv, nullptr,
        qkvh, qkvh + (size_t)TXT * ND3, TXT, ND3);

    // 2) RMSNorm + RoPE + split into fp16 fragment-packed q/k/v
    norm_rope<<<dim3(S_TOT * NH, 3), 128>>>(cosb, sinb, norm_q_w, norm_k_w,
                                            norm_aq_w, norm_ak_w);

    // 3) Flash attention (fp16 mma.sync)
    flash_f16<<<dim3(S_TOT / QT, NH), 256, FLASH_SMEM>>>();

    // 4) Output projections (fp16 mma.sync, fp32 output)
    gemm_f16<float><<<dim3(S_TOT / BM, D / BN), 256, GEMM_SMEM_BYTES>>>(
        attnh, waoh, woh, b_add_out, b_out,
        out + (size_t)IMG * D, out, TXT, D);
}

// round 8
// speedup vs baseline: 8.1054x; 1.1224x over previous
#include <cuda_runtime.h>
#include <cuda_fp16.h>
#include <math.h>
#include <stdint.h>

#define S_TOT 2560
#define TXT 256
#define IMG 2304
#define D 3072
#define NH 24
#define DH 128
#define ND3 9216
#define KDIM 3072
#define ATT_SCALE 0.08838834764831845f   // 1/sqrt(128)
#define CEXP (1.4426950408889634f * ATT_SCALE)
#define EPS 1e-5f

// ---------------- scratch (device globals: no allocation allowed) ----------------
__device__ __half g_qkvh[(size_t)S_TOT * ND3];
__device__ __half g_qfh[(size_t)NH * S_TOT * DH];   // fragment-packed fp16
__device__ __half g_kfh[(size_t)NH * S_TOT * DH];
__device__ __half g_vfh[(size_t)NH * S_TOT * DH];
__device__ __half g_attnh[(size_t)S_TOT * D];
// fp16 copies of inputs
__device__ __half g_xh[(size_t)S_TOT * D];
__device__ __half g_wqkvh[(size_t)ND3 * D];
__device__ __half g_waddqkvh[(size_t)ND3 * D];
__device__ __half g_wouth[(size_t)D * D];
__device__ __half g_waddouth[(size_t)D * D];

// ================= helpers =================
static __device__ __forceinline__ uint32_t smem_u32(const void* p) {
    uint32_t r;
    asm("{ .reg .u64 t; cvta.to.shared.u64 t, %1; cvt.u32.u64 %0, t; }" : "=r"(r) : "l"(p));
    return r;
}
static __device__ __forceinline__ void cp16(uint32_t dst, const void* src) {
    asm volatile("cp.async.cg.shared.global [%0], [%1], 16;" :: "r"(dst), "l"(src));
}
#define CP_COMMIT() asm volatile("cp.async.commit_group;" ::: "memory")
#define CP_WAIT(n)  asm volatile("cp.async.wait_group %0;" :: "n"(n) : "memory")

static __device__ __forceinline__ void mma_f16(
    float& c0, float& c1, float& c2, float& c3,
    uint32_t a0, uint32_t a1, uint32_t a2, uint32_t a3,
    uint32_t b0, uint32_t b1)
{
    asm volatile(
        "mma.sync.aligned.m16n8k16.row.col.f32.f16.f16.f32 "
        "{%0,%1,%2,%3}, {%4,%5,%6,%7}, {%8,%9}, {%0,%1,%2,%3};"
        : "+f"(c0), "+f"(c1), "+f"(c2), "+f"(c3)
        : "r"(a0), "r"(a1), "r"(a2), "r"(a3), "r"(b0), "r"(b1));
}
static __device__ __forceinline__ void ldsm_x4(
    uint32_t& r0, uint32_t& r1, uint32_t& r2, uint32_t& r3, uint32_t addr)
{
    asm volatile("ldmatrix.sync.aligned.m8n8.x4.shared.b16 {%0,%1,%2,%3}, [%4];"
                 : "=r"(r0), "=r"(r1), "=r"(r2), "=r"(r3) : "r"(addr));
}
static __device__ __forceinline__ uint32_t pack_h2(float x, float y) {
    __half2 h = __float22half2_rn(make_float2(x, y));
    return *reinterpret_cast<uint32_t*>(&h);
}

// ---------------- fp32 -> fp16 conversion passes ----------------
// dual-source into one destination (activations: encoder rows then hidden rows)
__global__ void f2h_x2(const float4* __restrict__ s0, int n0_4,
                       const float4* __restrict__ s1, int n1_4,
                       __half2* __restrict__ dst)
{
    int i = blockIdx.x * blockDim.x + threadIdx.x;
    if (i >= n0_4 + n1_4) return;
    float4 v = (i < n0_4) ? s0[i] : s1[i - n0_4];
    dst[i * 2]     = __float22half2_rn(make_float2(v.x, v.y));
    dst[i * 2 + 1] = __float22half2_rn(make_float2(v.z, v.w));
}
// two independent src->dst pairs in one kernel
__global__ void f2h_w2(const float4* __restrict__ s0, __half2* __restrict__ d0, int n0_4,
                       const float4* __restrict__ s1, __half2* __restrict__ d1, int n1_4)
{
    int i = blockIdx.x * blockDim.x + threadIdx.x;
    if (i >= n0_4 + n1_4) return;
    const float4* s; __half2* d; int k;
    if (i < n0_4) { s = s0; d = d0; k = i; }
    else          { s = s1; d = d1; k = i - n0_4; }
    float4 v = s[k];
    d[k * 2]     = __float22half2_rn(make_float2(v.x, v.y));
    d[k * 2 + 1] = __float22half2_rn(make_float2(v.z, v.w));
}

// ================= fp16 mma.sync GEMM =================
// C = A @ W^T (+bias). Block 128x256, BK=64 halves, 3 stages, ldmatrix frags,
// 8 warps (2M x 4N) of 64x64 warp tiles, m16n8k16. OT = float or __half.
#define BM 128
#define BN 256
#define BK 64
#define GSTG 3
#define NCHUNK (KDIM / BK)       // 48
#define HPITCH 72                // halves per row (144 B)
#define A_SH (BM * HPITCH)       // 9216 halves
#define B_SH (BN * HPITCH)       // 18432 halves
#define GEMM_SMEM_BYTES (GSTG * (A_SH + B_SH) * 2)   // 165888

template <typename OT>
__global__ __launch_bounds__(256, 1)
void gemm_f16(const __half* __restrict__ A,
              const __half* __restrict__ W0, const __half* __restrict__ W1,
              const float* __restrict__ b0, const float* __restrict__ b1,
              OT* __restrict__ C0, OT* __restrict__ C1,
              int M0, int N)
{
    extern __shared__ __half hsm[];
    __half* Asm = hsm;
    __half* Bsm = hsm + GSTG * A_SH;

    const int tid  = threadIdx.x;
    const int lane = tid & 31;
    const int wid  = tid >> 5;
    const int wm   = wid >> 2;
    const int wn   = wid & 3;
    const int g    = lane >> 2;
    const int t    = lane & 3;

    const int bm = blockIdx.x, bn = blockIdx.y;   // m fastest
    const int rowbase = bm * BM;
    const int n0 = bn * BN;

    const __half* Ab = A + (size_t)rowbase * KDIM;
    const __half* W; const float* bias; OT* C;
    if (rowbase < M0) { W = W0; bias = b0; C = C0 + (size_t)rowbase * N; }
    else              { W = W1; bias = b1; C = C1 + (size_t)(rowbase - M0) * N; }

    const uint32_t asu = smem_u32(Asm);
    const uint32_t bsu = smem_u32(Bsm);

    // ldmatrix per-lane base addresses (bytes):
    // A .x4: m0=rows[0..7]@k0, m1=rows[8..15]@k0, m2=rows[0..7]@k0+8, m3=rows[8..15]@k0+8
    const uint32_t aL = asu + (uint32_t)(((wm * 64 + (lane & 15)) * HPITCH
                                          + (lane >> 4) * 8) * 2);
    // B .x4 (pair of n-tiles): m0=n[0..7]@k0, m1=n[0..7]@k0+8, m2=n[8..15]@k0, m3=n[8..15]@k0+8
    const uint32_t bL = bsu + (uint32_t)(((wn * 64 + (lane & 7) + (lane >> 4) * 8) * HPITCH
                                          + ((lane >> 3) & 1) * 8) * 2);

    // ---- async chunk loader: A 1024 x 16B (4/thr), B 2048 x 16B (8/thr) ----
    auto load_chunk = [&](int ck, int st) {
        const int k0 = ck * BK;
        const uint32_t au = asu + st * (A_SH * 2);
        const uint32_t bu = bsu + st * (B_SH * 2);
        #pragma unroll
        for (int i = 0; i < 4; i++) {
            int idx = tid + 256 * i;
            int row = idx >> 3, c = idx & 7;
            cp16(au + row * (HPITCH * 2) + c * 16,
                 Ab + (size_t)row * KDIM + k0 + c * 8);
        }
        #pragma unroll
        for (int i = 0; i < 8; i++) {
            int idx = tid + 256 * i;
            int row = idx >> 3, c = idx & 7;
            cp16(bu + row * (HPITCH * 2) + c * 16,
                 W + (size_t)(n0 + row) * KDIM + k0 + c * 8);
        }
        CP_COMMIT();
    };

    float acc[4][8][4];
    #pragma unroll
    for (int i = 0; i < 4; i++)
        #pragma unroll
        for (int j = 0; j < 8; j++)
            #pragma unroll
            for (int q = 0; q < 4; q++) acc[i][j][q] = 0.f;

    load_chunk(0, 0); load_chunk(1, 1);

    for (int j = 0; j < NCHUNK; j++) {
        if (j < NCHUNK - 2) CP_WAIT(1); else CP_WAIT(0);
        __syncthreads();

        if (j + 2 < NCHUNK) load_chunk(j + 2, (j + 2) % GSTG);

        const int st = j % GSTG;
        const uint32_t aS = aL + st * (A_SH * 2);
        const uint32_t bS = bL + st * (B_SH * 2);

        #pragma unroll
        for (int kc = 0; kc < 4; kc++) {
            uint32_t af[4][4], bf[8][2];
            #pragma unroll
            for (int mt = 0; mt < 4; mt++)
                ldsm_x4(af[mt][0], af[mt][1], af[mt][2], af[mt][3],
                        aS + mt * (16 * HPITCH * 2) + kc * 32);
            #pragma unroll
            for (int p = 0; p < 4; p++)
                ldsm_x4(bf[2 * p][0], bf[2 * p][1], bf[2 * p + 1][0], bf[2 * p + 1][1],
                        bS + p * (16 * HPITCH * 2) + kc * 32);
            #pragma unroll
            for (int mt = 0; mt < 4; mt++)
                #pragma unroll
                for (int nt = 0; nt < 8; nt++)
                    mma_f16(acc[mt][nt][0], acc[mt][nt][1], acc[mt][nt][2], acc[mt][nt][3],
                            af[mt][0], af[mt][1], af[mt][2], af[mt][3],
                            bf[nt][0], bf[nt][1]);
        }
    }

    // ---- epilogue ----
    #pragma unroll
    for (int nt = 0; nt < 8; nt++) {
        const int col = n0 + wn * 64 + nt * 8 + 2 * t;
        float bx = 0.f, by = 0.f;
        if (bias) { bx = bias[col]; by = bias[col + 1]; }
        #pragma unroll
        for (int mt = 0; mt < 4; mt++) {
            const int r0 = wm * 64 + mt * 16 + g;
            if constexpr (sizeof(OT) == 2) {
                *(__half2*)((__half*)C + (size_t)r0 * N + col) =
                    __float22half2_rn(make_float2(acc[mt][nt][0] + bx, acc[mt][nt][1] + by));
                *(__half2*)((__half*)C + (size_t)(r0 + 8) * N + col) =
                    __float22half2_rn(make_float2(acc[mt][nt][2] + bx, acc[mt][nt][3] + by));
            } else {
                float2 v0, v1;
                v0.x = acc[mt][nt][0] + bx; v0.y = acc[mt][nt][1] + by;
                v1.x = acc[mt][nt][2] + bx; v1.y = acc[mt][nt][3] + by;
                *(float2*)((float*)C + (size_t)r0 * N + col)       = v0;
                *(float2*)((float*)C + (size_t)(r0 + 8) * N + col) = v1;
            }
        }
    }
}

// ---------------- RMSNorm + RoPE + head split into fp16 fragment-packed layouts ----------------
__global__ void norm_rope(const float* __restrict__ cosb, const float* __restrict__ sinb,
                          const float* __restrict__ nqw,  const float* __restrict__ nkw,
                          const float* __restrict__ naqw, const float* __restrict__ nakw)
{
    const int s = blockIdx.x / NH, h = blockIdx.x % NH;
    const int which = blockIdx.y;
    const int dh = threadIdx.x;

    __half xh16 = g_qkvh[(size_t)s * ND3 + which * D + h * DH + dh];
    float x = __half2float(xh16);

    if (which == 2) {
        int lane = (dh & 7) * 4 + ((s & 7) >> 1);
        int reg  = (s >> 3) & 1;
        size_t off = (((size_t)h * (S_TOT / 16) + (s >> 4)) * 16 + (dh >> 3)) * 128
                   + (size_t)(lane * 4 + reg * 2 + (s & 1));
        g_vfh[off] = xh16;
        return;
    }

    __shared__ float sh[128];
    __shared__ float red[4];

    float sq = x * x;
    #pragma unroll
    for (int o = 16; o; o >>= 1) sq += __shfl_xor_sync(0xffffffff, sq, o);
    if ((dh & 31) == 0) red[dh >> 5] = sq;
    __syncthreads();
    float msum = red[0] + red[1] + red[2] + red[3];
    float r = rsqrtf(msum * (1.0f / 128.0f) + EPS);

    const float* w;
    if (which == 0) w = (s < TXT) ? naqw : nqw;
    else            w = (s < TXT) ? nakw : nkw;

    float xn = x * r * w[dh];
    sh[dh] = xn;
    __syncthreads();

    float c  = cosb[s * 64 + (dh >> 1)];
    float sn = sinb[s * 64 + (dh >> 1)];
    float other = sh[dh ^ 1];
    float o = (dh & 1) ? fmaf(xn, c,  other * sn)
                       : fmaf(xn, c, -other * sn);
    __half oh = __float2half_rn(o);

    if (which == 0) {
        int lane = (s & 7) * 4 + ((dh & 7) >> 1);
        int reg  = ((s >> 3) & 1) + 2 * ((dh >> 3) & 1);
        size_t off = (((size_t)h * (S_TOT / 16) + (s >> 4)) * 8 + (dh >> 4)) * 256
                   + (size_t)(lane * 8 + reg * 2 + (dh & 1));
        g_qfh[off] = oh;
    } else {
        int lane = (s & 7) * 4 + ((dh & 7) >> 1);
        int reg  = (dh >> 3) & 1;
        size_t off = (((size_t)h * (S_TOT / 8) + (s >> 3)) * 8 + (dh >> 4)) * 128
                   + (size_t)(lane * 4 + reg * 2 + (dh & 1));
        g_kfh[off] = oh;
    }
}

// ---------------- Flash attention, fp16 mma.sync ----------------
#define QT 128
#define KT 32
#define NKV (S_TOT / KT)     // 80
#define FLASH_SMEM ((16384 + 2 * 4096 + 2 * 4096) * 2)   // 65536 bytes

extern __shared__ __half hfsm[];

__global__ __launch_bounds__(256, 2)
void flash_f16()
{
    __half* Qs = hfsm;
    __half* Ks = hfsm + 16384;
    __half* Vs = hfsm + 16384 + 8192;

    const int h   = blockIdx.y;
    const int q0  = blockIdx.x * QT;
    const int tid = threadIdx.x;
    const int lane = tid & 31, wid = tid >> 5;
    const int g = lane >> 2, t = lane & 3;

    const __half* Qg = g_qfh + ((size_t)h * (S_TOT / 16) + (q0 >> 4)) * 2048;
    const __half* Kg = g_kfh + (size_t)h * (S_TOT / 8) * 1024;
    const __half* Vg = g_vfh + (size_t)h * (S_TOT / 16) * 2048;

    const uint32_t qs_u = smem_u32(Qs);
    const uint32_t ks_u = smem_u32(Ks);
    const uint32_t vs_u = smem_u32(Vs);

    #pragma unroll
    for (int i = 0; i < 8; i++)
        cp16(qs_u + (uint32_t)(tid + 256 * i) * 16, Qg + (size_t)(tid + 256 * i) * 8);
    CP_COMMIT();

    auto loadKV = [&](int j, int st) {
        const __half* kp = Kg + (size_t)j * 4096;
        const __half* vp = Vg + (size_t)j * 4096;
        uint32_t ku = ks_u + st * 8192;
        uint32_t vu = vs_u + st * 8192;
        #pragma unroll
        for (int i = 0; i < 2; i++) {
            cp16(ku + (uint32_t)(tid + 256 * i) * 16, kp + (size_t)(tid + 256 * i) * 8);
            cp16(vu + (uint32_t)(tid + 256 * i) * 16, vp + (size_t)(tid + 256 * i) * 8);
        }
        CP_COMMIT();
    };
    loadKV(0, 0);

    float oc[16][4];
    #pragma unroll
    for (int nt = 0; nt < 16; nt++)
        #pragma unroll
        for (int q = 0; q < 4; q++) oc[nt][q] = 0.f;
    float mr0 = -3.4e38f, mr1 = -3.4e38f, lr0 = 0.f, lr1 = 0.f;

    for (int j = 0; j < NKV; j++) {
        if (j + 1 < NKV) { loadKV(j + 1, (j + 1) & 1); CP_WAIT(1); }
        else             { CP_WAIT(0); }
        __syncthreads();

        const __half* Kst = Ks + (j & 1) * 4096;
        const __half* Vst = Vs + (j & 1) * 4096;

        float sc[4][4];
        #pragma unroll
        for (int nt = 0; nt < 4; nt++)
            #pragma unroll
            for (int q = 0; q < 4; q++) sc[nt][q] = 0.f;

        #pragma unroll
        for (int kc = 0; kc < 8; kc++) {
            uint4 a = *(const uint4*)(Qs + (wid * 8 + kc) * 256 + lane * 8);
            #pragma unroll
            for (int nt = 0; nt < 4; nt++) {
                uint2 b = *(const uint2*)(Kst + (nt * 8 + kc) * 128 + lane * 4);
                mma_f16(sc[nt][0], sc[nt][1], sc[nt][2], sc[nt][3],
                        a.x, a.y, a.z, a.w, b.x, b.y);
            }
        }

        float mx0 = -3.4e38f, mx1 = -3.4e38f;
        #pragma unroll
        for (int nt = 0; nt < 4; nt++) {
            mx0 = fmaxf(mx0, fmaxf(sc[nt][0], sc[nt][1]));
            mx1 = fmaxf(mx1, fmaxf(sc[nt][2], sc[nt][3]));
        }
        mx0 = fmaxf(mx0, __shfl_xor_sync(0xffffffff, mx0, 1));
        mx0 = fmaxf(mx0, __shfl_xor_sync(0xffffffff, mx0, 2));
        mx1 = fmaxf(mx1, __shfl_xor_sync(0xffffffff, mx1, 1));
        mx1 = fmaxf(mx1, __shfl_xor_sync(0xffffffff, mx1, 2));

        float mn0 = fmaxf(mr0, mx0), mn1 = fmaxf(mr1, mx1);
        float al0 = exp2f((mr0 - mn0) * CEXP);
        float al1 = exp2f((mr1 - mn1) * CEXP);
        mr0 = mn0; mr1 = mn1;

        float s0 = 0.f, s1 = 0.f;
        #pragma unroll
        for (int nt = 0; nt < 4; nt++) {
            sc[nt][0] = exp2f((sc[nt][0] - mn0) * CEXP);
            sc[nt][1] = exp2f((sc[nt][1] - mn0) * CEXP);
            sc[nt][2] = exp2f((sc[nt][2] - mn1) * CEXP);
            sc[nt][3] = exp2f((sc[nt][3] - mn1) * CEXP);
            s0 += sc[nt][0] + sc[nt][1];
            s1 += sc[nt][2] + sc[nt][3];
        }
        s0 += __shfl_xor_sync(0xffffffff, s0, 1);
        s0 += __shfl_xor_sync(0xffffffff, s0, 2);
        s1 += __shfl_xor_sync(0xffffffff, s1, 1);
        s1 += __shfl_xor_sync(0xffffffff, s1, 2);
        lr0 = lr0 * al0 + s0;
        lr1 = lr1 * al1 + s1;

        #pragma unroll
        for (int nt = 0; nt < 16; nt++) {
            oc[nt][0] *= al0; oc[nt][1] *= al0;
            oc[nt][2] *= al1; oc[nt][3] *= al1;
        }

        #pragma unroll
        for (int kc = 0; kc < 2; kc++) {
            uint32_t a0 = pack_h2(sc[2 * kc][0],     sc[2 * kc][1]);
            uint32_t a1 = pack_h2(sc[2 * kc][2],     sc[2 * kc][3]);
            uint32_t a2 = pack_h2(sc[2 * kc + 1][0], sc[2 * kc + 1][1]);
            uint32_t a3 = pack_h2(sc[2 * kc + 1][2], sc[2 * kc + 1][3]);
            #pragma unroll
            for (int nt = 0; nt < 16; nt++) {
                uint2 b = *(const uint2*)(Vst + (kc * 16 + nt) * 128 + lane * 4);
                mma_f16(oc[nt][0], oc[nt][1], oc[nt][2], oc[nt][3],
                        a0, a1, a2, a3, b.x, b.y);
            }
        }
        __syncthreads();
    }

    float li0 = 1.f / lr0, li1 = 1.f / lr1;
    __half* orow0 = g_attnh + (size_t)(q0 + wid * 16 + g) * D + h * DH;
    __half* orow1 = orow0 + (size_t)8 * D;
    #pragma unroll
    for (int nt = 0; nt < 16; nt++) {
        *(__half2*)(orow0 + nt * 8 + 2 * t) =
            __float22half2_rn(make_float2(oc[nt][0] * li0, oc[nt][1] * li0));
        *(__half2*)(orow1 + nt * 8 + 2 * t) =
            __float22half2_rn(make_float2(oc[nt][2] * li1, oc[nt][3] * li1));
    }
}

// ---------------- launch ----------------
extern "C" void kernel_launch(void* const* d_in, const int* in_sizes, int n_in,
                              void* d_out, int out_size)
{
    const float* hidden     = (const float*)d_in[0];
    const float* encoder    = (const float*)d_in[1];
    const float* cosb       = (const float*)d_in[2];
    const float* sinb       = (const float*)d_in[3];
    const float* w_qkv      = (const float*)d_in[4];
    const float* w_add_qkv  = (const float*)d_in[5];
    const float* b_add_qkv  = (const float*)d_in[6];
    const float* norm_q_w   = (const float*)d_in[7];
    const float* norm_k_w   = (const float*)d_in[8];
    const float* norm_aq_w  = (const float*)d_in[9];
    const float* norm_ak_w  = (const float*)d_in[10];
    const float* w_out      = (const float*)d_in[11];
    const float* b_out      = (const float*)d_in[12];
    const float* w_add_out  = (const float*)d_in[13];
    const float* b_add_out  = (const float*)d_in[14];
    float* out = (float*)d_out;

    __half *qkvh, *xh, *wqh, *waqh, *woh, *waoh, *attnh;
    cudaGetSymbolAddress((void**)&qkvh,  g_qkvh);
    cudaGetSymbolAddress((void**)&xh,    g_xh);
    cudaGetSymbolAddress((void**)&wqh,   g_wqkvh);
    cudaGetSymbolAddress((void**)&waqh,  g_waddqkvh);
    cudaGetSymbolAddress((void**)&woh,   g_wouth);
    cudaGetSymbolAddress((void**)&waoh,  g_waddouth);
    cudaGetSymbolAddress((void**)&attnh, g_attnh);

    cudaFuncSetAttribute(flash_f16, cudaFuncAttributeMaxDynamicSharedMemorySize, FLASH_SMEM);
    cudaFuncSetAttribute(gemm_f16<__half>, cudaFuncAttributeMaxDynamicSharedMemorySize, GEMM_SMEM_BYTES);
    cudaFuncSetAttribute(gemm_f16<float>,  cudaFuncAttributeMaxDynamicSharedMemorySize, GEMM_SMEM_BYTES);

    // Launch order (ncu -s 5 -c 1 -> index 5 = flash_f16):
    // 0: f2h_x2, 1: f2h_w2(qkv weights), 2: f2h_w2(out weights),
    // 3: gemm qkv, 4: norm_rope, 5: flash, 6: gemm out
    {
        int n0_4 = (TXT * D) / 4, n1_4 = (IMG * D) / 4;
        int tot = n0_4 + n1_4;
        f2h_x2<<<(tot + 255) / 256, 256>>>((const float4*)encoder, n0_4,
                                           (const float4*)hidden,  n1_4,
                                           (__half2*)xh);
    }
    {
        int n4 = (ND3 * D) / 4, tot = 2 * n4;
        f2h_w2<<<(tot + 255) / 256, 256>>>((const float4*)w_qkv,     (__half2*)wqh,  n4,
                                           (const float4*)w_add_qkv, (__half2*)waqh, n4);
    }
    {
        int n4 = (D * D) / 4, tot = 2 * n4;
        f2h_w2<<<(tot + 255) / 256, 256>>>((const float4*)w_out,     (__half2*)woh,  n4,
                                           (const float4*)w_add_out, (__half2*)waoh, n4);
    }

    // QKV projection (fp16 mma.sync + ldmatrix)
    gemm_f16<__half><<<dim3(S_TOT / BM, ND3 / BN), 256, GEMM_SMEM_BYTES>>>(
        xh, waqh, wqh, b_add_qkv, nullptr,
        qkvh, qkvh + (size_t)TXT * ND3, TXT, ND3);

    // RMSNorm + RoPE + split into fp16 fragment-packed q/k/v
    norm_rope<<<dim3(S_TOT * NH, 3), 128>>>(cosb, sinb, norm_q_w, norm_k_w,
                                            norm_aq_w, norm_ak_w);

    // Flash attention (fp16 mma.sync) — profiled launch
    flash_f16<<<dim3(S_TOT / QT, NH), 256, FLASH_SMEM>>>();

    // Output projections (fp16 mma.sync, fp32 output)
    gemm_f16<float><<<dim3(S_TOT / BM, D / BN), 256, GEMM_SMEM_BYTES>>>(
        attnh, waoh, woh, b_add_out, b_out,
        out + (size_t)IMG * D, out, TXT, D);
}

// round 9
// speedup vs baseline: 8.2454x; 1.0173x over previous
#include <cuda_runtime.h>
#include <cuda_fp16.h>
#include <math.h>
#include <stdint.h>

#define S_TOT 2560
#define TXT 256
#define IMG 2304
#define D 3072
#define NH 24
#define DH 128
#define ND3 9216
#define KDIM 3072
#define ATT_SCALE 0.08838834764831845f   // 1/sqrt(128)
#define CEXP (1.4426950408889634f * ATT_SCALE)
#define EPS 1e-5f

// ---------------- scratch (device globals: no allocation allowed) ----------------
__device__ __half g_qkvh[(size_t)S_TOT * ND3];
__device__ __half g_qfh[(size_t)NH * S_TOT * DH];   // fragment-packed fp16
__device__ __half g_kfh[(size_t)NH * S_TOT * DH];
__device__ __half g_vfh[(size_t)NH * S_TOT * DH];
__device__ __half g_attnh[(size_t)S_TOT * D];
// fp16 copies of inputs
__device__ __half g_xh[(size_t)S_TOT * D];
__device__ __half g_wqkvh[(size_t)ND3 * D];
__device__ __half g_waddqkvh[(size_t)ND3 * D];
__device__ __half g_wouth[(size_t)D * D];
__device__ __half g_waddouth[(size_t)D * D];

// ================= helpers =================
static __device__ __forceinline__ uint32_t smem_u32(const void* p) {
    uint32_t r;
    asm("{ .reg .u64 t; cvta.to.shared.u64 t, %1; cvt.u32.u64 %0, t; }" : "=r"(r) : "l"(p));
    return r;
}
static __device__ __forceinline__ void cp16(uint32_t dst, const void* src) {
    asm volatile("cp.async.cg.shared.global [%0], [%1], 16;" :: "r"(dst), "l"(src));
}
#define CP_COMMIT() asm volatile("cp.async.commit_group;" ::: "memory")
#define CP_WAIT(n)  asm volatile("cp.async.wait_group %0;" :: "n"(n) : "memory")

static __device__ __forceinline__ void mma_f16(
    float& c0, float& c1, float& c2, float& c3,
    uint32_t a0, uint32_t a1, uint32_t a2, uint32_t a3,
    uint32_t b0, uint32_t b1)
{
    asm volatile(
        "mma.sync.aligned.m16n8k16.row.col.f32.f16.f16.f32 "
        "{%0,%1,%2,%3}, {%4,%5,%6,%7}, {%8,%9}, {%0,%1,%2,%3};"
        : "+f"(c0), "+f"(c1), "+f"(c2), "+f"(c3)
        : "r"(a0), "r"(a1), "r"(a2), "r"(a3), "r"(b0), "r"(b1));
}
static __device__ __forceinline__ void ldsm_x4(
    uint32_t& r0, uint32_t& r1, uint32_t& r2, uint32_t& r3, uint32_t addr)
{
    asm volatile("ldmatrix.sync.aligned.m8n8.x4.shared.b16 {%0,%1,%2,%3}, [%4];"
                 : "=r"(r0), "=r"(r1), "=r"(r2), "=r"(r3) : "r"(addr));
}
static __device__ __forceinline__ uint32_t pack_h2(float x, float y) {
    __half2 h = __float22half2_rn(make_float2(x, y));
    return *reinterpret_cast<uint32_t*>(&h);
}

// ---------------- single merged fp32 -> fp16 conversion pass ----------------
// segments: encoder, hidden -> xh ; 4 weight matrices -> their fp16 copies
__global__ void conv_all(const float4* __restrict__ enc, const float4* __restrict__ hid,
                         const float4* __restrict__ wq,  const float4* __restrict__ waq,
                         const float4* __restrict__ wo,  const float4* __restrict__ wao,
                         __half2* __restrict__ xh,
                         __half2* __restrict__ wqh, __half2* __restrict__ waqh,
                         __half2* __restrict__ woh, __half2* __restrict__ waoh)
{
    const int NE = TXT * D / 4, NHd = IMG * D / 4;
    const int NW = ND3 * D / 4, NO = D * D / 4;
    const int TOT = NE + NHd + 2 * NW + 2 * NO;
    int i = blockIdx.x * blockDim.x + threadIdx.x;
    if (i >= TOT) return;

    const float4* s; __half2* d; int k;
    if (i < NE)                        { s = enc; d = xh;                      k = i; }
    else if (i < NE + NHd)             { s = hid; d = xh + (size_t)NE * 2;     k = i - NE; }
    else if (i < NE + NHd + NW)        { s = wq;  d = wqh;                     k = i - NE - NHd; }
    else if (i < NE + NHd + 2 * NW)    { s = waq; d = waqh;                    k = i - NE - NHd - NW; }
    else if (i < NE + NHd + 2 * NW + NO){ s = wo; d = woh;                     k = i - NE - NHd - 2 * NW; }
    else                               { s = wao; d = waoh;                    k = i - NE - NHd - 2 * NW - NO; }

    float4 v = s[k];
    d[k * 2]     = __float22half2_rn(make_float2(v.x, v.y));
    d[k * 2 + 1] = __float22half2_rn(make_float2(v.z, v.w));
}

// ================= fp16 mma.sync GEMM =================
// C = A @ W^T (+bias). Block 128x128, BK=64, 3 stages, ldmatrix frags,
// 128 threads = 4 warps (2M x 2N) of 64x64 tiles. 2 CTAs/SM co-resident.
#define BM 128
#define BN 128
#define BK 64
#define GSTG 3
#define NCHUNK (KDIM / BK)       // 48
#define HPITCH 72                // halves per row (144 B)
#define A_SH (BM * HPITCH)       // 9216 halves
#define B_SH (BN * HPITCH)       // 9216 halves
#define GEMM_SMEM_BYTES (GSTG * (A_SH + B_SH) * 2)   // 110592

template <typename OT>
__global__ __launch_bounds__(128, 2)
void gemm_f16(const __half* __restrict__ A,
              const __half* __restrict__ W0, const __half* __restrict__ W1,
              const float* __restrict__ b0, const float* __restrict__ b1,
              OT* __restrict__ C0, OT* __restrict__ C1,
              int M0, int N)
{
    extern __shared__ __half hsm[];
    __half* Asm = hsm;
    __half* Bsm = hsm + GSTG * A_SH;

    const int tid  = threadIdx.x;
    const int lane = tid & 31;
    const int wid  = tid >> 5;
    const int wm   = wid >> 1;      // 0..1
    const int wn   = wid & 1;       // 0..1
    const int g    = lane >> 2;
    const int t    = lane & 3;

    const int bm = blockIdx.x, bn = blockIdx.y;   // m fastest
    const int rowbase = bm * BM;
    const int n0 = bn * BN;

    const __half* Ab = A + (size_t)rowbase * KDIM;
    const __half* W; const float* bias; OT* C;
    if (rowbase < M0) { W = W0; bias = b0; C = C0 + (size_t)rowbase * N; }
    else              { W = W1; bias = b1; C = C1 + (size_t)(rowbase - M0) * N; }

    const uint32_t asu = smem_u32(Asm);
    const uint32_t bsu = smem_u32(Bsm);

    // ldmatrix per-lane base addresses (bytes)
    const uint32_t aL = asu + (uint32_t)(((wm * 64 + (lane & 15)) * HPITCH
                                          + (lane >> 4) * 8) * 2);
    const uint32_t bL = bsu + (uint32_t)(((wn * 64 + (lane & 7) + (lane >> 4) * 8) * HPITCH
                                          + ((lane >> 3) & 1) * 8) * 2);

    // ---- async chunk loader: A 1024 x 16B (8/thr), B 1024 x 16B (8/thr) ----
    auto load_chunk = [&](int ck, int st) {
        const int k0 = ck * BK;
        const uint32_t au = asu + st * (A_SH * 2);
        const uint32_t bu = bsu + st * (B_SH * 2);
        #pragma unroll
        for (int i = 0; i < 8; i++) {
            int idx = tid + 128 * i;
            int row = idx >> 3, c = idx & 7;
            cp16(au + row * (HPITCH * 2) + c * 16,
                 Ab + (size_t)row * KDIM + k0 + c * 8);
        }
        #pragma unroll
        for (int i = 0; i < 8; i++) {
            int idx = tid + 128 * i;
            int row = idx >> 3, c = idx & 7;
            cp16(bu + row * (HPITCH * 2) + c * 16,
                 W + (size_t)(n0 + row) * KDIM + k0 + c * 8);
        }
        CP_COMMIT();
    };

    float acc[4][8][4];
    #pragma unroll
    for (int i = 0; i < 4; i++)
        #pragma unroll
        for (int j = 0; j < 8; j++)
            #pragma unroll
            for (int q = 0; q < 4; q++) acc[i][j][q] = 0.f;

    load_chunk(0, 0); load_chunk(1, 1);

    for (int j = 0; j < NCHUNK; j++) {
        if (j < NCHUNK - 2) CP_WAIT(1); else CP_WAIT(0);
        __syncthreads();

        if (j + 2 < NCHUNK) load_chunk(j + 2, (j + 2) % GSTG);

        const int st = j % GSTG;
        const uint32_t aS = aL + st * (A_SH * 2);
        const uint32_t bS = bL + st * (B_SH * 2);

        #pragma unroll
        for (int kc = 0; kc < 4; kc++) {
            uint32_t af[4][4], bf[8][2];
            #pragma unroll
            for (int mt = 0; mt < 4; mt++)
                ldsm_x4(af[mt][0], af[mt][1], af[mt][2], af[mt][3],
                        aS + mt * (16 * HPITCH * 2) + kc * 32);
            #pragma unroll
            for (int p = 0; p < 4; p++)
                ldsm_x4(bf[2 * p][0], bf[2 * p][1], bf[2 * p + 1][0], bf[2 * p + 1][1],
                        bS + p * (16 * HPITCH * 2) + kc * 32);
            #pragma unroll
            for (int mt = 0; mt < 4; mt++)
                #pragma unroll
                for (int nt = 0; nt < 8; nt++)
                    mma_f16(acc[mt][nt][0], acc[mt][nt][1], acc[mt][nt][2], acc[mt][nt][3],
                            af[mt][0], af[mt][1], af[mt][2], af[mt][3],
                            bf[nt][0], bf[nt][1]);
        }
    }

    // ---- epilogue ----
    #pragma unroll
    for (int nt = 0; nt < 8; nt++) {
        const int col = n0 + wn * 64 + nt * 8 + 2 * t;
        float bx = 0.f, by = 0.f;
        if (bias) { bx = bias[col]; by = bias[col + 1]; }
        #pragma unroll
        for (int mt = 0; mt < 4; mt++) {
            const int r0 = wm * 64 + mt * 16 + g;
            if constexpr (sizeof(OT) == 2) {
                *(__half2*)((__half*)C + (size_t)r0 * N + col) =
                    __float22half2_rn(make_float2(acc[mt][nt][0] + bx, acc[mt][nt][1] + by));
                *(__half2*)((__half*)C + (size_t)(r0 + 8) * N + col) =
                    __float22half2_rn(make_float2(acc[mt][nt][2] + bx, acc[mt][nt][3] + by));
            } else {
                float2 v0, v1;
                v0.x = acc[mt][nt][0] + bx; v0.y = acc[mt][nt][1] + by;
                v1.x = acc[mt][nt][2] + bx; v1.y = acc[mt][nt][3] + by;
                *(float2*)((float*)C + (size_t)r0 * N + col)       = v0;
                *(float2*)((float*)C + (size_t)(r0 + 8) * N + col) = v1;
            }
        }
    }
}

// ---------------- RMSNorm + RoPE + head split into fp16 fragment-packed layouts ----------------
__global__ void norm_rope(const float* __restrict__ cosb, const float* __restrict__ sinb,
                          const float* __restrict__ nqw,  const float* __restrict__ nkw,
                          const float* __restrict__ naqw, const float* __restrict__ nakw)
{
    const int s = blockIdx.x / NH, h = blockIdx.x % NH;
    const int which = blockIdx.y;
    const int dh = threadIdx.x;

    __half xh16 = g_qkvh[(size_t)s * ND3 + which * D + h * DH + dh];
    float x = __half2float(xh16);

    if (which == 2) {
        int lane = (dh & 7) * 4 + ((s & 7) >> 1);
        int reg  = (s >> 3) & 1;
        size_t off = (((size_t)h * (S_TOT / 16) + (s >> 4)) * 16 + (dh >> 3)) * 128
                   + (size_t)(lane * 4 + reg * 2 + (s & 1));
        g_vfh[off] = xh16;
        return;
    }

    __shared__ float sh[128];
    __shared__ float red[4];

    float sq = x * x;
    #pragma unroll
    for (int o = 16; o; o >>= 1) sq += __shfl_xor_sync(0xffffffff, sq, o);
    if ((dh & 31) == 0) red[dh >> 5] = sq;
    __syncthreads();
    float msum = red[0] + red[1] + red[2] + red[3];
    float r = rsqrtf(msum * (1.0f / 128.0f) + EPS);

    const float* w;
    if (which == 0) w = (s < TXT) ? naqw : nqw;
    else            w = (s < TXT) ? nakw : nkw;

    float xn = x * r * w[dh];
    sh[dh] = xn;
    __syncthreads();

    float c  = cosb[s * 64 + (dh >> 1)];
    float sn = sinb[s * 64 + (dh >> 1)];
    float other = sh[dh ^ 1];
    float o = (dh & 1) ? fmaf(xn, c,  other * sn)
                       : fmaf(xn, c, -other * sn);
    __half oh = __float2half_rn(o);

    if (which == 0) {
        int lane = (s & 7) * 4 + ((dh & 7) >> 1);
        int reg  = ((s >> 3) & 1) + 2 * ((dh >> 3) & 1);
        size_t off = (((size_t)h * (S_TOT / 16) + (s >> 4)) * 8 + (dh >> 4)) * 256
                   + (size_t)(lane * 8 + reg * 2 + (dh & 1));
        g_qfh[off] = oh;
    } else {
        int lane = (s & 7) * 4 + ((dh & 7) >> 1);
        int reg  = (dh >> 3) & 1;
        size_t off = (((size_t)h * (S_TOT / 8) + (s >> 3)) * 8 + (dh >> 4)) * 128
                   + (size_t)(lane * 4 + reg * 2 + (dh & 1));
        g_kfh[off] = oh;
    }
}

// ---------------- Flash attention, fp16 mma.sync ----------------
#define QT 128
#define KT 32
#define NKV (S_TOT / KT)     // 80
#define FLASH_SMEM ((16384 + 2 * 4096 + 2 * 4096) * 2)   // 65536 bytes

extern __shared__ __half hfsm[];

__global__ __launch_bounds__(256, 2)
void flash_f16()
{
    __half* Qs = hfsm;
    __half* Ks = hfsm + 16384;
    __half* Vs = hfsm + 16384 + 8192;

    const int h   = blockIdx.y;
    const int q0  = blockIdx.x * QT;
    const int tid = threadIdx.x;
    const int lane = tid & 31, wid = tid >> 5;
    const int g = lane >> 2, t = lane & 3;

    const __half* Qg = g_qfh + ((size_t)h * (S_TOT / 16) + (q0 >> 4)) * 2048;
    const __half* Kg = g_kfh + (size_t)h * (S_TOT / 8) * 1024;
    const __half* Vg = g_vfh + (size_t)h * (S_TOT / 16) * 2048;

    const uint32_t qs_u = smem_u32(Qs);
    const uint32_t ks_u = smem_u32(Ks);
    const uint32_t vs_u = smem_u32(Vs);

    #pragma unroll
    for (int i = 0; i < 8; i++)
        cp16(qs_u + (uint32_t)(tid + 256 * i) * 16, Qg + (size_t)(tid + 256 * i) * 8);
    CP_COMMIT();

    auto loadKV = [&](int j, int st) {
        const __half* kp = Kg + (size_t)j * 4096;
        const __half* vp = Vg + (size_t)j * 4096;
        uint32_t ku = ks_u + st * 8192;
        uint32_t vu = vs_u + st * 8192;
        #pragma unroll
        for (int i = 0; i < 2; i++) {
            cp16(ku + (uint32_t)(tid + 256 * i) * 16, kp + (size_t)(tid + 256 * i) * 8);
            cp16(vu + (uint32_t)(tid + 256 * i) * 16, vp + (size_t)(tid + 256 * i) * 8);
        }
        CP_COMMIT();
    };
    loadKV(0, 0);

    float oc[16][4];
    #pragma unroll
    for (int nt = 0; nt < 16; nt++)
        #pragma unroll
        for (int q = 0; q < 4; q++) oc[nt][q] = 0.f;
    float mr0 = -3.4e38f, mr1 = -3.4e38f, lr0 = 0.f, lr1 = 0.f;

    for (int j = 0; j < NKV; j++) {
        if (j + 1 < NKV) { loadKV(j + 1, (j + 1) & 1); CP_WAIT(1); }
        else             { CP_WAIT(0); }
        __syncthreads();

        const __half* Kst = Ks + (j & 1) * 4096;
        const __half* Vst = Vs + (j & 1) * 4096;

        float sc[4][4];
        #pragma unroll
        for (int nt = 0; nt < 4; nt++)
            #pragma unroll
            for (int q = 0; q < 4; q++) sc[nt][q] = 0.f;

        #pragma unroll
        for (int kc = 0; kc < 8; kc++) {
            uint4 a = *(const uint4*)(Qs + (wid * 8 + kc) * 256 + lane * 8);
            #pragma unroll
            for (int nt = 0; nt < 4; nt++) {
                uint2 b = *(const uint2*)(Kst + (nt * 8 + kc) * 128 + lane * 4);
                mma_f16(sc[nt][0], sc[nt][1], sc[nt][2], sc[nt][3],
                        a.x, a.y, a.z, a.w, b.x, b.y);
            }
        }

        float mx0 = -3.4e38f, mx1 = -3.4e38f;
        #pragma unroll
        for (int nt = 0; nt < 4; nt++) {
            mx0 = fmaxf(mx0, fmaxf(sc[nt][0], sc[nt][1]));
            mx1 = fmaxf(mx1, fmaxf(sc[nt][2], sc[nt][3]));
        }
        mx0 = fmaxf(mx0, __shfl_xor_sync(0xffffffff, mx0, 1));
        mx0 = fmaxf(mx0, __shfl_xor_sync(0xffffffff, mx0, 2));
        mx1 = fmaxf(mx1, __shfl_xor_sync(0xffffffff, mx1, 1));
        mx1 = fmaxf(mx1, __shfl_xor_sync(0xffffffff, mx1, 2));

        float mn0 = fmaxf(mr0, mx0), mn1 = fmaxf(mr1, mx1);
        float al0 = exp2f((mr0 - mn0) * CEXP);
        float al1 = exp2f((mr1 - mn1) * CEXP);
        mr0 = mn0; mr1 = mn1;

        float s0 = 0.f, s1 = 0.f;
        #pragma unroll
        for (int nt = 0; nt < 4; nt++) {
            sc[nt][0] = exp2f((sc[nt][0] - mn0) * CEXP);
            sc[nt][1] = exp2f((sc[nt][1] - mn0) * CEXP);
            sc[nt][2] = exp2f((sc[nt][2] - mn1) * CEXP);
            sc[nt][3] = exp2f((sc[nt][3] - mn1) * CEXP);
            s0 += sc[nt][0] + sc[nt][1];
            s1 += sc[nt][2] + sc[nt][3];
        }
        s0 += __shfl_xor_sync(0xffffffff, s0, 1);
        s0 += __shfl_xor_sync(0xffffffff, s0, 2);
        s1 += __shfl_xor_sync(0xffffffff, s1, 1);
        s1 += __shfl_xor_sync(0xffffffff, s1, 2);
        lr0 = lr0 * al0 + s0;
        lr1 = lr1 * al1 + s1;

        #pragma unroll
        for (int nt = 0; nt < 16; nt++) {
            oc[nt][0] *= al0; oc[nt][1] *= al0;
            oc[nt][2] *= al1; oc[nt][3] *= al1;
        }

        #pragma unroll
        for (int kc = 0; kc < 2; kc++) {
            uint32_t a0 = pack_h2(sc[2 * kc][0],     sc[2 * kc][1]);
            uint32_t a1 = pack_h2(sc[2 * kc][2],     sc[2 * kc][3]);
            uint32_t a2 = pack_h2(sc[2 * kc + 1][0], sc[2 * kc + 1][1]);
            uint32_t a3 = pack_h2(sc[2 * kc + 1][2], sc[2 * kc + 1][3]);
            #pragma unroll
            for (int nt = 0; nt < 16; nt++) {
                uint2 b = *(const uint2*)(Vst + (kc * 16 + nt) * 128 + lane * 4);
                mma_f16(oc[nt][0], oc[nt][1], oc[nt][2], oc[nt][3],
                        a0, a1, a2, a3, b.x, b.y);
            }
        }
        __syncthreads();
    }

    float li0 = 1.f / lr0, li1 = 1.f / lr1;
    __half* orow0 = g_attnh + (size_t)(q0 + wid * 16 + g) * D + h * DH;
    __half* orow1 = orow0 + (size_t)8 * D;
    #pragma unroll
    for (int nt = 0; nt < 16; nt++) {
        *(__half2*)(orow0 + nt * 8 + 2 * t) =
            __float22half2_rn(make_float2(oc[nt][0] * li0, oc[nt][1] * li0));
        *(__half2*)(orow1 + nt * 8 + 2 * t) =
            __float22half2_rn(make_float2(oc[nt][2] * li1, oc[nt][3] * li1));
    }
}

// ---------------- launch ----------------
extern "C" void kernel_launch(void* const* d_in, const int* in_sizes, int n_in,
                              void* d_out, int out_size)
{
    const float* hidden     = (const float*)d_in[0];
    const float* encoder    = (const float*)d_in[1];
    const float* cosb       = (const float*)d_in[2];
    const float* sinb       = (const float*)d_in[3];
    const float* w_qkv      = (const float*)d_in[4];
    const float* w_add_qkv  = (const float*)d_in[5];
    const float* b_add_qkv  = (const float*)d_in[6];
    const float* norm_q_w   = (const float*)d_in[7];
    const float* norm_k_w   = (const float*)d_in[8];
    const float* norm_aq_w  = (const float*)d_in[9];
    const float* norm_ak_w  = (const float*)d_in[10];
    const float* w_out      = (const float*)d_in[11];
    const float* b_out      = (const float*)d_in[12];
    const float* w_add_out  = (const float*)d_in[13];
    const float* b_add_out  = (const float*)d_in[14];
    float* out = (float*)d_out;

    __half *qkvh, *xh, *wqh, *waqh, *woh, *waoh, *attnh;
    cudaGetSymbolAddress((void**)&qkvh,  g_qkvh);
    cudaGetSymbolAddress((void**)&xh,    g_xh);
    cudaGetSymbolAddress((void**)&wqh,   g_wqkvh);
    cudaGetSymbolAddress((void**)&waqh,  g_waddqkvh);
    cudaGetSymbolAddress((void**)&woh,   g_wouth);
    cudaGetSymbolAddress((void**)&waoh,  g_waddouth);
    cudaGetSymbolAddress((void**)&attnh, g_attnh);

    cudaFuncSetAttribute(flash_f16, cudaFuncAttributeMaxDynamicSharedMemorySize, FLASH_SMEM);
    cudaFuncSetAttribute(gemm_f16<__half>, cudaFuncAttributeMaxDynamicSharedMemorySize, GEMM_SMEM_BYTES);
    cudaFuncSetAttribute(gemm_f16<float>,  cudaFuncAttributeMaxDynamicSharedMemorySize, GEMM_SMEM_BYTES);

    // Launch order (profiled index is empirically 3 -> flash_f16):
    // 0: conv_all, 1: gemm qkv, 2: norm_rope, 3: flash, 4: gemm out
    {
        const int NE = TXT * D / 4, NHd = IMG * D / 4;
        const int NW = ND3 * D / 4, NO = D * D / 4;
        const int TOT = NE + NHd + 2 * NW + 2 * NO;
        conv_all<<<(TOT + 255) / 256, 256>>>(
            (const float4*)encoder, (const float4*)hidden,
            (const float4*)w_qkv, (const float4*)w_add_qkv,
            (const float4*)w_out, (const float4*)w_add_out,
            (__half2*)xh, (__half2*)wqh, (__half2*)waqh,
            (__half2*)woh, (__half2*)waoh);
    }

    // QKV projection (fp16 mma.sync + ldmatrix, 2 CTAs/SM)
    gemm_f16<__half><<<dim3(S_TOT / BM, ND3 / BN), 128, GEMM_SMEM_BYTES>>>(
        xh, waqh, wqh, b_add_qkv, nullptr,
        qkvh, qkvh + (size_t)TXT * ND3, TXT, ND3);

    // RMSNorm + RoPE + split into fp16 fragment-packed q/k/v
    norm_rope<<<dim3(S_TOT * NH, 3), 128>>>(cosb, sinb, norm_q_w, norm_k_w,
                                            norm_aq_w, norm_ak_w);

    // Flash attention (fp16 mma.sync) — profiled launch
    flash_f16<<<dim3(S_TOT / QT, NH), 256, FLASH_SMEM>>>();

    // Output projections (fp16 mma.sync, fp32 output)
    gemm_f16<float><<<dim3(S_TOT / BM, D / BN), 128, GEMM_SMEM_BYTES>>>(
        attnh, waoh, woh, b_add_out, b_out,
        out + (size_t)IMG * D, out, TXT, D);
}

// round 10
// speedup vs baseline: 8.3041x; 1.0071x over previous
#include <cuda_runtime.h>
#include <cuda_fp16.h>
#include <math.h>
#include <stdint.h>

#define S_TOT 2560
#define TXT 256
#define IMG 2304
#define D 3072
#define NH 24
#define DH 128
#define ND3 9216
#define KDIM 3072
#define ATT_SCALE 0.08838834764831845f   // 1/sqrt(128)
#define CEXP (1.4426950408889634f * ATT_SCALE)
#define EPS 1e-5f

// ---------------- scratch (device globals: no allocation allowed) ----------------
__device__ __half g_qkvh[(size_t)S_TOT * ND3];
__device__ __half g_qfh[(size_t)NH * S_TOT * DH];   // fragment-packed fp16
__device__ __half g_kfh[(size_t)NH * S_TOT * DH];
__device__ __half g_vfh[(size_t)NH * S_TOT * DH];
__device__ __half g_attnh[(size_t)S_TOT * D];
// fp16 copies of inputs
__device__ __half g_xh[(size_t)S_TOT * D];
__device__ __half g_wqkvh[(size_t)ND3 * D];
__device__ __half g_waddqkvh[(size_t)ND3 * D];
__device__ __half g_wouth[(size_t)D * D];
__device__ __half g_waddouth[(size_t)D * D];

// ================= helpers =================
static __device__ __forceinline__ uint32_t smem_u32(const void* p) {
    uint32_t r;
    asm("{ .reg .u64 t; cvta.to.shared.u64 t, %1; cvt.u32.u64 %0, t; }" : "=r"(r) : "l"(p));
    return r;
}
static __device__ __forceinline__ void cp16(uint32_t dst, const void* src) {
    asm volatile("cp.async.cg.shared.global [%0], [%1], 16;" :: "r"(dst), "l"(src));
}
#define CP_COMMIT() asm volatile("cp.async.commit_group;" ::: "memory")
#define CP_WAIT(n)  asm volatile("cp.async.wait_group %0;" :: "n"(n) : "memory")

static __device__ __forceinline__ void mma_f16(
    float& c0, float& c1, float& c2, float& c3,
    uint32_t a0, uint32_t a1, uint32_t a2, uint32_t a3,
    uint32_t b0, uint32_t b1)
{
    asm volatile(
        "mma.sync.aligned.m16n8k16.row.col.f32.f16.f16.f32 "
        "{%0,%1,%2,%3}, {%4,%5,%6,%7}, {%8,%9}, {%0,%1,%2,%3};"
        : "+f"(c0), "+f"(c1), "+f"(c2), "+f"(c3)
        : "r"(a0), "r"(a1), "r"(a2), "r"(a3), "r"(b0), "r"(b1));
}
static __device__ __forceinline__ void ldsm_x4(
    uint32_t& r0, uint32_t& r1, uint32_t& r2, uint32_t& r3, uint32_t addr)
{
    asm volatile("ldmatrix.sync.aligned.m8n8.x4.shared.b16 {%0,%1,%2,%3}, [%4];"
                 : "=r"(r0), "=r"(r1), "=r"(r2), "=r"(r3) : "r"(addr));
}
static __device__ __forceinline__ uint32_t pack_h2(float x, float y) {
    __half2 h = __float22half2_rn(make_float2(x, y));
    return *reinterpret_cast<uint32_t*>(&h);
}
static __device__ __forceinline__ float ex2f(float x) {
    float r;
    asm("ex2.approx.f32 %0, %1;" : "=f"(r) : "f"(x));
    return r;
}

// ---------------- single merged fp32 -> fp16 conversion pass ----------------
__global__ void conv_all(const float4* __restrict__ enc, const float4* __restrict__ hid,
                         const float4* __restrict__ wq,  const float4* __restrict__ waq,
                         const float4* __restrict__ wo,  const float4* __restrict__ wao,
                         __half2* __restrict__ xh,
                         __half2* __restrict__ wqh, __half2* __restrict__ waqh,
                         __half2* __restrict__ woh, __half2* __restrict__ waoh)
{
    const int NE = TXT * D / 4, NHd = IMG * D / 4;
    const int NW = ND3 * D / 4, NO = D * D / 4;
    const int TOT = NE + NHd + 2 * NW + 2 * NO;
    int i = blockIdx.x * blockDim.x + threadIdx.x;
    if (i >= TOT) return;

    const float4* s; __half2* d; int k;
    if (i < NE)                        { s = enc; d = xh;                      k = i; }
    else if (i < NE + NHd)             { s = hid; d = xh + (size_t)NE * 2;     k = i - NE; }
    else if (i < NE + NHd + NW)        { s = wq;  d = wqh;                     k = i - NE - NHd; }
    else if (i < NE + NHd + 2 * NW)    { s = waq; d = waqh;                    k = i - NE - NHd - NW; }
    else if (i < NE + NHd + 2 * NW + NO){ s = wo; d = woh;                     k = i - NE - NHd - 2 * NW; }
    else                               { s = wao; d = waoh;                    k = i - NE - NHd - 2 * NW - NO; }

    float4 v = s[k];
    d[k * 2]     = __float22half2_rn(make_float2(v.x, v.y));
    d[k * 2 + 1] = __float22half2_rn(make_float2(v.z, v.w));
}

// ================= fp16 mma.sync GEMM (unchanged from R9) =================
#define BM 128
#define BN 128
#define BK 64
#define GSTG 3
#define NCHUNK (KDIM / BK)       // 48
#define HPITCH 72
#define A_SH (BM * HPITCH)
#define B_SH (BN * HPITCH)
#define GEMM_SMEM_BYTES (GSTG * (A_SH + B_SH) * 2)   // 110592

template <typename OT>
__global__ __launch_bounds__(128, 2)
void gemm_f16(const __half* __restrict__ A,
              const __half* __restrict__ W0, const __half* __restrict__ W1,
              const float* __restrict__ b0, const float* __restrict__ b1,
              OT* __restrict__ C0, OT* __restrict__ C1,
              int M0, int N)
{
    extern __shared__ __half hsm[];
    __half* Asm = hsm;
    __half* Bsm = hsm + GSTG * A_SH;

    const int tid  = threadIdx.x;
    const int lane = tid & 31;
    const int wid  = tid >> 5;
    const int wm   = wid >> 1;
    const int wn   = wid & 1;
    const int g    = lane >> 2;
    const int t    = lane & 3;

    const int bm = blockIdx.x, bn = blockIdx.y;
    const int rowbase = bm * BM;
    const int n0 = bn * BN;

    const __half* Ab = A + (size_t)rowbase * KDIM;
    const __half* W; const float* bias; OT* C;
    if (rowbase < M0) { W = W0; bias = b0; C = C0 + (size_t)rowbase * N; }
    else              { W = W1; bias = b1; C = C1 + (size_t)(rowbase - M0) * N; }

    const uint32_t asu = smem_u32(Asm);
    const uint32_t bsu = smem_u32(Bsm);

    const uint32_t aL = asu + (uint32_t)(((wm * 64 + (lane & 15)) * HPITCH
                                          + (lane >> 4) * 8) * 2);
    const uint32_t bL = bsu + (uint32_t)(((wn * 64 + (lane & 7) + (lane >> 4) * 8) * HPITCH
                                          + ((lane >> 3) & 1) * 8) * 2);

    auto load_chunk = [&](int ck, int st) {
        const int k0 = ck * BK;
        const uint32_t au = asu + st * (A_SH * 2);
        const uint32_t bu = bsu + st * (B_SH * 2);
        #pragma unroll
        for (int i = 0; i < 8; i++) {
            int idx = tid + 128 * i;
            int row = idx >> 3, c = idx & 7;
            cp16(au + row * (HPITCH * 2) + c * 16,
                 Ab + (size_t)row * KDIM + k0 + c * 8);
        }
        #pragma unroll
        for (int i = 0; i < 8; i++) {
            int idx = tid + 128 * i;
            int row = idx >> 3, c = idx & 7;
            cp16(bu + row * (HPITCH * 2) + c * 16,
                 W + (size_t)(n0 + row) * KDIM + k0 + c * 8);
        }
        CP_COMMIT();
    };

    float acc[4][8][4];
    #pragma unroll
    for (int i = 0; i < 4; i++)
        #pragma unroll
        for (int j = 0; j < 8; j++)
            #pragma unroll
            for (int q = 0; q < 4; q++) acc[i][j][q] = 0.f;

    load_chunk(0, 0); load_chunk(1, 1);

    for (int j = 0; j < NCHUNK; j++) {
        if (j < NCHUNK - 2) CP_WAIT(1); else CP_WAIT(0);
        __syncthreads();

        if (j + 2 < NCHUNK) load_chunk(j + 2, (j + 2) % GSTG);

        const int st = j % GSTG;
        const uint32_t aS = aL + st * (A_SH * 2);
        const uint32_t bS = bL + st * (B_SH * 2);

        #pragma unroll
        for (int kc = 0; kc < 4; kc++) {
            uint32_t af[4][4], bf[8][2];
            #pragma unroll
            for (int mt = 0; mt < 4; mt++)
                ldsm_x4(af[mt][0], af[mt][1], af[mt][2], af[mt][3],
                        aS + mt * (16 * HPITCH * 2) + kc * 32);
            #pragma unroll
            for (int p = 0; p < 4; p++)
                ldsm_x4(bf[2 * p][0], bf[2 * p][1], bf[2 * p + 1][0], bf[2 * p + 1][1],
                        bS + p * (16 * HPITCH * 2) + kc * 32);
            #pragma unroll
            for (int mt = 0; mt < 4; mt++)
                #pragma unroll
                for (int nt = 0; nt < 8; nt++)
                    mma_f16(acc[mt][nt][0], acc[mt][nt][1], acc[mt][nt][2], acc[mt][nt][3],
                            af[mt][0], af[mt][1], af[mt][2], af[mt][3],
                            bf[nt][0], bf[nt][1]);
        }
    }

    #pragma unroll
    for (int nt = 0; nt < 8; nt++) {
        const int col = n0 + wn * 64 + nt * 8 + 2 * t;
        float bx = 0.f, by = 0.f;
        if (bias) { bx = bias[col]; by = bias[col + 1]; }
        #pragma unroll
        for (int mt = 0; mt < 4; mt++) {
            const int r0 = wm * 64 + mt * 16 + g;
            if constexpr (sizeof(OT) == 2) {
                *(__half2*)((__half*)C + (size_t)r0 * N + col) =
                    __float22half2_rn(make_float2(acc[mt][nt][0] + bx, acc[mt][nt][1] + by));
                *(__half2*)((__half*)C + (size_t)(r0 + 8) * N + col) =
                    __float22half2_rn(make_float2(acc[mt][nt][2] + bx, acc[mt][nt][3] + by));
            } else {
                float2 v0, v1;
                v0.x = acc[mt][nt][0] + bx; v0.y = acc[mt][nt][1] + by;
                v1.x = acc[mt][nt][2] + bx; v1.y = acc[mt][nt][3] + by;
                *(float2*)((float*)C + (size_t)r0 * N + col)       = v0;
                *(float2*)((float*)C + (size_t)(r0 + 8) * N + col) = v1;
            }
        }
    }
}

// ---------------- RMSNorm + RoPE + head split into fp16 fragment-packed layouts ----------------
// Q A-frag block [h][s/16][dh/16][256]: lane=(s&7)*4+((dh&7)>>1); reg=((s>>3)&1)+2*((dh>>3)&1)
//   idx = lane*8 + reg*2 + (dh&1)
// K B-frag PAIRED block [h][s/8][dh/32][256]: lane=(s&7)*4+((dh&7)>>1)
//   idx = lane*8 + ((dh>>4)&1)*4 + ((dh>>3)&1)*2 + (dh&1)
// V B-frag PAIRED block [h][s/16][dh/16][256]: lane=(dh&7)*4+((s&7)>>1)
//   idx = lane*8 + ((dh>>3)&1)*4 + ((s>>3)&1)*2 + (s&1)
__global__ void norm_rope(const float* __restrict__ cosb, const float* __restrict__ sinb,
                          const float* __restrict__ nqw,  const float* __restrict__ nkw,
                          const float* __restrict__ naqw, const float* __restrict__ nakw)
{
    const int s = blockIdx.x / NH, h = blockIdx.x % NH;
    const int which = blockIdx.y;
    const int dh = threadIdx.x;

    __half xh16 = g_qkvh[(size_t)s * ND3 + which * D + h * DH + dh];
    float x = __half2float(xh16);

    if (which == 2) {
        int lane = (dh & 7) * 4 + ((s & 7) >> 1);
        size_t off = (((size_t)h * (S_TOT / 16) + (s >> 4)) * 8 + (dh >> 4)) * 256
                   + (size_t)(lane * 8 + ((dh >> 3) & 1) * 4 + ((s >> 3) & 1) * 2 + (s & 1));
        g_vfh[off] = xh16;
        return;
    }

    __shared__ float sh[128];
    __shared__ float red[4];

    float sq = x * x;
    #pragma unroll
    for (int o = 16; o; o >>= 1) sq += __shfl_xor_sync(0xffffffff, sq, o);
    if ((dh & 31) == 0) red[dh >> 5] = sq;
    __syncthreads();
    float msum = red[0] + red[1] + red[2] + red[3];
    float r = rsqrtf(msum * (1.0f / 128.0f) + EPS);

    const float* w;
    if (which == 0) w = (s < TXT) ? naqw : nqw;
    else            w = (s < TXT) ? nakw : nkw;

    float xn = x * r * w[dh];
    sh[dh] = xn;
    __syncthreads();

    float c  = cosb[s * 64 + (dh >> 1)];
    float sn = sinb[s * 64 + (dh >> 1)];
    float other = sh[dh ^ 1];
    float o = (dh & 1) ? fmaf(xn, c,  other * sn)
                       : fmaf(xn, c, -other * sn);
    __half oh = __float2half_rn(o);

    if (which == 0) {
        int lane = (s & 7) * 4 + ((dh & 7) >> 1);
        int reg  = ((s >> 3) & 1) + 2 * ((dh >> 3) & 1);
        size_t off = (((size_t)h * (S_TOT / 16) + (s >> 4)) * 8 + (dh >> 4)) * 256
                   + (size_t)(lane * 8 + reg * 2 + (dh & 1));
        g_qfh[off] = oh;
    } else {
        int lane = (s & 7) * 4 + ((dh & 7) >> 1);
        size_t off = (((size_t)h * (S_TOT / 8) + (s >> 3)) * 4 + (dh >> 5)) * 256
                   + (size_t)(lane * 8 + ((dh >> 4) & 1) * 4 + ((dh >> 3) & 1) * 2 + (dh & 1));
        g_kfh[off] = oh;
    }
}

// ---------------- Flash attention, fp16 mma.sync ----------------
// q-tile 128 (8 warps x 16 rows), kv-tile 32, 3-stage K/V, one sync/iter,
// paired uint4 fragment loads, ex2.approx softmax.
#define QT 128
#define KT 32
#define NKV (S_TOT / KT)     // 80
#define FSTG 3
#define FLASH_SMEM ((16384 + FSTG * 4096 + FSTG * 4096) * 2)   // 81920 bytes

extern __shared__ __half hfsm[];

__global__ __launch_bounds__(256, 2)
void flash_f16()
{
    __half* Qs = hfsm;                         // 16384 halves
    __half* Ks = hfsm + 16384;                 // 3 x 4096
    __half* Vs = hfsm + 16384 + FSTG * 4096;   // 3 x 4096

    const int h   = blockIdx.y;
    const int q0  = blockIdx.x * QT;
    const int tid = threadIdx.x;
    const int lane = tid & 31, wid = tid >> 5;
    const int g = lane >> 2, t = lane & 3;

    const __half* Qg = g_qfh + ((size_t)h * (S_TOT / 16) + (q0 >> 4)) * 2048;
    const __half* Kg = g_kfh + (size_t)h * (S_TOT / 8) * 1024;
    const __half* Vg = g_vfh + (size_t)h * (S_TOT / 16) * 2048;

    const uint32_t qs_u = smem_u32(Qs);
    const uint32_t ks_u = smem_u32(Ks);
    const uint32_t vs_u = smem_u32(Vs);

    #pragma unroll
    for (int i = 0; i < 8; i++)
        cp16(qs_u + (uint32_t)(tid + 256 * i) * 16, Qg + (size_t)(tid + 256 * i) * 8);
    CP_COMMIT();

    auto loadKV = [&](int j, int st) {
        const __half* kp = Kg + (size_t)j * 4096;
        const __half* vp = Vg + (size_t)j * 4096;
        uint32_t ku = ks_u + st * 8192;
        uint32_t vu = vs_u + st * 8192;
        #pragma unroll
        for (int i = 0; i < 2; i++) {
            cp16(ku + (uint32_t)(tid + 256 * i) * 16, kp + (size_t)(tid + 256 * i) * 8);
            cp16(vu + (uint32_t)(tid + 256 * i) * 16, vp + (size_t)(tid + 256 * i) * 8);
        }
        CP_COMMIT();
    };
    loadKV(0, 0);
    loadKV(1, 1);

    float oc[16][4];
    #pragma unroll
    for (int nt = 0; nt < 16; nt++)
        #pragma unroll
        for (int q = 0; q < 4; q++) oc[nt][q] = 0.f;
    float mr0 = -3.4e38f, mr1 = -3.4e38f, lr0 = 0.f, lr1 = 0.f;

    for (int j = 0; j < NKV; j++) {
        // groups outstanding at entry: g(j), g(j+1) [if it exists]
        if (j < NKV - 1) CP_WAIT(1); else CP_WAIT(0);
        __syncthreads();                       // all warps done with stage (j%3) from iter j-3
        if (j + 2 < NKV) loadKV(j + 2, (j + 2) % FSTG);

        const __half* Kst = Ks + (j % FSTG) * 4096;
        const __half* Vst = Vs + (j % FSTG) * 4096;

        // ---- QK^T: S[16 x 32] per warp; paired K loads ----
        float sc[4][4];
        #pragma unroll
        for (int nt = 0; nt < 4; nt++)
            #pragma unroll
            for (int q = 0; q < 4; q++) sc[nt][q] = 0.f;

        #pragma unroll
        for (int kc2 = 0; kc2 < 4; kc2++) {
            uint4 a0v = *(const uint4*)(Qs + (wid * 8 + 2 * kc2) * 256 + lane * 8);
            uint4 a1v = *(const uint4*)(Qs + (wid * 8 + 2 * kc2 + 1) * 256 + lane * 8);
            #pragma unroll
            for (int nt = 0; nt < 4; nt++) {
                uint4 kb = *(const uint4*)(Kst + (nt * 4 + kc2) * 256 + lane * 8);
                mma_f16(sc[nt][0], sc[nt][1], sc[nt][2], sc[nt][3],
                        a0v.x, a0v.y, a0v.z, a0v.w, kb.x, kb.y);
                mma_f16(sc[nt][0], sc[nt][1], sc[nt][2], sc[nt][3],
                        a1v.x, a1v.y, a1v.z, a1v.w, kb.z, kb.w);
            }
        }

        // ---- online softmax (registers; rows g and g+8) ----
        float mx0 = -3.4e38f, mx1 = -3.4e38f;
        #pragma unroll
        for (int nt = 0; nt < 4; nt++) {
            mx0 = fmaxf(mx0, fmaxf(sc[nt][0], sc[nt][1]));
            mx1 = fmaxf(mx1, fmaxf(sc[nt][2], sc[nt][3]));
        }
        mx0 = fmaxf(mx0, __shfl_xor_sync(0xffffffff, mx0, 1));
        mx0 = fmaxf(mx0, __shfl_xor_sync(0xffffffff, mx0, 2));
        mx1 = fmaxf(mx1, __shfl_xor_sync(0xffffffff, mx1, 1));
        mx1 = fmaxf(mx1, __shfl_xor_sync(0xffffffff, mx1, 2));

        float mn0 = fmaxf(mr0, mx0), mn1 = fmaxf(mr1, mx1);
        float al0 = ex2f((mr0 - mn0) * CEXP);
        float al1 = ex2f((mr1 - mn1) * CEXP);
        mr0 = mn0; mr1 = mn1;

        float s0 = 0.f, s1 = 0.f;
        #pragma unroll
        for (int nt = 0; nt < 4; nt++) {
            sc[nt][0] = ex2f((sc[nt][0] - mn0) * CEXP);
            sc[nt][1] = ex2f((sc[nt][1] - mn0) * CEXP);
            sc[nt][2] = ex2f((sc[nt][2] - mn1) * CEXP);
            sc[nt][3] = ex2f((sc[nt][3] - mn1) * CEXP);
            s0 += sc[nt][0] + sc[nt][1];
            s1 += sc[nt][2] + sc[nt][3];
        }
        s0 += __shfl_xor_sync(0xffffffff, s0, 1);
        s0 += __shfl_xor_sync(0xffffffff, s0, 2);
        s1 += __shfl_xor_sync(0xffffffff, s1, 1);
        s1 += __shfl_xor_sync(0xffffffff, s1, 2);
        lr0 = lr0 * al0 + s0;
        lr1 = lr1 * al1 + s1;

        #pragma unroll
        for (int nt = 0; nt < 16; nt++) {
            oc[nt][0] *= al0; oc[nt][1] *= al0;
            oc[nt][2] *= al1; oc[nt][3] *= al1;
        }

        // ---- P @ V: P refragmented in registers; paired V loads ----
        #pragma unroll
        for (int kc = 0; kc < 2; kc++) {
            uint32_t a0 = pack_h2(sc[2 * kc][0],     sc[2 * kc][1]);
            uint32_t a1 = pack_h2(sc[2 * kc][2],     sc[2 * kc][3]);
            uint32_t a2 = pack_h2(sc[2 * kc + 1][0], sc[2 * kc + 1][1]);
            uint32_t a3 = pack_h2(sc[2 * kc + 1][2], sc[2 * kc + 1][3]);
            #pragma unroll
            for (int ntp = 0; ntp < 8; ntp++) {
                uint4 vb = *(const uint4*)(Vst + (kc * 8 + ntp) * 256 + lane * 8);
                mma_f16(oc[2 * ntp][0], oc[2 * ntp][1], oc[2 * ntp][2], oc[2 * ntp][3],
                        a0, a1, a2, a3, vb.x, vb.y);
                mma_f16(oc[2 * ntp + 1][0], oc[2 * ntp + 1][1],
                        oc[2 * ntp + 1][2], oc[2 * ntp + 1][3],
                        a0, a1, a2, a3, vb.z, vb.w);
            }
        }
    }

    // ---- normalize + write fp16 (feeds fp16 out-proj) ----
    float li0 = 1.f / lr0, li1 = 1.f / lr1;
    __half* orow0 = g_attnh + (size_t)(q0 + wid * 16 + g) * D + h * DH;
    __half* orow1 = orow0 + (size_t)8 * D;
    #pragma unroll
    for (int nt = 0; nt < 16; nt++) {
        *(__half2*)(orow0 + nt * 8 + 2 * t) =
            __float22half2_rn(make_float2(oc[nt][0] * li0, oc[nt][1] * li0));
        *(__half2*)(orow1 + nt * 8 + 2 * t) =
            __float22half2_rn(make_float2(oc[nt][2] * li1, oc[nt][3] * li1));
    }
}

// ---------------- launch ----------------
extern "C" void kernel_launch(void* const* d_in, const int* in_sizes, int n_in,
                              void* d_out, int out_size)
{
    const float* hidden     = (const float*)d_in[0];
    const float* encoder    = (const float*)d_in[1];
    const float* cosb       = (const float*)d_in[2];
    const float* sinb       = (const float*)d_in[3];
    const float* w_qkv      = (const float*)d_in[4];
    const float* w_add_qkv  = (const float*)d_in[5];
    const float* b_add_qkv  = (const float*)d_in[6];
    const float* norm_q_w   = (const float*)d_in[7];
    const float* norm_k_w   = (const float*)d_in[8];
    const float* norm_aq_w  = (const float*)d_in[9];
    const float* norm_ak_w  = (const float*)d_in[10];
    const float* w_out      = (const float*)d_in[11];
    const float* b_out      = (const float*)d_in[12];
    const float* w_add_out  = (const float*)d_in[13];
    const float* b_add_out  = (const float*)d_in[14];
    float* out = (float*)d_out;

    __half *qkvh, *xh, *wqh, *waqh, *woh, *waoh, *attnh;
    cudaGetSymbolAddress((void**)&qkvh,  g_qkvh);
    cudaGetSymbolAddress((void**)&xh,    g_xh);
    cudaGetSymbolAddress((void**)&wqh,   g_wqkvh);
    cudaGetSymbolAddress((void**)&waqh,  g_waddqkvh);
    cudaGetSymbolAddress((void**)&woh,   g_wouth);
    cudaGetSymbolAddress((void**)&waoh,  g_waddouth);
    cudaGetSymbolAddress((void**)&attnh, g_attnh);

    cudaFuncSetAttribute(flash_f16, cudaFuncAttributeMaxDynamicSharedMemorySize, FLASH_SMEM);
    cudaFuncSetAttribute(gemm_f16<__half>, cudaFuncAttributeMaxDynamicSharedMemorySize, GEMM_SMEM_BYTES);
    cudaFuncSetAttribute(gemm_f16<float>,  cudaFuncAttributeMaxDynamicSharedMemorySize, GEMM_SMEM_BYTES);

    // Launch order: 0 conv_all, 1 gemm qkv, 2 norm_rope, 3 flash (profiled), 4 gemm out
    {
        const int NE = TXT * D / 4, NHd = IMG * D / 4;
        const int NW = ND3 * D / 4, NO = D * D / 4;
        const int TOT = NE + NHd + 2 * NW + 2 * NO;
        conv_all<<<(TOT + 255) / 256, 256>>>(
            (const float4*)encoder, (const float4*)hidden,
            (const float4*)w_qkv, (const float4*)w_add_qkv,
            (const float4*)w_out, (const float4*)w_add_out,
            (__half2*)xh, (__half2*)wqh, (__half2*)waqh,
            (__half2*)woh, (__half2*)waoh);
    }

    gemm_f16<__half><<<dim3(S_TOT / BM, ND3 / BN), 128, GEMM_SMEM_BYTES>>>(
        xh, waqh, wqh, b_add_qkv, nullptr,
        qkvh, qkvh + (size_t)TXT * ND3, TXT, ND3);

    norm_rope<<<dim3(S_TOT * NH, 3), 128>>>(cosb, sinb, norm_q_w, norm_k_w,
                                            norm_aq_w, norm_ak_w);

    flash_f16<<<dim3(S_TOT / QT, NH), 256, FLASH_SMEM>>>();

    gemm_f16<float><<<dim3(S_TOT / BM, D / BN), 128, GEMM_SMEM_BYTES>>>(
        attnh, waoh, woh, b_add_out, b_out,
        out + (size_t)IMG * D, out, TXT, D);
}